// round 10
// baseline (speedup 1.0000x reference)
#include <cuda_runtime.h>
#include <cuda_fp16.h>
#include <cstdint>
#include <cstddef>

// ---------------------------------------------------------------------------
// SmallSpatialPolicyHead — R9 + k2 software pipelining: LN-phase-A and tproj
// prefetch for pair i+1 issued under the MMA phase of pair i (double-buffered
// mu/is/tproj).
// ---------------------------------------------------------------------------

#define BMAX 16384
#define K2_GRID 296
#define K3_GRID 592

__device__ float d_tb[208];
__device__ __half d_Wh[160 * 48];    // k2 node proj hi  [n][k]
__device__ __half d_Wl[160 * 48];    // k2 node proj lo
__device__ __half d_Wth[208 * 80];   // k1 trunk proj hi [o][k]
__device__ __half d_Wtl[208 * 80];   // k1 trunk proj lo
__device__ float d_tproj[(size_t)BMAX * 128];
__device__ float d_h[(size_t)BMAX * 80];
__device__ float d_partial[296 * 160];
__device__ float d_bnscale[80];
__device__ float d_bnshift[80];

// ---- k2 smem byte offsets ----
#define SM_XP    0             // P_s 108x97 f = 41904
#define SM_AH    41920         // 128x56 fp16 = 14336
#define SM_AL    56256
#define SM_WH    70592         // 160x56 fp16 = 17920
#define SM_WL    88512
#define WLOFF    17920
#define SM_TPROJ 106432        // 2 x 256 f (double buffer)
#define SM_W2    108480        // 96 f
#define SM_ROB2  108864        // 160 f
#define SM_B2    109504        // 8 f
#define SM_LNW   109536        // 48 f
#define SM_LNB   109728        // 48 f
#define SM_MU    109920        // 2 x 110 f (double buffer, 448B each)
#define SM_IS    110816        // 2 x 110 f
#define SM_RP    111712        // 144 i
#define SM_TI    112288        // 114 i
#define SM_TOTAL 112752

// ---- k1 smem byte offsets ----
#define X1_XS    0             // 128x84 f = 43008 (reused as hs)
#define X1_AH    43008         // 128x88 fp16 = 22528
#define X1_AL    65536
#define X1_WH    88064         // 208x88 fp16 = 36608
#define X1_WL    124672
#define W1OFF    36608
#define X1_TB    161280        // 208 f
#define X1_LNW   162112        // 80 f
#define X1_LNB   162432        // 80 f
#define K1_SMEM  162752

__device__ __forceinline__ uint32_t smem_u32(const void* p) {
    uint32_t a;
    asm("{ .reg .u64 t; cvta.to.shared.u64 t, %1; cvt.u32.u64 %0, t; }" : "=r"(a) : "l"(p));
    return a;
}
__device__ __forceinline__ void cp16(uint32_t dst, const void* src) {
    asm volatile("cp.async.cg.shared.global [%0], [%1], 16;" :: "r"(dst), "l"(src));
}
#define CP_COMMIT() asm volatile("cp.async.commit_group;" ::: "memory")
#define CP_WAIT_ALL() asm volatile("cp.async.wait_group 0;" ::: "memory")
#define CP_COMMIT_WAIT() do { CP_COMMIT(); CP_WAIT_ALL(); } while (0)

#define LDSM_X4(r0,r1,r2,r3,addr) \
    asm volatile("ldmatrix.sync.aligned.m8n8.x4.shared.b16 {%0,%1,%2,%3}, [%4];" \
        : "=r"(r0),"=r"(r1),"=r"(r2),"=r"(r3) : "r"(addr))
#define LDSM_X2(r0,r1,addr) \
    asm volatile("ldmatrix.sync.aligned.m8n8.x2.shared.b16 {%0,%1}, [%2];" \
        : "=r"(r0),"=r"(r1) : "r"(addr))
#define LDSM_X4_NV(r0,r1,r2,r3,addr) \
    asm("ldmatrix.sync.aligned.m8n8.x4.shared.b16 {%0,%1,%2,%3}, [%4];" \
        : "=r"(r0),"=r"(r1),"=r"(r2),"=r"(r3) : "r"(addr))
#define LDSM_X2_NV(r0,r1,addr) \
    asm("ldmatrix.sync.aligned.m8n8.x2.shared.b16 {%0,%1}, [%2];" \
        : "=r"(r0),"=r"(r1) : "r"(addr))

__device__ __forceinline__ void mma16816(float* d, const uint32_t* a, uint32_t b0, uint32_t b1) {
    asm volatile(
        "mma.sync.aligned.m16n8k16.row.col.f32.f16.f16.f32 "
        "{%0,%1,%2,%3},{%4,%5,%6,%7},{%8,%9},{%0,%1,%2,%3};"
        : "+f"(d[0]), "+f"(d[1]), "+f"(d[2]), "+f"(d[3])
        : "r"(a[0]), "r"(a[1]), "r"(a[2]), "r"(a[3]), "r"(b0), "r"(b1));
}

__device__ __forceinline__ float mishf(float x) {
    float u = __expf(fminf(x, 15.f));
    float d = __fmaf_rn(u, u + 2.f, 2.f);
    return x - __fdividef(2.f * x, d);
}
__device__ __forceinline__ float warp_sum(float v) {
    #pragma unroll
    for (int o = 16; o; o >>= 1) v += __shfl_xor_sync(0xffffffffu, v, o);
    return v;
}

// ------------------------------ prep ------------------------------
__global__ void k_prep(const float* __restrict__ sett1_w, const float* __restrict__ city1_w,
                       const float* __restrict__ road1_w, const float* __restrict__ rob1_w,
                       const float* __restrict__ gfc1_w,
                       const float* __restrict__ sett1_b, const float* __restrict__ city1_b,
                       const float* __restrict__ road1_b, const float* __restrict__ rob1_b,
                       const float* __restrict__ gfc1_b) {
    int i = blockIdx.x * blockDim.x + threadIdx.x;
    if (i < 160 * 48) {
        int j = i / 48, k = i % 48;
        float v;
        if (j < 32)       v = sett1_w[j * 128 + 80 + k];
        else if (j < 64)  v = city1_w[(j - 32) * 128 + 80 + k];
        else if (j < 96)  v = road1_w[(j - 64) * 176 + 80 + k];
        else if (j < 128) v = road1_w[(j - 96) * 176 + 128 + k];
        else              v = rob1_w[(j - 128) * 128 + 80 + k];
        __half h = __float2half(v);
        d_Wh[i] = h;
        d_Wl[i] = __float2half(v - __half2float(h));
    }
    if (i < 208 * 80) {
        int o = i / 80, k = i % 80;
        float v;
        if (o < 32)       v = sett1_w[o * 128 + k];
        else if (o < 64)  v = city1_w[(o - 32) * 128 + k];
        else if (o < 96)  v = road1_w[(o - 64) * 176 + k];
        else if (o < 128) v = rob1_w[(o - 96) * 128 + k];
        else              v = gfc1_w[(o - 128) * 80 + k];
        __half h = __float2half(v);
        d_Wth[i] = h;
        d_Wtl[i] = __float2half(v - __half2float(h));
    }
    if (i < 208) {
        float v;
        if (i < 32)       v = sett1_b[i];
        else if (i < 64)  v = city1_b[i - 32];
        else if (i < 96)  v = road1_b[i - 64];
        else if (i < 128) v = rob1_b[i - 96];
        else              v = gfc1_b[i - 128];
        d_tb[i] = v;
    }
}

// ------------------------------ K1: HMMA trunk kernel (unchanged, proven) ------------------------------
__global__ __launch_bounds__(512, 1) void k1(const float* __restrict__ trunk,
                                             const float* __restrict__ ln_t_w,
                                             const float* __restrict__ ln_t_b, int B) {
    extern __shared__ char smem[];
    const uint32_t sbase = smem_u32(smem);
    const int tid = threadIdx.x, wid = tid >> 5, lane = tid & 31;

    float* xs  = (float*)(smem + X1_XS);
    float* hs  = (float*)(smem + X1_XS);
    float* tb_s = (float*)(smem + X1_TB);
    float* lnw = (float*)(smem + X1_LNW);
    float* lnb = (float*)(smem + X1_LNB);

    for (int i = tid; i < 208 * 80; i += 512) {
        int o = i / 80, k = i % 80;
        *(__half*)(smem + X1_WH + (o * 88 + k) * 2) = d_Wth[i];
        *(__half*)(smem + X1_WL + (o * 88 + k) * 2) = d_Wtl[i];
    }
    for (int i = tid; i < 208; i += 512) tb_s[i] = d_tb[i];
    if (tid < 80) { lnw[tid] = ln_t_w[tid]; lnb[tid] = ln_t_b[tid]; }

    const int rows_valid = min(128, B - (int)blockIdx.x * 128);

    {
        const float4* tr4 = (const float4*)trunk;
        size_t base4 = (size_t)blockIdx.x * 2560;
        #pragma unroll
        for (int q = 0; q < 5; q++) {
            int il = tid + q * 512;
            int row = il / 20, c = il % 20;
            if (row < rows_valid)
                cp16(sbase + X1_XS + (uint32_t)((row * 84 + 4 * c) * 4), tr4 + base4 + il);
        }
        CP_COMMIT_WAIT();
    }
    __syncthreads();

    if (tid < 256) {
        const int r = tid >> 1, h = tid & 1;
        float4 v[10];
        if (r < rows_valid) {
            const float4* xr = (const float4*)(xs + r * 84 + h * 40);
            #pragma unroll
            for (int j = 0; j < 10; j++) v[j] = xr[j];
        } else {
            #pragma unroll
            for (int j = 0; j < 10; j++) v[j] = make_float4(0.f, 0.f, 0.f, 0.f);
        }
        float s = 0.f, q = 0.f;
        #pragma unroll
        for (int j = 0; j < 10; j++) {
            s += v[j].x + v[j].y + v[j].z + v[j].w;
            q += v[j].x * v[j].x + v[j].y * v[j].y + v[j].z * v[j].z + v[j].w * v[j].w;
        }
        s += __shfl_xor_sync(0xffffffffu, s, 1);
        q += __shfl_xor_sync(0xffffffffu, q, 1);
        float mu = s * (1.f / 80.f);
        float is = rsqrtf(q * (1.f / 80.f) - mu * mu + 1e-5f);
        char* dh = smem + X1_AH + (r * 88 + h * 40) * 2;
        char* dl = dh + (X1_AL - X1_AH);
        const float4* lw4 = (const float4*)(lnw + h * 40);
        const float4* lb4 = (const float4*)(lnb + h * 40);
        #pragma unroll
        for (int j = 0; j < 10; j++) {
            float4 w = lw4[j], b = lb4[j];
            float a0 = (v[j].x - mu) * is * w.x + b.x;
            float a1 = (v[j].y - mu) * is * w.y + b.y;
            float a2 = (v[j].z - mu) * is * w.z + b.z;
            float a3 = (v[j].w - mu) * is * w.w + b.w;
            if (r >= rows_valid) { a0 = a1 = a2 = a3 = 0.f; }
            __half2 h01 = __floats2half2_rn(a0, a1), h23 = __floats2half2_rn(a2, a3);
            __half2 l01 = __floats2half2_rn(a0 - __low2float(h01), a1 - __high2float(h01));
            __half2 l23 = __floats2half2_rn(a2 - __low2float(h23), a3 - __high2float(h23));
            uint2 uh; uh.x = *(uint32_t*)&h01; uh.y = *(uint32_t*)&h23;
            uint2 ul; ul.x = *(uint32_t*)&l01; ul.y = *(uint32_t*)&l23;
            *(uint2*)(dh + j * 8) = uh;
            *(uint2*)(dl + j * 8) = ul;
        }
    }
    __syncthreads();

    {
        const int mt = wid & 7, nh = wid >> 3;
        const int g = lane >> 2, k0 = (lane & 3) * 2;
        const uint32_t abase = sbase + X1_AH +
            (uint32_t)((mt * 16 + (lane & 15)) * 176 + (lane >> 4) * 16);
        uint32_t ah[5][4];
        #pragma unroll
        for (int ks = 0; ks < 5; ks++)
            LDSM_X4(ah[ks][0], ah[ks][1], ah[ks][2], ah[ks][3], abase + ks * 32);

        uint32_t wx4 = sbase + X1_WH +
            (uint32_t)((lane & 7) * 176 + (lane >> 3) * 16) + (uint32_t)(nh * 13 * 1408);
        uint32_t wx2 = sbase + X1_WH +
            (uint32_t)((lane & 7) * 176 + ((lane >> 3) & 1) * 16 + 128) + (uint32_t)(nh * 13 * 1408);

        #pragma unroll
        for (int ni = 0; ni < 13; ni++) {
            const int nt = nh * 13 + ni;
            uint32_t bhA[4], bhB[4], bh2[2], blA[4], blB[4], bl2[2];
            LDSM_X4(bhA[0], bhA[1], bhA[2], bhA[3], wx4);
            LDSM_X4(bhB[0], bhB[1], bhB[2], bhB[3], wx4 + 64);
            LDSM_X2(bh2[0], bh2[1], wx2);
            LDSM_X4(blA[0], blA[1], blA[2], blA[3], wx4 + W1OFF);
            LDSM_X4(blB[0], blB[1], blB[2], blB[3], wx4 + 64 + W1OFF);
            LDSM_X2(bl2[0], bl2[1], wx2 + W1OFF);

            float acc[4] = {0.f, 0.f, 0.f, 0.f};
            mma16816(acc, ah[0], bhA[0], bhA[1]);
            mma16816(acc, ah[1], bhA[2], bhA[3]);
            mma16816(acc, ah[2], bhB[0], bhB[1]);
            mma16816(acc, ah[3], bhB[2], bhB[3]);
            mma16816(acc, ah[4], bh2[0], bh2[1]);
            mma16816(acc, ah[0], blA[0], blA[1]);
            mma16816(acc, ah[1], blA[2], blA[3]);
            mma16816(acc, ah[2], blB[0], blB[1]);
            mma16816(acc, ah[3], blB[2], blB[3]);
            mma16816(acc, ah[4], bl2[0], bl2[1]);
            {
                uint32_t al[4];
                const uint32_t albase = abase + (X1_AL - X1_AH);
                LDSM_X4(al[0], al[1], al[2], al[3], albase);
                mma16816(acc, al, bhA[0], bhA[1]);
                LDSM_X4(al[0], al[1], al[2], al[3], albase + 32);
                mma16816(acc, al, bhA[2], bhA[3]);
                LDSM_X4(al[0], al[1], al[2], al[3], albase + 64);
                mma16816(acc, al, bhB[0], bhB[1]);
                LDSM_X4(al[0], al[1], al[2], al[3], albase + 96);
                mma16816(acc, al, bhB[2], bhB[3]);
                LDSM_X4(al[0], al[1], al[2], al[3], albase + 128);
                mma16816(acc, al, bh2[0], bh2[1]);
            }
            wx4 += 1408; wx2 += 1408;

            const int col = nt * 8 + k0;
            const int row0 = mt * 16 + g, row1 = row0 + 8;
            if (col < 128) {
                float b0 = tb_s[col], b1 = tb_s[col + 1];
                if (row0 < rows_valid) {
                    size_t o = (size_t)((size_t)blockIdx.x * 128 + row0) * 128 + col;
                    d_tproj[o] = acc[0] + b0; d_tproj[o + 1] = acc[1] + b1;
                }
                if (row1 < rows_valid) {
                    size_t o = (size_t)((size_t)blockIdx.x * 128 + row1) * 128 + col;
                    d_tproj[o] = acc[2] + b0; d_tproj[o + 1] = acc[3] + b1;
                }
            } else {
                const int ch = col - 128;
                hs[row0 * 84 + ch] = acc[0]; hs[row0 * 84 + ch + 1] = acc[1];
                hs[row1 * 84 + ch] = acc[2]; hs[row1 * 84 + ch + 1] = acc[3];
                if (row0 < rows_valid) {
                    size_t o = (size_t)((size_t)blockIdx.x * 128 + row0) * 80 + ch;
                    d_h[o] = acc[0]; d_h[o + 1] = acc[1];
                }
                if (row1 < rows_valid) {
                    size_t o = (size_t)((size_t)blockIdx.x * 128 + row1) * 80 + ch;
                    d_h[o] = acc[2]; d_h[o + 1] = acc[3];
                }
            }
        }
    }
    __syncthreads();

    if (tid < 80) {
        float s1 = 0.f, s2 = 0.f;
        for (int r = 0; r < rows_valid; r++) {
            float v = hs[r * 84 + tid];
            s1 += v; s2 += v * v;
        }
        d_partial[blockIdx.x * 160 + tid] = s1;
        d_partial[blockIdx.x * 160 + 80 + tid] = s2;
    }
}

// ------------------------------ BN finalize ------------------------------
__global__ void k_bn(const float* __restrict__ bn_w, const float* __restrict__ bn_b,
                     int B, int nblk) {
    int t = threadIdx.x;
    if (t >= 80) return;
    float S1 = 0.f, S2 = 0.f;
    for (int blk = 0; blk < nblk; blk++) {
        S1 += d_partial[blk * 160 + t];
        S2 += d_partial[blk * 160 + 80 + t];
    }
    float invB = 1.f / (float)B;
    float mu = S1 * invB;
    float var = S2 * invB - mu * mu;
    float sc = bn_w[t] * rsqrtf(var + 1e-5f);
    d_bnscale[t] = sc;
    d_bnshift[t] = bn_b[t] - mu * sc;
}

// ------------------------------ K2: HMMA fused node kernel, pipelined ------------------------------
__global__ __launch_bounds__(256, 2) void k2(const float* __restrict__ node_emb,
                                             const float* __restrict__ ln_n_w,
                                             const float* __restrict__ ln_n_b,
                                             const int* __restrict__ road_pairs,
                                             const int* __restrict__ tile_nodes,
                                             const float* __restrict__ sett2_w, const float* __restrict__ sett2_b,
                                             const float* __restrict__ city2_w, const float* __restrict__ city2_b,
                                             const float* __restrict__ road2_w, const float* __restrict__ road2_b,
                                             const float* __restrict__ rob2_w, const float* __restrict__ rob2_b,
                                             float* __restrict__ out, int B) {
    extern __shared__ char smem[];
    const uint32_t sbase = smem_u32(smem);
    const int tid = threadIdx.x, wid = tid >> 5, lane = tid & 31;

    float* P_s     = (float*)(smem + SM_XP);   // rows x 97
    float* w2_s    = (float*)(smem + SM_W2);
    float* rob2_s  = (float*)(smem + SM_ROB2);
    float* b2_s    = (float*)(smem + SM_B2);
    float* lnw     = (float*)(smem + SM_LNW);
    float* lnb     = (float*)(smem + SM_LNB);
    int*   rp_s    = (int*)(smem + SM_RP);
    int*   ti_s    = (int*)(smem + SM_TI);

    for (int i = tid; i < 160 * 48; i += 256) {
        int n = i / 48, k = i % 48;
        *(__half*)(smem + SM_WH + (n * 56 + k) * 2) = d_Wh[i];
        *(__half*)(smem + SM_WL + (n * 56 + k) * 2) = d_Wl[i];
    }
    if (tid < 48) { lnw[tid] = ln_n_w[tid]; lnb[tid] = ln_n_b[tid]; }
    if (tid < 32) { w2_s[tid] = sett2_w[tid]; w2_s[32 + tid] = city2_w[tid]; w2_s[64 + tid] = road2_w[tid]; }
    if (tid < 160) rob2_s[tid] = rob2_w[tid];
    if (tid == 0) { b2_s[0] = sett2_b[0]; b2_s[1] = city2_b[0]; b2_s[2] = road2_b[0]; }
    if (tid < 5) b2_s[3 + tid] = rob2_b[tid];
    if (tid < 144) rp_s[tid] = road_pairs[tid];
    if (tid < 114) ti_s[tid] = tile_nodes[tid];

    const int g = lane >> 2;
    const int k0 = (lane & 3) * 2;
    const int mrow = (wid & 3) * 32;
    const int hd = wid >> 2;              // 0 = sett group, 1 = city group

    int rown[4]; int tpoff[4];
    #pragma unroll
    for (int s = 0; s < 4; s++) {
        rown[s] = mrow + 16 * (s >> 1) + 8 * (s & 1) + g;
        tpoff[s] = (rown[s] >= 54) ? 128 : 0;
    }

    const uint32_t wx4base0 = sbase + SM_WH +
        (uint32_t)((lane & 7) * 112 + (lane >> 3) * 16);
    const uint32_t wx2base0 = sbase + SM_WH +
        (uint32_t)((lane & 7) * 112 + ((lane >> 3) & 1) * 16 + 64);

    const long npairs = ((long)B + 1) / 2;
    const size_t totp4 = (size_t)B * 32;
    const float4* tp4 = (const float4*)d_tproj;

    // ---- prologue: LN-A + tproj prefetch for first pair into buf 0 ----
    long pair = blockIdx.x;
    int buf = 0;
    if (pair < npairs) {
        const int nr = (int)((long)B * 54 - pair * 108 >= 108 ? 108 : (long)B * 54 - pair * 108);
        if (tid < nr) {
            const float4* xr = (const float4*)(node_emb + ((size_t)pair * 108 + tid) * 48);
            float s = 0.f, q = 0.f;
            #pragma unroll
            for (int j = 0; j < 12; j++) {
                float4 v = xr[j];
                s += v.x + v.y + v.z + v.w;
                q += v.x * v.x + v.y * v.y + v.z * v.z + v.w * v.w;
            }
            float mu = s * (1.f / 48.f);
            ((float*)(smem + SM_MU))[tid] = mu;
            ((float*)(smem + SM_IS))[tid] = rsqrtf(q * (1.f / 48.f) - mu * mu + 1e-5f);
        }
        if (tid < 64) {
            size_t t4 = (size_t)pair * 64 + tid;
            if (t4 < totp4) cp16(sbase + SM_TPROJ + tid * 16, tp4 + t4);
        }
        CP_COMMIT();
    }

    for (; pair < npairs; pair += gridDim.x, buf ^= 1) {
        const float* mu_s = (const float*)(smem + SM_MU + buf * 448);
        const float* is_s = (const float*)(smem + SM_IS + buf * 448);
        const float* tpb  = (const float*)(smem + SM_TPROJ + buf * 1024);

        CP_WAIT_ALL();          // tproj(buf) landed
        __syncthreads();        // LN-A(buf) writes visible; prev heads done with P_s

        const int nrows = (int)((long)B * 54 - pair * 108 >= 108 ? 108 : (long)B * 54 - pair * 108);

        // ---- LN phase B: re-read gmem (L1-resident), split into AH/AL ----
        for (int i = tid; i < 2592; i += 256) {
            int r = i / 24, c2 = (i % 24) * 2;
            if (r < nrows) {
                float2 v = *(const float2*)(node_emb + ((size_t)pair * 108 + r) * 48 + c2);
                float mu = mu_s[r], is = is_s[r];
                float v0 = (v.x - mu) * is * lnw[c2] + lnb[c2];
                float v1 = (v.y - mu) * is * lnw[c2 + 1] + lnb[c2 + 1];
                __half2 h = __floats2half2_rn(v0, v1);
                __half2 l = __floats2half2_rn(v0 - __low2float(h), v1 - __high2float(h));
                *(__half2*)(smem + SM_AH + (r * 56 + c2) * 2) = h;
                *(__half2*)(smem + SM_AL + (r * 56 + c2) * 2) = l;
            }
        }
        __syncthreads();

        // ---- A fragments (plain LDS; compiler-scheduled) ----
        uint32_t afh[2][3][4], afl[2][3][4];
        #pragma unroll
        for (int t = 0; t < 2; t++) {
            #pragma unroll
            for (int ks = 0; ks < 3; ks++) {
                const char* ba = smem + SM_AH + ((mrow + 16 * t + g) * 56 + k0 + 16 * ks) * 2;
                afh[t][ks][0] = *(const uint32_t*)(ba);
                afh[t][ks][1] = *(const uint32_t*)(ba + 896);
                afh[t][ks][2] = *(const uint32_t*)(ba + 16);
                afh[t][ks][3] = *(const uint32_t*)(ba + 896 + 16);
                const char* bl = ba + (SM_AL - SM_AH);
                afl[t][ks][0] = *(const uint32_t*)(bl);
                afl[t][ks][1] = *(const uint32_t*)(bl + 896);
                afl[t][ks][2] = *(const uint32_t*)(bl + 16);
                afl[t][ks][3] = *(const uint32_t*)(bl + 896 + 16);
            }
        }

        // ---- prefetch next pair: LN-A + tproj into buf^1 (hides under MMA) ----
        {
            long nxt = pair + gridDim.x;
            if (nxt < npairs) {
                const int nr = (int)((long)B * 54 - nxt * 108 >= 108 ? 108 : (long)B * 54 - nxt * 108);
                if (tid < nr) {
                    const float4* xr = (const float4*)(node_emb + ((size_t)nxt * 108 + tid) * 48);
                    float s = 0.f, q = 0.f;
                    #pragma unroll
                    for (int j = 0; j < 12; j++) {
                        float4 v = xr[j];
                        s += v.x + v.y + v.z + v.w;
                        q += v.x * v.x + v.y * v.y + v.z * v.z + v.w * v.w;
                    }
                    float mu = s * (1.f / 48.f);
                    ((float*)(smem + SM_MU + (buf ^ 1) * 448))[tid] = mu;
                    ((float*)(smem + SM_IS + (buf ^ 1) * 448))[tid] =
                        rsqrtf(q * (1.f / 48.f) - mu * mu + 1e-5f);
                }
                if (tid < 64) {
                    size_t t4 = (size_t)nxt * 64 + tid;
                    if (t4 < totp4)
                        cp16(sbase + SM_TPROJ + (buf ^ 1) * 1024 + tid * 16, tp4 + t4);
                }
                CP_COMMIT();
            }
        }

        float sacc[4] = {0.f, 0.f, 0.f, 0.f};

        // nt map: hd=0 -> {0,1,2,3, 8..13}; hd=1 -> {4,5,6,7, 14..19}
        #pragma unroll
        for (int ni = 0; ni < 10; ni++) {
            const int nt = (ni < 4) ? (4 * hd + ni) : (8 + 6 * hd + (ni - 4));
            uint32_t bh[4], bh2[2], bl[4], bl2[2];
            LDSM_X4_NV(bh[0], bh[1], bh[2], bh[3], wx4base0 + nt * 896);
            LDSM_X2_NV(bh2[0], bh2[1], wx2base0 + nt * 896);
            LDSM_X4_NV(bl[0], bl[1], bl[2], bl[3], wx4base0 + nt * 896 + WLOFF);
            LDSM_X2_NV(bl2[0], bl2[1], wx2base0 + nt * 896 + WLOFF);

            float acc[2][4] = {{0.f, 0.f, 0.f, 0.f}, {0.f, 0.f, 0.f, 0.f}};
            #pragma unroll
            for (int t = 0; t < 2; t++) {
                mma16816(acc[t], afh[t][0], bh[0], bh[1]);
                mma16816(acc[t], afh[t][1], bh[2], bh[3]);
                mma16816(acc[t], afh[t][2], bh2[0], bh2[1]);
                mma16816(acc[t], afh[t][0], bl[0], bl[1]);
                mma16816(acc[t], afh[t][1], bl[2], bl[3]);
                mma16816(acc[t], afh[t][2], bl2[0], bl2[1]);
                mma16816(acc[t], afl[t][0], bh[0], bh[1]);
                mma16816(acc[t], afl[t][1], bh[2], bh[3]);
                mma16816(acc[t], afl[t][2], bh2[0], bh2[1]);
            }
            const int col = nt * 8 + k0;
            if (ni < 4) {
                float w2a = w2_s[col], w2b = w2_s[col + 1];
                #pragma unroll
                for (int s = 0; s < 4; s++) {
                    float v0 = acc[s >> 1][2 * (s & 1)];
                    float v1 = acc[s >> 1][2 * (s & 1) + 1];
                    sacc[s] += mishf(v0 + tpb[tpoff[s] + col]) * w2a
                             + mishf(v1 + tpb[tpoff[s] + col + 1]) * w2b;
                }
            } else {
                #pragma unroll
                for (int s = 0; s < 4; s++) {
                    int r = rown[s];
                    if (r < 108) {
                        float* pr = P_s + r * 97 + (col - 64);
                        pr[0] = acc[s >> 1][2 * (s & 1)];
                        pr[1] = acc[s >> 1][2 * (s & 1) + 1];
                    }
                }
            }
        }

        // sett/city finalize: every warp reduces its single head
        {
            #pragma unroll
            for (int s = 0; s < 4; s++) {
                sacc[s] += __shfl_xor_sync(0xffffffffu, sacc[s], 1);
                sacc[s] += __shfl_xor_sync(0xffffffffu, sacc[s], 2);
            }
            if ((lane & 3) == 0) {
                #pragma unroll
                for (int s = 0; s < 4; s++) {
                    int r = rown[s];
                    if (r < nrows) {
                        int bl = (r >= 54) ? 1 : 0;
                        int n = r - 54 * bl;
                        out[((size_t)(pair * 2 + bl)) * 397 + 5 + 54 * hd + n] = sacc[s] + b2_s[hd];
                    }
                }
            }
        }
        __syncthreads();

        const int nb = (nrows > 54) ? 2 : 1;
        // ---- road heads: 4 edges per warp-task, 8-lane groups ----
        {
            const int sub = lane >> 3, c = lane & 7;
            for (int t = wid; t < nb * 18; t += 8) {
                int bl = (t >= 18) ? 1 : 0;
                int tg = t - 18 * bl;
                int e = tg * 4 + sub;
                int sN = rp_s[2 * e], dN = rp_s[2 * e + 1];
                const float* tp = tpb + bl * 128 + 64;
                const float* Ps = P_s + (bl * 54 + sN) * 97;
                const float* Pd = P_s + (bl * 54 + dN) * 97 + 32;
                float part = 0.f;
                #pragma unroll
                for (int j = 0; j < 4; j++) {
                    int cj = c + 8 * j;
                    part += mishf(tp[cj] + Ps[cj] + Pd[cj]) * w2_s[64 + cj];
                }
                part += __shfl_xor_sync(0xffffffffu, part, 1);
                part += __shfl_xor_sync(0xffffffffu, part, 2);
                part += __shfl_xor_sync(0xffffffffu, part, 4);
                if (c == 0) out[((size_t)(pair * 2 + bl)) * 397 + 113 + e] = part + b2_s[2];
            }
        }
        // ---- robber heads ----
        for (int t = wid; t < nb * 19; t += 8) {
            int bl = (t >= 19) ? 1 : 0;
            int tt = t - 19 * bl;
            float a = 0.f;
            #pragma unroll
            for (int i = 0; i < 6; i++)
                a += P_s[(bl * 54 + ti_s[tt * 6 + i]) * 97 + 64 + lane];
            float m = mishf(tpb[bl * 128 + 96 + lane] + a * (1.f / 6.f));
            #pragma unroll
            for (int o = 0; o < 5; o++) {
                float red = warp_sum(m * rob2_s[o * 32 + lane]);
                if (lane == 0)
                    out[((size_t)(pair * 2 + bl)) * 397 + 185 + tt * 5 + o] = red + b2_s[3 + o];
            }
        }
        // (no end barrier: next iteration's top barrier protects P_s/tproj)
    }
}

// ------------------------------ K3: BN + mish + gfc2, 8-row batched ------------------------------
__global__ __launch_bounds__(128) void k3(const float* __restrict__ gfc2_w,
                                          const float* __restrict__ gfc2_b,
                                          float* __restrict__ out, int B) {
    __shared__ __align__(16) float m8[80 * 8];
    __shared__ __align__(16) float Wg[80 * 122];
    __shared__ float bs[122];
    __shared__ float sc[80], sh[80];
    int tid = threadIdx.x;
    for (int i = tid; i < 80 * 122; i += 128) {
        int k = i / 122, t = i % 122;
        int r = (t < 5) ? t : (275 + t);
        Wg[i] = gfc2_w[r * 80 + k];
    }
    if (tid < 122) { int r = (tid < 5) ? tid : (275 + tid); bs[tid] = gfc2_b[r]; }
    if (tid < 80) { sc[tid] = d_bnscale[tid]; sh[tid] = d_bnshift[tid]; }
    __syncthreads();
    int nq = (B + 7) >> 3;
    for (int qb = blockIdx.x; qb < nq; qb += gridDim.x) {
        if (tid < 80) {
            #pragma unroll
            for (int rb = 0; rb < 8; rb++) {
                int b = qb * 8 + rb;
                float v = (b < B) ? d_h[(size_t)b * 80 + tid] : 0.f;
                m8[tid * 8 + rb] = mishf(v * sc[tid] + sh[tid]);
            }
        }
        __syncthreads();
        if (tid < 122) {
            float a[8];
            #pragma unroll
            for (int rb = 0; rb < 8; rb++) a[rb] = bs[tid];
            for (int k = 0; k < 80; k++) {
                float4 mA = *(const float4*)(m8 + k * 8);
                float4 mB = *(const float4*)(m8 + k * 8 + 4);
                float w = Wg[k * 122 + tid];
                a[0] += mA.x * w; a[1] += mA.y * w; a[2] += mA.z * w; a[3] += mA.w * w;
                a[4] += mB.x * w; a[5] += mB.y * w; a[6] += mB.z * w; a[7] += mB.w * w;
            }
            int col = (tid < 5) ? tid : (275 + tid);
            #pragma unroll
            for (int rb = 0; rb < 8; rb++) {
                int b = qb * 8 + rb;
                if (b < B) out[(size_t)b * 397 + col] = a[rb];
            }
        }
        __syncthreads();
    }
}

// ------------------------------ launch ------------------------------
extern "C" void kernel_launch(void* const* d_in, const int* in_sizes, int n_in,
                              void* d_out, int out_size) {
    const float* trunk      = (const float*)d_in[0];
    const float* node_emb   = (const float*)d_in[1];
    const int*   road_pairs = (const int*)d_in[2];
    const int*   tile_nodes = (const int*)d_in[3];
    const float* ln_t_w = (const float*)d_in[4];
    const float* ln_t_b = (const float*)d_in[5];
    const float* ln_n_w = (const float*)d_in[6];
    const float* ln_n_b = (const float*)d_in[7];
    const float* gfc1_w = (const float*)d_in[8];
    const float* gfc1_b = (const float*)d_in[9];
    const float* bn_w   = (const float*)d_in[10];
    const float* bn_b   = (const float*)d_in[11];
    const float* gfc2_w = (const float*)d_in[12];
    const float* gfc2_b = (const float*)d_in[13];
    const float* sett1_w = (const float*)d_in[14];
    const float* sett1_b = (const float*)d_in[15];
    const float* sett2_w = (const float*)d_in[16];
    const float* sett2_b = (const float*)d_in[17];
    const float* city1_w = (const float*)d_in[18];
    const float* city1_b = (const float*)d_in[19];
    const float* city2_w = (const float*)d_in[20];
    const float* city2_b = (const float*)d_in[21];
    const float* road1_w = (const float*)d_in[22];
    const float* road1_b = (const float*)d_in[23];
    const float* road2_w = (const float*)d_in[24];
    const float* road2_b = (const float*)d_in[25];
    const float* rob1_w = (const float*)d_in[26];
    const float* rob1_b = (const float*)d_in[27];
    const float* rob2_w = (const float*)d_in[28];
    const float* rob2_b = (const float*)d_in[29];

    int B = in_sizes[0] / 80;
    if (B > BMAX) B = BMAX;
    float* out = (float*)d_out;
    int nblk1 = (B + 127) / 128;

    cudaFuncSetAttribute(k1, cudaFuncAttributeMaxDynamicSharedMemorySize, K1_SMEM);
    cudaFuncSetAttribute(k2, cudaFuncAttributeMaxDynamicSharedMemorySize, SM_TOTAL);

    k_prep<<<(208 * 80 + 255) / 256, 256>>>(sett1_w, city1_w, road1_w, rob1_w, gfc1_w,
                                            sett1_b, city1_b, road1_b, rob1_b, gfc1_b);
    k1<<<nblk1, 512, K1_SMEM>>>(trunk, ln_t_w, ln_t_b, B);
    k_bn<<<1, 80>>>(bn_w, bn_b, B, nblk1);
    k2<<<K2_GRID, 256, SM_TOTAL>>>(node_emb, ln_n_w, ln_n_b, road_pairs, tile_nodes,
                                   sett2_w, sett2_b, city2_w, city2_b,
                                   road2_w, road2_b, rob2_w, rob2_b, out, B);
    k3<<<K3_GRID, 128>>>(gfc2_w, gfc2_b, out, B);
}

// round 11
// speedup vs baseline: 1.0665x; 1.0665x over previous
#include <cuda_runtime.h>
#include <cuda_fp16.h>
#include <cstdint>
#include <cstddef>

// ---------------------------------------------------------------------------
// SmallSpatialPolicyHead — R10 + k2: A-frags via ldmatrix (volatile),
// LN-phase-B at float4 granularity. Targets the 64%-utilized L1 pipe.
// ---------------------------------------------------------------------------

#define BMAX 16384
#define K2_GRID 296
#define K3_GRID 592

__device__ float d_tb[208];
__device__ __half d_Wh[160 * 48];    // k2 node proj hi  [n][k]
__device__ __half d_Wl[160 * 48];    // k2 node proj lo
__device__ __half d_Wth[208 * 80];   // k1 trunk proj hi [o][k]
__device__ __half d_Wtl[208 * 80];   // k1 trunk proj lo
__device__ float d_tproj[(size_t)BMAX * 128];
__device__ float d_h[(size_t)BMAX * 80];
__device__ float d_partial[296 * 160];
__device__ float d_bnscale[80];
__device__ float d_bnshift[80];

// ---- k2 smem byte offsets ----
#define SM_XP    0             // P_s 108x97 f = 41904
#define SM_AH    41920         // 128x56 fp16 = 14336
#define SM_AL    56256
#define SM_WH    70592         // 160x56 fp16 = 17920
#define SM_WL    88512
#define WLOFF    17920
#define SM_TPROJ 106432        // 2 x 256 f (double buffer)
#define SM_W2    108480        // 96 f
#define SM_ROB2  108864        // 160 f
#define SM_B2    109504        // 8 f
#define SM_LNW   109536        // 48 f
#define SM_LNB   109728        // 48 f
#define SM_MU    109920        // 2 x 110 f (double buffer, 448B each)
#define SM_IS    110816        // 2 x 110 f
#define SM_RP    111712        // 144 i
#define SM_TI    112288        // 114 i
#define SM_TOTAL 112752

// ---- k1 smem byte offsets ----
#define X1_XS    0             // 128x84 f = 43008 (reused as hs)
#define X1_AH    43008         // 128x88 fp16 = 22528
#define X1_AL    65536
#define X1_WH    88064         // 208x88 fp16 = 36608
#define X1_WL    124672
#define W1OFF    36608
#define X1_TB    161280        // 208 f
#define X1_LNW   162112        // 80 f
#define X1_LNB   162432        // 80 f
#define K1_SMEM  162752

__device__ __forceinline__ uint32_t smem_u32(const void* p) {
    uint32_t a;
    asm("{ .reg .u64 t; cvta.to.shared.u64 t, %1; cvt.u32.u64 %0, t; }" : "=r"(a) : "l"(p));
    return a;
}
__device__ __forceinline__ void cp16(uint32_t dst, const void* src) {
    asm volatile("cp.async.cg.shared.global [%0], [%1], 16;" :: "r"(dst), "l"(src));
}
#define CP_COMMIT() asm volatile("cp.async.commit_group;" ::: "memory")
#define CP_WAIT_ALL() asm volatile("cp.async.wait_group 0;" ::: "memory")
#define CP_COMMIT_WAIT() do { CP_COMMIT(); CP_WAIT_ALL(); } while (0)

#define LDSM_X4(r0,r1,r2,r3,addr) \
    asm volatile("ldmatrix.sync.aligned.m8n8.x4.shared.b16 {%0,%1,%2,%3}, [%4];" \
        : "=r"(r0),"=r"(r1),"=r"(r2),"=r"(r3) : "r"(addr))
#define LDSM_X2(r0,r1,addr) \
    asm volatile("ldmatrix.sync.aligned.m8n8.x2.shared.b16 {%0,%1}, [%2];" \
        : "=r"(r0),"=r"(r1) : "r"(addr))
#define LDSM_X4_NV(r0,r1,r2,r3,addr) \
    asm("ldmatrix.sync.aligned.m8n8.x4.shared.b16 {%0,%1,%2,%3}, [%4];" \
        : "=r"(r0),"=r"(r1),"=r"(r2),"=r"(r3) : "r"(addr))
#define LDSM_X2_NV(r0,r1,addr) \
    asm("ldmatrix.sync.aligned.m8n8.x2.shared.b16 {%0,%1}, [%2];" \
        : "=r"(r0),"=r"(r1) : "r"(addr))

__device__ __forceinline__ void mma16816(float* d, const uint32_t* a, uint32_t b0, uint32_t b1) {
    asm volatile(
        "mma.sync.aligned.m16n8k16.row.col.f32.f16.f16.f32 "
        "{%0,%1,%2,%3},{%4,%5,%6,%7},{%8,%9},{%0,%1,%2,%3};"
        : "+f"(d[0]), "+f"(d[1]), "+f"(d[2]), "+f"(d[3])
        : "r"(a[0]), "r"(a[1]), "r"(a[2]), "r"(a[3]), "r"(b0), "r"(b1));
}

__device__ __forceinline__ float mishf(float x) {
    float u = __expf(fminf(x, 15.f));
    float d = __fmaf_rn(u, u + 2.f, 2.f);
    return x - __fdividef(2.f * x, d);
}
__device__ __forceinline__ float warp_sum(float v) {
    #pragma unroll
    for (int o = 16; o; o >>= 1) v += __shfl_xor_sync(0xffffffffu, v, o);
    return v;
}

// ------------------------------ prep ------------------------------
__global__ void k_prep(const float* __restrict__ sett1_w, const float* __restrict__ city1_w,
                       const float* __restrict__ road1_w, const float* __restrict__ rob1_w,
                       const float* __restrict__ gfc1_w,
                       const float* __restrict__ sett1_b, const float* __restrict__ city1_b,
                       const float* __restrict__ road1_b, const float* __restrict__ rob1_b,
                       const float* __restrict__ gfc1_b) {
    int i = blockIdx.x * blockDim.x + threadIdx.x;
    if (i < 160 * 48) {
        int j = i / 48, k = i % 48;
        float v;
        if (j < 32)       v = sett1_w[j * 128 + 80 + k];
        else if (j < 64)  v = city1_w[(j - 32) * 128 + 80 + k];
        else if (j < 96)  v = road1_w[(j - 64) * 176 + 80 + k];
        else if (j < 128) v = road1_w[(j - 96) * 176 + 128 + k];
        else              v = rob1_w[(j - 128) * 128 + 80 + k];
        __half h = __float2half(v);
        d_Wh[i] = h;
        d_Wl[i] = __float2half(v - __half2float(h));
    }
    if (i < 208 * 80) {
        int o = i / 80, k = i % 80;
        float v;
        if (o < 32)       v = sett1_w[o * 128 + k];
        else if (o < 64)  v = city1_w[(o - 32) * 128 + k];
        else if (o < 96)  v = road1_w[(o - 64) * 176 + k];
        else if (o < 128) v = rob1_w[(o - 96) * 128 + k];
        else              v = gfc1_w[(o - 128) * 80 + k];
        __half h = __float2half(v);
        d_Wth[i] = h;
        d_Wtl[i] = __float2half(v - __half2float(h));
    }
    if (i < 208) {
        float v;
        if (i < 32)       v = sett1_b[i];
        else if (i < 64)  v = city1_b[i - 32];
        else if (i < 96)  v = road1_b[i - 64];
        else if (i < 128) v = rob1_b[i - 96];
        else              v = gfc1_b[i - 128];
        d_tb[i] = v;
    }
}

// ------------------------------ K1: HMMA trunk kernel (unchanged, proven) ------------------------------
__global__ __launch_bounds__(512, 1) void k1(const float* __restrict__ trunk,
                                             const float* __restrict__ ln_t_w,
                                             const float* __restrict__ ln_t_b, int B) {
    extern __shared__ char smem[];
    const uint32_t sbase = smem_u32(smem);
    const int tid = threadIdx.x, wid = tid >> 5, lane = tid & 31;

    float* xs  = (float*)(smem + X1_XS);
    float* hs  = (float*)(smem + X1_XS);
    float* tb_s = (float*)(smem + X1_TB);
    float* lnw = (float*)(smem + X1_LNW);
    float* lnb = (float*)(smem + X1_LNB);

    for (int i = tid; i < 208 * 80; i += 512) {
        int o = i / 80, k = i % 80;
        *(__half*)(smem + X1_WH + (o * 88 + k) * 2) = d_Wth[i];
        *(__half*)(smem + X1_WL + (o * 88 + k) * 2) = d_Wtl[i];
    }
    for (int i = tid; i < 208; i += 512) tb_s[i] = d_tb[i];
    if (tid < 80) { lnw[tid] = ln_t_w[tid]; lnb[tid] = ln_t_b[tid]; }

    const int rows_valid = min(128, B - (int)blockIdx.x * 128);

    {
        const float4* tr4 = (const float4*)trunk;
        size_t base4 = (size_t)blockIdx.x * 2560;
        #pragma unroll
        for (int q = 0; q < 5; q++) {
            int il = tid + q * 512;
            int row = il / 20, c = il % 20;
            if (row < rows_valid)
                cp16(sbase + X1_XS + (uint32_t)((row * 84 + 4 * c) * 4), tr4 + base4 + il);
        }
        CP_COMMIT_WAIT();
    }
    __syncthreads();

    if (tid < 256) {
        const int r = tid >> 1, h = tid & 1;
        float4 v[10];
        if (r < rows_valid) {
            const float4* xr = (const float4*)(xs + r * 84 + h * 40);
            #pragma unroll
            for (int j = 0; j < 10; j++) v[j] = xr[j];
        } else {
            #pragma unroll
            for (int j = 0; j < 10; j++) v[j] = make_float4(0.f, 0.f, 0.f, 0.f);
        }
        float s = 0.f, q = 0.f;
        #pragma unroll
        for (int j = 0; j < 10; j++) {
            s += v[j].x + v[j].y + v[j].z + v[j].w;
            q += v[j].x * v[j].x + v[j].y * v[j].y + v[j].z * v[j].z + v[j].w * v[j].w;
        }
        s += __shfl_xor_sync(0xffffffffu, s, 1);
        q += __shfl_xor_sync(0xffffffffu, q, 1);
        float mu = s * (1.f / 80.f);
        float is = rsqrtf(q * (1.f / 80.f) - mu * mu + 1e-5f);
        char* dh = smem + X1_AH + (r * 88 + h * 40) * 2;
        char* dl = dh + (X1_AL - X1_AH);
        const float4* lw4 = (const float4*)(lnw + h * 40);
        const float4* lb4 = (const float4*)(lnb + h * 40);
        #pragma unroll
        for (int j = 0; j < 10; j++) {
            float4 w = lw4[j], b = lb4[j];
            float a0 = (v[j].x - mu) * is * w.x + b.x;
            float a1 = (v[j].y - mu) * is * w.y + b.y;
            float a2 = (v[j].z - mu) * is * w.z + b.z;
            float a3 = (v[j].w - mu) * is * w.w + b.w;
            if (r >= rows_valid) { a0 = a1 = a2 = a3 = 0.f; }
            __half2 h01 = __floats2half2_rn(a0, a1), h23 = __floats2half2_rn(a2, a3);
            __half2 l01 = __floats2half2_rn(a0 - __low2float(h01), a1 - __high2float(h01));
            __half2 l23 = __floats2half2_rn(a2 - __low2float(h23), a3 - __high2float(h23));
            uint2 uh; uh.x = *(uint32_t*)&h01; uh.y = *(uint32_t*)&h23;
            uint2 ul; ul.x = *(uint32_t*)&l01; ul.y = *(uint32_t*)&l23;
            *(uint2*)(dh + j * 8) = uh;
            *(uint2*)(dl + j * 8) = ul;
        }
    }
    __syncthreads();

    {
        const int mt = wid & 7, nh = wid >> 3;
        const int g = lane >> 2, k0 = (lane & 3) * 2;
        const uint32_t abase = sbase + X1_AH +
            (uint32_t)((mt * 16 + (lane & 15)) * 176 + (lane >> 4) * 16);
        uint32_t ah[5][4];
        #pragma unroll
        for (int ks = 0; ks < 5; ks++)
            LDSM_X4(ah[ks][0], ah[ks][1], ah[ks][2], ah[ks][3], abase + ks * 32);

        uint32_t wx4 = sbase + X1_WH +
            (uint32_t)((lane & 7) * 176 + (lane >> 3) * 16) + (uint32_t)(nh * 13 * 1408);
        uint32_t wx2 = sbase + X1_WH +
            (uint32_t)((lane & 7) * 176 + ((lane >> 3) & 1) * 16 + 128) + (uint32_t)(nh * 13 * 1408);

        #pragma unroll
        for (int ni = 0; ni < 13; ni++) {
            const int nt = nh * 13 + ni;
            uint32_t bhA[4], bhB[4], bh2[2], blA[4], blB[4], bl2[2];
            LDSM_X4(bhA[0], bhA[1], bhA[2], bhA[3], wx4);
            LDSM_X4(bhB[0], bhB[1], bhB[2], bhB[3], wx4 + 64);
            LDSM_X2(bh2[0], bh2[1], wx2);
            LDSM_X4(blA[0], blA[1], blA[2], blA[3], wx4 + W1OFF);
            LDSM_X4(blB[0], blB[1], blB[2], blB[3], wx4 + 64 + W1OFF);
            LDSM_X2(bl2[0], bl2[1], wx2 + W1OFF);

            float acc[4] = {0.f, 0.f, 0.f, 0.f};
            mma16816(acc, ah[0], bhA[0], bhA[1]);
            mma16816(acc, ah[1], bhA[2], bhA[3]);
            mma16816(acc, ah[2], bhB[0], bhB[1]);
            mma16816(acc, ah[3], bhB[2], bhB[3]);
            mma16816(acc, ah[4], bh2[0], bh2[1]);
            mma16816(acc, ah[0], blA[0], blA[1]);
            mma16816(acc, ah[1], blA[2], blA[3]);
            mma16816(acc, ah[2], blB[0], blB[1]);
            mma16816(acc, ah[3], blB[2], blB[3]);
            mma16816(acc, ah[4], bl2[0], bl2[1]);
            {
                uint32_t al[4];
                const uint32_t albase = abase + (X1_AL - X1_AH);
                LDSM_X4(al[0], al[1], al[2], al[3], albase);
                mma16816(acc, al, bhA[0], bhA[1]);
                LDSM_X4(al[0], al[1], al[2], al[3], albase + 32);
                mma16816(acc, al, bhA[2], bhA[3]);
                LDSM_X4(al[0], al[1], al[2], al[3], albase + 64);
                mma16816(acc, al, bhB[0], bhB[1]);
                LDSM_X4(al[0], al[1], al[2], al[3], albase + 96);
                mma16816(acc, al, bhB[2], bhB[3]);
                LDSM_X4(al[0], al[1], al[2], al[3], albase + 128);
                mma16816(acc, al, bh2[0], bh2[1]);
            }
            wx4 += 1408; wx2 += 1408;

            const int col = nt * 8 + k0;
            const int row0 = mt * 16 + g, row1 = row0 + 8;
            if (col < 128) {
                float b0 = tb_s[col], b1 = tb_s[col + 1];
                if (row0 < rows_valid) {
                    size_t o = (size_t)((size_t)blockIdx.x * 128 + row0) * 128 + col;
                    d_tproj[o] = acc[0] + b0; d_tproj[o + 1] = acc[1] + b1;
                }
                if (row1 < rows_valid) {
                    size_t o = (size_t)((size_t)blockIdx.x * 128 + row1) * 128 + col;
                    d_tproj[o] = acc[2] + b0; d_tproj[o + 1] = acc[3] + b1;
                }
            } else {
                const int ch = col - 128;
                hs[row0 * 84 + ch] = acc[0]; hs[row0 * 84 + ch + 1] = acc[1];
                hs[row1 * 84 + ch] = acc[2]; hs[row1 * 84 + ch + 1] = acc[3];
                if (row0 < rows_valid) {
                    size_t o = (size_t)((size_t)blockIdx.x * 128 + row0) * 80 + ch;
                    d_h[o] = acc[0]; d_h[o + 1] = acc[1];
                }
                if (row1 < rows_valid) {
                    size_t o = (size_t)((size_t)blockIdx.x * 128 + row1) * 80 + ch;
                    d_h[o] = acc[2]; d_h[o + 1] = acc[3];
                }
            }
        }
    }
    __syncthreads();

    if (tid < 80) {
        float s1 = 0.f, s2 = 0.f;
        for (int r = 0; r < rows_valid; r++) {
            float v = hs[r * 84 + tid];
            s1 += v; s2 += v * v;
        }
        d_partial[blockIdx.x * 160 + tid] = s1;
        d_partial[blockIdx.x * 160 + 80 + tid] = s2;
    }
}

// ------------------------------ BN finalize ------------------------------
__global__ void k_bn(const float* __restrict__ bn_w, const float* __restrict__ bn_b,
                     int B, int nblk) {
    int t = threadIdx.x;
    if (t >= 80) return;
    float S1 = 0.f, S2 = 0.f;
    for (int blk = 0; blk < nblk; blk++) {
        S1 += d_partial[blk * 160 + t];
        S2 += d_partial[blk * 160 + 80 + t];
    }
    float invB = 1.f / (float)B;
    float mu = S1 * invB;
    float var = S2 * invB - mu * mu;
    float sc = bn_w[t] * rsqrtf(var + 1e-5f);
    d_bnscale[t] = sc;
    d_bnshift[t] = bn_b[t] - mu * sc;
}

// ------------------------------ K2: HMMA fused node kernel, pipelined ------------------------------
__global__ __launch_bounds__(256, 2) void k2(const float* __restrict__ node_emb,
                                             const float* __restrict__ ln_n_w,
                                             const float* __restrict__ ln_n_b,
                                             const int* __restrict__ road_pairs,
                                             const int* __restrict__ tile_nodes,
                                             const float* __restrict__ sett2_w, const float* __restrict__ sett2_b,
                                             const float* __restrict__ city2_w, const float* __restrict__ city2_b,
                                             const float* __restrict__ road2_w, const float* __restrict__ road2_b,
                                             const float* __restrict__ rob2_w, const float* __restrict__ rob2_b,
                                             float* __restrict__ out, int B) {
    extern __shared__ char smem[];
    const uint32_t sbase = smem_u32(smem);
    const int tid = threadIdx.x, wid = tid >> 5, lane = tid & 31;

    float* P_s     = (float*)(smem + SM_XP);   // rows x 97
    float* w2_s    = (float*)(smem + SM_W2);
    float* rob2_s  = (float*)(smem + SM_ROB2);
    float* b2_s    = (float*)(smem + SM_B2);
    float* lnw     = (float*)(smem + SM_LNW);
    float* lnb     = (float*)(smem + SM_LNB);
    int*   rp_s    = (int*)(smem + SM_RP);
    int*   ti_s    = (int*)(smem + SM_TI);

    for (int i = tid; i < 160 * 48; i += 256) {
        int n = i / 48, k = i % 48;
        *(__half*)(smem + SM_WH + (n * 56 + k) * 2) = d_Wh[i];
        *(__half*)(smem + SM_WL + (n * 56 + k) * 2) = d_Wl[i];
    }
    if (tid < 48) { lnw[tid] = ln_n_w[tid]; lnb[tid] = ln_n_b[tid]; }
    if (tid < 32) { w2_s[tid] = sett2_w[tid]; w2_s[32 + tid] = city2_w[tid]; w2_s[64 + tid] = road2_w[tid]; }
    if (tid < 160) rob2_s[tid] = rob2_w[tid];
    if (tid == 0) { b2_s[0] = sett2_b[0]; b2_s[1] = city2_b[0]; b2_s[2] = road2_b[0]; }
    if (tid < 5) b2_s[3 + tid] = rob2_b[tid];
    if (tid < 144) rp_s[tid] = road_pairs[tid];
    if (tid < 114) ti_s[tid] = tile_nodes[tid];

    const int g = lane >> 2;
    const int k0 = (lane & 3) * 2;
    const int mrow = (wid & 3) * 32;
    const int hd = wid >> 2;              // 0 = sett group, 1 = city group

    int rown[4]; int tpoff[4];
    #pragma unroll
    for (int s = 0; s < 4; s++) {
        rown[s] = mrow + 16 * (s >> 1) + 8 * (s & 1) + g;
        tpoff[s] = (rown[s] >= 54) ? 128 : 0;
    }

    const uint32_t wx4base0 = sbase + SM_WH +
        (uint32_t)((lane & 7) * 112 + (lane >> 3) * 16);
    const uint32_t wx2base0 = sbase + SM_WH +
        (uint32_t)((lane & 7) * 112 + ((lane >> 3) & 1) * 16 + 64);
    // A-frag ldmatrix base: lane -> row (mrow + lane&15), 16B half (lane>>4)
    const uint32_t abase0 = sbase + SM_AH +
        (uint32_t)((mrow + (lane & 15)) * 112 + (lane >> 4) * 16);

    const long npairs = ((long)B + 1) / 2;
    const size_t totp4 = (size_t)B * 32;
    const float4* tp4 = (const float4*)d_tproj;

    // ---- prologue: LN-A + tproj prefetch for first pair into buf 0 ----
    long pair = blockIdx.x;
    int buf = 0;
    if (pair < npairs) {
        const int nr = (int)((long)B * 54 - pair * 108 >= 108 ? 108 : (long)B * 54 - pair * 108);
        if (tid < nr) {
            const float4* xr = (const float4*)(node_emb + ((size_t)pair * 108 + tid) * 48);
            float s = 0.f, q = 0.f;
            #pragma unroll
            for (int j = 0; j < 12; j++) {
                float4 v = xr[j];
                s += v.x + v.y + v.z + v.w;
                q += v.x * v.x + v.y * v.y + v.z * v.z + v.w * v.w;
            }
            float mu = s * (1.f / 48.f);
            ((float*)(smem + SM_MU))[tid] = mu;
            ((float*)(smem + SM_IS))[tid] = rsqrtf(q * (1.f / 48.f) - mu * mu + 1e-5f);
        }
        if (tid < 64) {
            size_t t4 = (size_t)pair * 64 + tid;
            if (t4 < totp4) cp16(sbase + SM_TPROJ + tid * 16, tp4 + t4);
        }
        CP_COMMIT();
    }

    for (; pair < npairs; pair += gridDim.x, buf ^= 1) {
        const float* mu_s = (const float*)(smem + SM_MU + buf * 448);
        const float* is_s = (const float*)(smem + SM_IS + buf * 448);
        const float* tpb  = (const float*)(smem + SM_TPROJ + buf * 1024);

        CP_WAIT_ALL();          // tproj(buf) landed
        __syncthreads();        // LN-A(buf) writes visible; prev heads done with P_s

        const int nrows = (int)((long)B * 54 - pair * 108 >= 108 ? 108 : (long)B * 54 - pair * 108);

        // ---- LN phase B: float4 loads, uint2 stores into AH/AL ----
        for (int i = tid; i < 1296; i += 256) {
            int r = i / 12, c4 = (i % 12) * 4;
            if (r < nrows) {
                float4 v = *(const float4*)(node_emb + ((size_t)pair * 108 + r) * 48 + c4);
                float mu = mu_s[r], is = is_s[r];
                float a0 = (v.x - mu) * is * lnw[c4]     + lnb[c4];
                float a1 = (v.y - mu) * is * lnw[c4 + 1] + lnb[c4 + 1];
                float a2 = (v.z - mu) * is * lnw[c4 + 2] + lnb[c4 + 2];
                float a3 = (v.w - mu) * is * lnw[c4 + 3] + lnb[c4 + 3];
                __half2 h01 = __floats2half2_rn(a0, a1), h23 = __floats2half2_rn(a2, a3);
                __half2 l01 = __floats2half2_rn(a0 - __low2float(h01), a1 - __high2float(h01));
                __half2 l23 = __floats2half2_rn(a2 - __low2float(h23), a3 - __high2float(h23));
                uint2 uh; uh.x = *(uint32_t*)&h01; uh.y = *(uint32_t*)&h23;
                uint2 ul; ul.x = *(uint32_t*)&l01; ul.y = *(uint32_t*)&l23;
                *(uint2*)(smem + SM_AH + (r * 56 + c4) * 2) = uh;
                *(uint2*)(smem + SM_AL + (r * 56 + c4) * 2) = ul;
            }
        }
        __syncthreads();

        // ---- A fragments via ldmatrix (volatile: A changes per iteration) ----
        uint32_t afh[2][3][4], afl[2][3][4];
        #pragma unroll
        for (int t = 0; t < 2; t++) {
            #pragma unroll
            for (int ks = 0; ks < 3; ks++) {
                uint32_t ad = abase0 + (uint32_t)(t * 1792 + ks * 32);
                LDSM_X4(afh[t][ks][0], afh[t][ks][1], afh[t][ks][2], afh[t][ks][3], ad);
                LDSM_X4(afl[t][ks][0], afl[t][ks][1], afl[t][ks][2], afl[t][ks][3],
                        ad + (SM_AL - SM_AH));
            }
        }

        // ---- prefetch next pair: LN-A + tproj into buf^1 (hides under MMA) ----
        {
            long nxt = pair + gridDim.x;
            if (nxt < npairs) {
                const int nr = (int)((long)B * 54 - nxt * 108 >= 108 ? 108 : (long)B * 54 - nxt * 108);
                if (tid < nr) {
                    const float4* xr = (const float4*)(node_emb + ((size_t)nxt * 108 + tid) * 48);
                    float s = 0.f, q = 0.f;
                    #pragma unroll
                    for (int j = 0; j < 12; j++) {
                        float4 v = xr[j];
                        s += v.x + v.y + v.z + v.w;
                        q += v.x * v.x + v.y * v.y + v.z * v.z + v.w * v.w;
                    }
                    float mu = s * (1.f / 48.f);
                    ((float*)(smem + SM_MU + (buf ^ 1) * 448))[tid] = mu;
                    ((float*)(smem + SM_IS + (buf ^ 1) * 448))[tid] =
                        rsqrtf(q * (1.f / 48.f) - mu * mu + 1e-5f);
                }
                if (tid < 64) {
                    size_t t4 = (size_t)nxt * 64 + tid;
                    if (t4 < totp4)
                        cp16(sbase + SM_TPROJ + (buf ^ 1) * 1024 + tid * 16, tp4 + t4);
                }
                CP_COMMIT();
            }
        }

        float sacc[4] = {0.f, 0.f, 0.f, 0.f};

        // nt map: hd=0 -> {0,1,2,3, 8..13}; hd=1 -> {4,5,6,7, 14..19}
        #pragma unroll
        for (int ni = 0; ni < 10; ni++) {
            const int nt = (ni < 4) ? (4 * hd + ni) : (8 + 6 * hd + (ni - 4));
            uint32_t bh[4], bh2[2], bl[4], bl2[2];
            LDSM_X4_NV(bh[0], bh[1], bh[2], bh[3], wx4base0 + nt * 896);
            LDSM_X2_NV(bh2[0], bh2[1], wx2base0 + nt * 896);
            LDSM_X4_NV(bl[0], bl[1], bl[2], bl[3], wx4base0 + nt * 896 + WLOFF);
            LDSM_X2_NV(bl2[0], bl2[1], wx2base0 + nt * 896 + WLOFF);

            float acc[2][4] = {{0.f, 0.f, 0.f, 0.f}, {0.f, 0.f, 0.f, 0.f}};
            #pragma unroll
            for (int t = 0; t < 2; t++) {
                mma16816(acc[t], afh[t][0], bh[0], bh[1]);
                mma16816(acc[t], afh[t][1], bh[2], bh[3]);
                mma16816(acc[t], afh[t][2], bh2[0], bh2[1]);
                mma16816(acc[t], afh[t][0], bl[0], bl[1]);
                mma16816(acc[t], afh[t][1], bl[2], bl[3]);
                mma16816(acc[t], afh[t][2], bl2[0], bl2[1]);
                mma16816(acc[t], afl[t][0], bh[0], bh[1]);
                mma16816(acc[t], afl[t][1], bh[2], bh[3]);
                mma16816(acc[t], afl[t][2], bh2[0], bh2[1]);
            }
            const int col = nt * 8 + k0;
            if (ni < 4) {
                float w2a = w2_s[col], w2b = w2_s[col + 1];
                #pragma unroll
                for (int s = 0; s < 4; s++) {
                    float v0 = acc[s >> 1][2 * (s & 1)];
                    float v1 = acc[s >> 1][2 * (s & 1) + 1];
                    sacc[s] += mishf(v0 + tpb[tpoff[s] + col]) * w2a
                             + mishf(v1 + tpb[tpoff[s] + col + 1]) * w2b;
                }
            } else {
                #pragma unroll
                for (int s = 0; s < 4; s++) {
                    int r = rown[s];
                    if (r < 108) {
                        float* pr = P_s + r * 97 + (col - 64);
                        pr[0] = acc[s >> 1][2 * (s & 1)];
                        pr[1] = acc[s >> 1][2 * (s & 1) + 1];
                    }
                }
            }
        }

        // sett/city finalize: every warp reduces its single head
        {
            #pragma unroll
            for (int s = 0; s < 4; s++) {
                sacc[s] += __shfl_xor_sync(0xffffffffu, sacc[s], 1);
                sacc[s] += __shfl_xor_sync(0xffffffffu, sacc[s], 2);
            }
            if ((lane & 3) == 0) {
                #pragma unroll
                for (int s = 0; s < 4; s++) {
                    int r = rown[s];
                    if (r < nrows) {
                        int bl = (r >= 54) ? 1 : 0;
                        int n = r - 54 * bl;
                        out[((size_t)(pair * 2 + bl)) * 397 + 5 + 54 * hd + n] = sacc[s] + b2_s[hd];
                    }
                }
            }
        }
        __syncthreads();

        const int nb = (nrows > 54) ? 2 : 1;
        // ---- road heads: 4 edges per warp-task, 8-lane groups ----
        {
            const int sub = lane >> 3, c = lane & 7;
            for (int t = wid; t < nb * 18; t += 8) {
                int bl = (t >= 18) ? 1 : 0;
                int tg = t - 18 * bl;
                int e = tg * 4 + sub;
                int sN = rp_s[2 * e], dN = rp_s[2 * e + 1];
                const float* tp = tpb + bl * 128 + 64;
                const float* Ps = P_s + (bl * 54 + sN) * 97;
                const float* Pd = P_s + (bl * 54 + dN) * 97 + 32;
                float part = 0.f;
                #pragma unroll
                for (int j = 0; j < 4; j++) {
                    int cj = c + 8 * j;
                    part += mishf(tp[cj] + Ps[cj] + Pd[cj]) * w2_s[64 + cj];
                }
                part += __shfl_xor_sync(0xffffffffu, part, 1);
                part += __shfl_xor_sync(0xffffffffu, part, 2);
                part += __shfl_xor_sync(0xffffffffu, part, 4);
                if (c == 0) out[((size_t)(pair * 2 + bl)) * 397 + 113 + e] = part + b2_s[2];
            }
        }
        // ---- robber heads ----
        for (int t = wid; t < nb * 19; t += 8) {
            int bl = (t >= 19) ? 1 : 0;
            int tt = t - 19 * bl;
            float a = 0.f;
            #pragma unroll
            for (int i = 0; i < 6; i++)
                a += P_s[(bl * 54 + ti_s[tt * 6 + i]) * 97 + 64 + lane];
            float m = mishf(tpb[bl * 128 + 96 + lane] + a * (1.f / 6.f));
            #pragma unroll
            for (int o = 0; o < 5; o++) {
                float red = warp_sum(m * rob2_s[o * 32 + lane]);
                if (lane == 0)
                    out[((size_t)(pair * 2 + bl)) * 397 + 185 + tt * 5 + o] = red + b2_s[3 + o];
            }
        }
        // (no end barrier: next iteration's top barrier protects P_s/tproj)
    }
}

// ------------------------------ K3: BN + mish + gfc2, 8-row batched ------------------------------
__global__ __launch_bounds__(128) void k3(const float* __restrict__ gfc2_w,
                                          const float* __restrict__ gfc2_b,
                                          float* __restrict__ out, int B) {
    __shared__ __align__(16) float m8[80 * 8];
    __shared__ __align__(16) float Wg[80 * 122];
    __shared__ float bs[122];
    __shared__ float sc[80], sh[80];
    int tid = threadIdx.x;
    for (int i = tid; i < 80 * 122; i += 128) {
        int k = i / 122, t = i % 122;
        int r = (t < 5) ? t : (275 + t);
        Wg[i] = gfc2_w[r * 80 + k];
    }
    if (tid < 122) { int r = (tid < 5) ? tid : (275 + tid); bs[tid] = gfc2_b[r]; }
    if (tid < 80) { sc[tid] = d_bnscale[tid]; sh[tid] = d_bnshift[tid]; }
    __syncthreads();
    int nq = (B + 7) >> 3;
    for (int qb = blockIdx.x; qb < nq; qb += gridDim.x) {
        if (tid < 80) {
            #pragma unroll
            for (int rb = 0; rb < 8; rb++) {
                int b = qb * 8 + rb;
                float v = (b < B) ? d_h[(size_t)b * 80 + tid] : 0.f;
                m8[tid * 8 + rb] = mishf(v * sc[tid] + sh[tid]);
            }
        }
        __syncthreads();
        if (tid < 122) {
            float a[8];
            #pragma unroll
            for (int rb = 0; rb < 8; rb++) a[rb] = bs[tid];
            for (int k = 0; k < 80; k++) {
                float4 mA = *(const float4*)(m8 + k * 8);
                float4 mB = *(const float4*)(m8 + k * 8 + 4);
                float w = Wg[k * 122 + tid];
                a[0] += mA.x * w; a[1] += mA.y * w; a[2] += mA.z * w; a[3] += mA.w * w;
                a[4] += mB.x * w; a[5] += mB.y * w; a[6] += mB.z * w; a[7] += mB.w * w;
            }
            int col = (tid < 5) ? tid : (275 + tid);
            #pragma unroll
            for (int rb = 0; rb < 8; rb++) {
                int b = qb * 8 + rb;
                if (b < B) out[(size_t)b * 397 + col] = a[rb];
            }
        }
        __syncthreads();
    }
}

// ------------------------------ launch ------------------------------
extern "C" void kernel_launch(void* const* d_in, const int* in_sizes, int n_in,
                              void* d_out, int out_size) {
    const float* trunk      = (const float*)d_in[0];
    const float* node_emb   = (const float*)d_in[1];
    const int*   road_pairs = (const int*)d_in[2];
    const int*   tile_nodes = (const int*)d_in[3];
    const float* ln_t_w = (const float*)d_in[4];
    const float* ln_t_b = (const float*)d_in[5];
    const float* ln_n_w = (const float*)d_in[6];
    const float* ln_n_b = (const float*)d_in[7];
    const float* gfc1_w = (const float*)d_in[8];
    const float* gfc1_b = (const float*)d_in[9];
    const float* bn_w   = (const float*)d_in[10];
    const float* bn_b   = (const float*)d_in[11];
    const float* gfc2_w = (const float*)d_in[12];
    const float* gfc2_b = (const float*)d_in[13];
    const float* sett1_w = (const float*)d_in[14];
    const float* sett1_b = (const float*)d_in[15];
    const float* sett2_w = (const float*)d_in[16];
    const float* sett2_b = (const float*)d_in[17];
    const float* city1_w = (const float*)d_in[18];
    const float* city1_b = (const float*)d_in[19];
    const float* city2_w = (const float*)d_in[20];
    const float* city2_b = (const float*)d_in[21];
    const float* road1_w = (const float*)d_in[22];
    const float* road1_b = (const float*)d_in[23];
    const float* road2_w = (const float*)d_in[24];
    const float* road2_b = (const float*)d_in[25];
    const float* rob1_w = (const float*)d_in[26];
    const float* rob1_b = (const float*)d_in[27];
    const float* rob2_w = (const float*)d_in[28];
    const float* rob2_b = (const float*)d_in[29];

    int B = in_sizes[0] / 80;
    if (B > BMAX) B = BMAX;
    float* out = (float*)d_out;
    int nblk1 = (B + 127) / 128;

    cudaFuncSetAttribute(k1, cudaFuncAttributeMaxDynamicSharedMemorySize, K1_SMEM);
    cudaFuncSetAttribute(k2, cudaFuncAttributeMaxDynamicSharedMemorySize, SM_TOTAL);

    k_prep<<<(208 * 80 + 255) / 256, 256>>>(sett1_w, city1_w, road1_w, rob1_w, gfc1_w,
                                            sett1_b, city1_b, road1_b, rob1_b, gfc1_b);
    k1<<<nblk1, 512, K1_SMEM>>>(trunk, ln_t_w, ln_t_b, B);
    k_bn<<<1, 80>>>(bn_w, bn_b, B, nblk1);
    k2<<<K2_GRID, 256, SM_TOTAL>>>(node_emb, ln_n_w, ln_n_b, road_pairs, tile_nodes,
                                   sett2_w, sett2_b, city2_w, city2_b,
                                   road2_w, road2_b, rob2_w, rob2_b, out, B);
    k3<<<K3_GRID, 128>>>(gfc2_w, gfc2_b, out, B);
}

// round 12
// speedup vs baseline: 1.1066x; 1.0376x over previous
#include <cuda_runtime.h>
#include <cuda_fp16.h>
#include <cstdint>
#include <cstddef>

// ---------------------------------------------------------------------------
// SmallSpatialPolicyHead — R11 + k2: float4 road heads (P stride 100),
// paired-X2->X4 W fragment loads. Targets the 68%-utilized L1/LSU pipe.
// ---------------------------------------------------------------------------

#define BMAX 16384
#define K2_GRID 296
#define K3_GRID 592

__device__ float d_tb[208];
__device__ __half d_Wh[160 * 48];    // k2 node proj hi  [n][k]
__device__ __half d_Wl[160 * 48];    // k2 node proj lo
__device__ __half d_Wth[208 * 80];   // k1 trunk proj hi [o][k]
__device__ __half d_Wtl[208 * 80];   // k1 trunk proj lo
__device__ float d_tproj[(size_t)BMAX * 128];
__device__ float d_h[(size_t)BMAX * 80];
__device__ float d_partial[296 * 160];
__device__ float d_bnscale[80];
__device__ float d_bnshift[80];

// ---- k2 smem byte offsets ----
#define SM_XP    0             // P_s 108x100 f = 43200
#define SM_AH    43200         // 128x56 fp16 = 14336
#define SM_AL    57536
#define SM_WH    71872         // 160x56 fp16 = 17920
#define SM_WL    89792
#define WLOFF    17920
#define SM_TPROJ 107712        // 2 x 256 f (double buffer)
#define SM_W2    109760        // 96 f
#define SM_ROB2  110144        // 160 f
#define SM_B2    110784        // 8 f
#define SM_LNW   110816        // 48 f
#define SM_LNB   111008        // 48 f
#define SM_MU    111200        // 2 x 110 f (double buffer, 448B each)
#define SM_IS    112096        // 2 x 110 f
#define SM_RP    112992        // 144 i
#define SM_TI    113568        // 114 i
#define SM_TOTAL 114024

// ---- k1 smem byte offsets ----
#define X1_XS    0             // 128x84 f = 43008 (reused as hs)
#define X1_AH    43008         // 128x88 fp16 = 22528
#define X1_AL    65536
#define X1_WH    88064         // 208x88 fp16 = 36608
#define X1_WL    124672
#define W1OFF    36608
#define X1_TB    161280        // 208 f
#define X1_LNW   162112        // 80 f
#define X1_LNB   162432        // 80 f
#define K1_SMEM  162752

__device__ __forceinline__ uint32_t smem_u32(const void* p) {
    uint32_t a;
    asm("{ .reg .u64 t; cvta.to.shared.u64 t, %1; cvt.u32.u64 %0, t; }" : "=r"(a) : "l"(p));
    return a;
}
__device__ __forceinline__ void cp16(uint32_t dst, const void* src) {
    asm volatile("cp.async.cg.shared.global [%0], [%1], 16;" :: "r"(dst), "l"(src));
}
#define CP_COMMIT() asm volatile("cp.async.commit_group;" ::: "memory")
#define CP_WAIT_ALL() asm volatile("cp.async.wait_group 0;" ::: "memory")
#define CP_COMMIT_WAIT() do { CP_COMMIT(); CP_WAIT_ALL(); } while (0)

#define LDSM_X4(r0,r1,r2,r3,addr) \
    asm volatile("ldmatrix.sync.aligned.m8n8.x4.shared.b16 {%0,%1,%2,%3}, [%4];" \
        : "=r"(r0),"=r"(r1),"=r"(r2),"=r"(r3) : "r"(addr))
#define LDSM_X2(r0,r1,addr) \
    asm volatile("ldmatrix.sync.aligned.m8n8.x2.shared.b16 {%0,%1}, [%2];" \
        : "=r"(r0),"=r"(r1) : "r"(addr))
#define LDSM_X4_NV(r0,r1,r2,r3,addr) \
    asm("ldmatrix.sync.aligned.m8n8.x4.shared.b16 {%0,%1,%2,%3}, [%4];" \
        : "=r"(r0),"=r"(r1),"=r"(r2),"=r"(r3) : "r"(addr))

__device__ __forceinline__ void mma16816(float* d, const uint32_t* a, uint32_t b0, uint32_t b1) {
    asm volatile(
        "mma.sync.aligned.m16n8k16.row.col.f32.f16.f16.f32 "
        "{%0,%1,%2,%3},{%4,%5,%6,%7},{%8,%9},{%0,%1,%2,%3};"
        : "+f"(d[0]), "+f"(d[1]), "+f"(d[2]), "+f"(d[3])
        : "r"(a[0]), "r"(a[1]), "r"(a[2]), "r"(a[3]), "r"(b0), "r"(b1));
}

__device__ __forceinline__ float mishf(float x) {
    float u = __expf(fminf(x, 15.f));
    float d = __fmaf_rn(u, u + 2.f, 2.f);
    return x - __fdividef(2.f * x, d);
}
__device__ __forceinline__ float warp_sum(float v) {
    #pragma unroll
    for (int o = 16; o; o >>= 1) v += __shfl_xor_sync(0xffffffffu, v, o);
    return v;
}

// ------------------------------ prep ------------------------------
__global__ void k_prep(const float* __restrict__ sett1_w, const float* __restrict__ city1_w,
                       const float* __restrict__ road1_w, const float* __restrict__ rob1_w,
                       const float* __restrict__ gfc1_w,
                       const float* __restrict__ sett1_b, const float* __restrict__ city1_b,
                       const float* __restrict__ road1_b, const float* __restrict__ rob1_b,
                       const float* __restrict__ gfc1_b) {
    int i = blockIdx.x * blockDim.x + threadIdx.x;
    if (i < 160 * 48) {
        int j = i / 48, k = i % 48;
        float v;
        if (j < 32)       v = sett1_w[j * 128 + 80 + k];
        else if (j < 64)  v = city1_w[(j - 32) * 128 + 80 + k];
        else if (j < 96)  v = road1_w[(j - 64) * 176 + 80 + k];
        else if (j < 128) v = road1_w[(j - 96) * 176 + 128 + k];
        else              v = rob1_w[(j - 128) * 128 + 80 + k];
        __half h = __float2half(v);
        d_Wh[i] = h;
        d_Wl[i] = __float2half(v - __half2float(h));
    }
    if (i < 208 * 80) {
        int o = i / 80, k = i % 80;
        float v;
        if (o < 32)       v = sett1_w[o * 128 + k];
        else if (o < 64)  v = city1_w[(o - 32) * 128 + k];
        else if (o < 96)  v = road1_w[(o - 64) * 176 + k];
        else if (o < 128) v = rob1_w[(o - 96) * 128 + k];
        else              v = gfc1_w[(o - 128) * 80 + k];
        __half h = __float2half(v);
        d_Wth[i] = h;
        d_Wtl[i] = __float2half(v - __half2float(h));
    }
    if (i < 208) {
        float v;
        if (i < 32)       v = sett1_b[i];
        else if (i < 64)  v = city1_b[i - 32];
        else if (i < 96)  v = road1_b[i - 64];
        else if (i < 128) v = rob1_b[i - 96];
        else              v = gfc1_b[i - 128];
        d_tb[i] = v;
    }
}

// ------------------------------ K1: HMMA trunk kernel (unchanged, proven) ------------------------------
__global__ __launch_bounds__(512, 1) void k1(const float* __restrict__ trunk,
                                             const float* __restrict__ ln_t_w,
                                             const float* __restrict__ ln_t_b, int B) {
    extern __shared__ char smem[];
    const uint32_t sbase = smem_u32(smem);
    const int tid = threadIdx.x, wid = tid >> 5, lane = tid & 31;

    float* xs  = (float*)(smem + X1_XS);
    float* hs  = (float*)(smem + X1_XS);
    float* tb_s = (float*)(smem + X1_TB);
    float* lnw = (float*)(smem + X1_LNW);
    float* lnb = (float*)(smem + X1_LNB);

    for (int i = tid; i < 208 * 80; i += 512) {
        int o = i / 80, k = i % 80;
        *(__half*)(smem + X1_WH + (o * 88 + k) * 2) = d_Wth[i];
        *(__half*)(smem + X1_WL + (o * 88 + k) * 2) = d_Wtl[i];
    }
    for (int i = tid; i < 208; i += 512) tb_s[i] = d_tb[i];
    if (tid < 80) { lnw[tid] = ln_t_w[tid]; lnb[tid] = ln_t_b[tid]; }

    const int rows_valid = min(128, B - (int)blockIdx.x * 128);

    {
        const float4* tr4 = (const float4*)trunk;
        size_t base4 = (size_t)blockIdx.x * 2560;
        #pragma unroll
        for (int q = 0; q < 5; q++) {
            int il = tid + q * 512;
            int row = il / 20, c = il % 20;
            if (row < rows_valid)
                cp16(sbase + X1_XS + (uint32_t)((row * 84 + 4 * c) * 4), tr4 + base4 + il);
        }
        CP_COMMIT_WAIT();
    }
    __syncthreads();

    if (tid < 256) {
        const int r = tid >> 1, h = tid & 1;
        float4 v[10];
        if (r < rows_valid) {
            const float4* xr = (const float4*)(xs + r * 84 + h * 40);
            #pragma unroll
            for (int j = 0; j < 10; j++) v[j] = xr[j];
        } else {
            #pragma unroll
            for (int j = 0; j < 10; j++) v[j] = make_float4(0.f, 0.f, 0.f, 0.f);
        }
        float s = 0.f, q = 0.f;
        #pragma unroll
        for (int j = 0; j < 10; j++) {
            s += v[j].x + v[j].y + v[j].z + v[j].w;
            q += v[j].x * v[j].x + v[j].y * v[j].y + v[j].z * v[j].z + v[j].w * v[j].w;
        }
        s += __shfl_xor_sync(0xffffffffu, s, 1);
        q += __shfl_xor_sync(0xffffffffu, q, 1);
        float mu = s * (1.f / 80.f);
        float is = rsqrtf(q * (1.f / 80.f) - mu * mu + 1e-5f);
        char* dh = smem + X1_AH + (r * 88 + h * 40) * 2;
        char* dl = dh + (X1_AL - X1_AH);
        const float4* lw4 = (const float4*)(lnw + h * 40);
        const float4* lb4 = (const float4*)(lnb + h * 40);
        #pragma unroll
        for (int j = 0; j < 10; j++) {
            float4 w = lw4[j], b = lb4[j];
            float a0 = (v[j].x - mu) * is * w.x + b.x;
            float a1 = (v[j].y - mu) * is * w.y + b.y;
            float a2 = (v[j].z - mu) * is * w.z + b.z;
            float a3 = (v[j].w - mu) * is * w.w + b.w;
            if (r >= rows_valid) { a0 = a1 = a2 = a3 = 0.f; }
            __half2 h01 = __floats2half2_rn(a0, a1), h23 = __floats2half2_rn(a2, a3);
            __half2 l01 = __floats2half2_rn(a0 - __low2float(h01), a1 - __high2float(h01));
            __half2 l23 = __floats2half2_rn(a2 - __low2float(h23), a3 - __high2float(h23));
            uint2 uh; uh.x = *(uint32_t*)&h01; uh.y = *(uint32_t*)&h23;
            uint2 ul; ul.x = *(uint32_t*)&l01; ul.y = *(uint32_t*)&l23;
            *(uint2*)(dh + j * 8) = uh;
            *(uint2*)(dl + j * 8) = ul;
        }
    }
    __syncthreads();

    {
        const int mt = wid & 7, nh = wid >> 3;
        const int g = lane >> 2, k0 = (lane & 3) * 2;
        const uint32_t abase = sbase + X1_AH +
            (uint32_t)((mt * 16 + (lane & 15)) * 176 + (lane >> 4) * 16);
        uint32_t ah[5][4];
        #pragma unroll
        for (int ks = 0; ks < 5; ks++)
            LDSM_X4(ah[ks][0], ah[ks][1], ah[ks][2], ah[ks][3], abase + ks * 32);

        uint32_t wx4 = sbase + X1_WH +
            (uint32_t)((lane & 7) * 176 + (lane >> 3) * 16) + (uint32_t)(nh * 13 * 1408);
        uint32_t wx2 = sbase + X1_WH +
            (uint32_t)((lane & 7) * 176 + ((lane >> 3) & 1) * 16 + 128) + (uint32_t)(nh * 13 * 1408);

        #pragma unroll
        for (int ni = 0; ni < 13; ni++) {
            const int nt = nh * 13 + ni;
            uint32_t bhA[4], bhB[4], bh2[2], blA[4], blB[4], bl2[2];
            LDSM_X4(bhA[0], bhA[1], bhA[2], bhA[3], wx4);
            LDSM_X4(bhB[0], bhB[1], bhB[2], bhB[3], wx4 + 64);
            LDSM_X2(bh2[0], bh2[1], wx2);
            LDSM_X4(blA[0], blA[1], blA[2], blA[3], wx4 + W1OFF);
            LDSM_X4(blB[0], blB[1], blB[2], blB[3], wx4 + 64 + W1OFF);
            LDSM_X2(bl2[0], bl2[1], wx2 + W1OFF);

            float acc[4] = {0.f, 0.f, 0.f, 0.f};
            mma16816(acc, ah[0], bhA[0], bhA[1]);
            mma16816(acc, ah[1], bhA[2], bhA[3]);
            mma16816(acc, ah[2], bhB[0], bhB[1]);
            mma16816(acc, ah[3], bhB[2], bhB[3]);
            mma16816(acc, ah[4], bh2[0], bh2[1]);
            mma16816(acc, ah[0], blA[0], blA[1]);
            mma16816(acc, ah[1], blA[2], blA[3]);
            mma16816(acc, ah[2], blB[0], blB[1]);
            mma16816(acc, ah[3], blB[2], blB[3]);
            mma16816(acc, ah[4], bl2[0], bl2[1]);
            {
                uint32_t al[4];
                const uint32_t albase = abase + (X1_AL - X1_AH);
                LDSM_X4(al[0], al[1], al[2], al[3], albase);
                mma16816(acc, al, bhA[0], bhA[1]);
                LDSM_X4(al[0], al[1], al[2], al[3], albase + 32);
                mma16816(acc, al, bhA[2], bhA[3]);
                LDSM_X4(al[0], al[1], al[2], al[3], albase + 64);
                mma16816(acc, al, bhB[0], bhB[1]);
                LDSM_X4(al[0], al[1], al[2], al[3], albase + 96);
                mma16816(acc, al, bhB[2], bhB[3]);
                LDSM_X4(al[0], al[1], al[2], al[3], albase + 128);
                mma16816(acc, al, bh2[0], bh2[1]);
            }
            wx4 += 1408; wx2 += 1408;

            const int col = nt * 8 + k0;
            const int row0 = mt * 16 + g, row1 = row0 + 8;
            if (col < 128) {
                float b0 = tb_s[col], b1 = tb_s[col + 1];
                if (row0 < rows_valid) {
                    size_t o = (size_t)((size_t)blockIdx.x * 128 + row0) * 128 + col;
                    d_tproj[o] = acc[0] + b0; d_tproj[o + 1] = acc[1] + b1;
                }
                if (row1 < rows_valid) {
                    size_t o = (size_t)((size_t)blockIdx.x * 128 + row1) * 128 + col;
                    d_tproj[o] = acc[2] + b0; d_tproj[o + 1] = acc[3] + b1;
                }
            } else {
                const int ch = col - 128;
                hs[row0 * 84 + ch] = acc[0]; hs[row0 * 84 + ch + 1] = acc[1];
                hs[row1 * 84 + ch] = acc[2]; hs[row1 * 84 + ch + 1] = acc[3];
                if (row0 < rows_valid) {
                    size_t o = (size_t)((size_t)blockIdx.x * 128 + row0) * 80 + ch;
                    d_h[o] = acc[0]; d_h[o + 1] = acc[1];
                }
                if (row1 < rows_valid) {
                    size_t o = (size_t)((size_t)blockIdx.x * 128 + row1) * 80 + ch;
                    d_h[o] = acc[2]; d_h[o + 1] = acc[3];
                }
            }
        }
    }
    __syncthreads();

    if (tid < 80) {
        float s1 = 0.f, s2 = 0.f;
        for (int r = 0; r < rows_valid; r++) {
            float v = hs[r * 84 + tid];
            s1 += v; s2 += v * v;
        }
        d_partial[blockIdx.x * 160 + tid] = s1;
        d_partial[blockIdx.x * 160 + 80 + tid] = s2;
    }
}

// ------------------------------ BN finalize ------------------------------
__global__ void k_bn(const float* __restrict__ bn_w, const float* __restrict__ bn_b,
                     int B, int nblk) {
    int t = threadIdx.x;
    if (t >= 80) return;
    float S1 = 0.f, S2 = 0.f;
    for (int blk = 0; blk < nblk; blk++) {
        S1 += d_partial[blk * 160 + t];
        S2 += d_partial[blk * 160 + 80 + t];
    }
    float invB = 1.f / (float)B;
    float mu = S1 * invB;
    float var = S2 * invB - mu * mu;
    float sc = bn_w[t] * rsqrtf(var + 1e-5f);
    d_bnscale[t] = sc;
    d_bnshift[t] = bn_b[t] - mu * sc;
}

// ------------------------------ K2: HMMA fused node kernel, pipelined ------------------------------
__global__ __launch_bounds__(256, 2) void k2(const float* __restrict__ node_emb,
                                             const float* __restrict__ ln_n_w,
                                             const float* __restrict__ ln_n_b,
                                             const int* __restrict__ road_pairs,
                                             const int* __restrict__ tile_nodes,
                                             const float* __restrict__ sett2_w, const float* __restrict__ sett2_b,
                                             const float* __restrict__ city2_w, const float* __restrict__ city2_b,
                                             const float* __restrict__ road2_w, const float* __restrict__ road2_b,
                                             const float* __restrict__ rob2_w, const float* __restrict__ rob2_b,
                                             float* __restrict__ out, int B) {
    extern __shared__ char smem[];
    const uint32_t sbase = smem_u32(smem);
    const int tid = threadIdx.x, wid = tid >> 5, lane = tid & 31;

    float* P_s     = (float*)(smem + SM_XP);   // rows x 100
    float* w2_s    = (float*)(smem + SM_W2);
    float* rob2_s  = (float*)(smem + SM_ROB2);
    float* b2_s    = (float*)(smem + SM_B2);
    float* lnw     = (float*)(smem + SM_LNW);
    float* lnb     = (float*)(smem + SM_LNB);
    int*   rp_s    = (int*)(smem + SM_RP);
    int*   ti_s    = (int*)(smem + SM_TI);

    for (int i = tid; i < 160 * 48; i += 256) {
        int n = i / 48, k = i % 48;
        *(__half*)(smem + SM_WH + (n * 56 + k) * 2) = d_Wh[i];
        *(__half*)(smem + SM_WL + (n * 56 + k) * 2) = d_Wl[i];
    }
    if (tid < 48) { lnw[tid] = ln_n_w[tid]; lnb[tid] = ln_n_b[tid]; }
    if (tid < 32) { w2_s[tid] = sett2_w[tid]; w2_s[32 + tid] = city2_w[tid]; w2_s[64 + tid] = road2_w[tid]; }
    if (tid < 160) rob2_s[tid] = rob2_w[tid];
    if (tid == 0) { b2_s[0] = sett2_b[0]; b2_s[1] = city2_b[0]; b2_s[2] = road2_b[0]; }
    if (tid < 5) b2_s[3 + tid] = rob2_b[tid];
    if (tid < 144) rp_s[tid] = road_pairs[tid];
    if (tid < 114) ti_s[tid] = tile_nodes[tid];

    const int g = lane >> 2;
    const int k0 = (lane & 3) * 2;
    const int mrow = (wid & 3) * 32;
    const int hd = wid >> 2;              // 0 = sett group, 1 = city group

    int rown[4]; int tpoff[4];
    #pragma unroll
    for (int s = 0; s < 4; s++) {
        rown[s] = mrow + 16 * (s >> 1) + 8 * (s & 1) + g;
        tpoff[s] = (rown[s] >= 54) ? 128 : 0;
    }

    const uint32_t wx4base0 = sbase + SM_WH +
        (uint32_t)((lane & 7) * 112 + (lane >> 3) * 16);
    // paired X2->X4 base: lanes 0-15 serve nt, lanes 16-31 serve nt+1
    const uint32_t wpbase0 = sbase + SM_WH +
        (uint32_t)((lane & 7) * 112 + ((lane >> 3) & 1) * 16 + 64 + ((lane >> 4) & 1) * 896);
    const uint32_t abase0 = sbase + SM_AH +
        (uint32_t)((mrow + (lane & 15)) * 112 + (lane >> 4) * 16);

    const long npairs = ((long)B + 1) / 2;
    const size_t totp4 = (size_t)B * 32;
    const float4* tp4 = (const float4*)d_tproj;

    // ---- prologue: LN-A + tproj prefetch for first pair into buf 0 ----
    long pair = blockIdx.x;
    int buf = 0;
    if (pair < npairs) {
        const int nr = (int)((long)B * 54 - pair * 108 >= 108 ? 108 : (long)B * 54 - pair * 108);
        if (tid < nr) {
            const float4* xr = (const float4*)(node_emb + ((size_t)pair * 108 + tid) * 48);
            float s = 0.f, q = 0.f;
            #pragma unroll
            for (int j = 0; j < 12; j++) {
                float4 v = xr[j];
                s += v.x + v.y + v.z + v.w;
                q += v.x * v.x + v.y * v.y + v.z * v.z + v.w * v.w;
            }
            float mu = s * (1.f / 48.f);
            ((float*)(smem + SM_MU))[tid] = mu;
            ((float*)(smem + SM_IS))[tid] = rsqrtf(q * (1.f / 48.f) - mu * mu + 1e-5f);
        }
        if (tid < 64) {
            size_t t4 = (size_t)pair * 64 + tid;
            if (t4 < totp4) cp16(sbase + SM_TPROJ + tid * 16, tp4 + t4);
        }
        CP_COMMIT();
    }

    for (; pair < npairs; pair += gridDim.x, buf ^= 1) {
        const float* mu_s = (const float*)(smem + SM_MU + buf * 448);
        const float* is_s = (const float*)(smem + SM_IS + buf * 448);
        const float* tpb  = (const float*)(smem + SM_TPROJ + buf * 1024);

        CP_WAIT_ALL();
        __syncthreads();

        const int nrows = (int)((long)B * 54 - pair * 108 >= 108 ? 108 : (long)B * 54 - pair * 108);

        // ---- LN phase B: float4 loads, uint2 stores into AH/AL ----
        for (int i = tid; i < 1296; i += 256) {
            int r = i / 12, c4 = (i % 12) * 4;
            if (r < nrows) {
                float4 v = *(const float4*)(node_emb + ((size_t)pair * 108 + r) * 48 + c4);
                float mu = mu_s[r], is = is_s[r];
                float a0 = (v.x - mu) * is * lnw[c4]     + lnb[c4];
                float a1 = (v.y - mu) * is * lnw[c4 + 1] + lnb[c4 + 1];
                float a2 = (v.z - mu) * is * lnw[c4 + 2] + lnb[c4 + 2];
                float a3 = (v.w - mu) * is * lnw[c4 + 3] + lnb[c4 + 3];
                __half2 h01 = __floats2half2_rn(a0, a1), h23 = __floats2half2_rn(a2, a3);
                __half2 l01 = __floats2half2_rn(a0 - __low2float(h01), a1 - __high2float(h01));
                __half2 l23 = __floats2half2_rn(a2 - __low2float(h23), a3 - __high2float(h23));
                uint2 uh; uh.x = *(uint32_t*)&h01; uh.y = *(uint32_t*)&h23;
                uint2 ul; ul.x = *(uint32_t*)&l01; ul.y = *(uint32_t*)&l23;
                *(uint2*)(smem + SM_AH + (r * 56 + c4) * 2) = uh;
                *(uint2*)(smem + SM_AL + (r * 56 + c4) * 2) = ul;
            }
        }
        __syncthreads();

        // ---- A fragments via ldmatrix (volatile: A changes per iteration) ----
        uint32_t afh[2][3][4], afl[2][3][4];
        #pragma unroll
        for (int t = 0; t < 2; t++) {
            #pragma unroll
            for (int ks = 0; ks < 3; ks++) {
                uint32_t ad = abase0 + (uint32_t)(t * 1792 + ks * 32);
                LDSM_X4(afh[t][ks][0], afh[t][ks][1], afh[t][ks][2], afh[t][ks][3], ad);
                LDSM_X4(afl[t][ks][0], afl[t][ks][1], afl[t][ks][2], afl[t][ks][3],
                        ad + (SM_AL - SM_AH));
            }
        }

        // ---- prefetch next pair: LN-A + tproj into buf^1 (hides under MMA) ----
        {
            long nxt = pair + gridDim.x;
            if (nxt < npairs) {
                const int nr = (int)((long)B * 54 - nxt * 108 >= 108 ? 108 : (long)B * 54 - nxt * 108);
                if (tid < nr) {
                    const float4* xr = (const float4*)(node_emb + ((size_t)nxt * 108 + tid) * 48);
                    float s = 0.f, q = 0.f;
                    #pragma unroll
                    for (int j = 0; j < 12; j++) {
                        float4 v = xr[j];
                        s += v.x + v.y + v.z + v.w;
                        q += v.x * v.x + v.y * v.y + v.z * v.z + v.w * v.w;
                    }
                    float mu = s * (1.f / 48.f);
                    ((float*)(smem + SM_MU + (buf ^ 1) * 448))[tid] = mu;
                    ((float*)(smem + SM_IS + (buf ^ 1) * 448))[tid] =
                        rsqrtf(q * (1.f / 48.f) - mu * mu + 1e-5f);
                }
                if (tid < 64) {
                    size_t t4 = (size_t)nxt * 64 + tid;
                    if (t4 < totp4)
                        cp16(sbase + SM_TPROJ + (buf ^ 1) * 1024 + tid * 16, tp4 + t4);
                }
                CP_COMMIT();
            }
        }

        float sacc[4] = {0.f, 0.f, 0.f, 0.f};

        // nt pairs: hd=0 -> (0,1),(2,3),(8,9),(10,11),(12,13);
        //           hd=1 -> (4,5),(6,7),(14,15),(16,17),(18,19)
        #pragma unroll
        for (int pi = 0; pi < 5; pi++) {
            const int ntA = (pi < 2) ? (4 * hd + 2 * pi) : (8 + 6 * hd + 2 * (pi - 2));
            // combined X2->X4: frags {r0,r1} for ntA, {r2,r3} for ntA+1
            uint32_t c2h[4], c2l[4];
            LDSM_X4_NV(c2h[0], c2h[1], c2h[2], c2h[3], wpbase0 + ntA * 896);
            LDSM_X4_NV(c2l[0], c2l[1], c2l[2], c2l[3], wpbase0 + ntA * 896 + WLOFF);

            #pragma unroll
            for (int sub = 0; sub < 2; sub++) {
                const int nt = ntA + sub;
                uint32_t bh[4], bl[4];
                LDSM_X4_NV(bh[0], bh[1], bh[2], bh[3], wx4base0 + nt * 896);
                LDSM_X4_NV(bl[0], bl[1], bl[2], bl[3], wx4base0 + nt * 896 + WLOFF);
                const uint32_t bh2a = c2h[2 * sub], bh2b = c2h[2 * sub + 1];
                const uint32_t bl2a = c2l[2 * sub], bl2b = c2l[2 * sub + 1];

                float acc[2][4] = {{0.f, 0.f, 0.f, 0.f}, {0.f, 0.f, 0.f, 0.f}};
                #pragma unroll
                for (int t = 0; t < 2; t++) {
                    mma16816(acc[t], afh[t][0], bh[0], bh[1]);
                    mma16816(acc[t], afh[t][1], bh[2], bh[3]);
                    mma16816(acc[t], afh[t][2], bh2a, bh2b);
                    mma16816(acc[t], afh[t][0], bl[0], bl[1]);
                    mma16816(acc[t], afh[t][1], bl[2], bl[3]);
                    mma16816(acc[t], afh[t][2], bl2a, bl2b);
                    mma16816(acc[t], afl[t][0], bh[0], bh[1]);
                    mma16816(acc[t], afl[t][1], bh[2], bh[3]);
                    mma16816(acc[t], afl[t][2], bh2a, bh2b);
                }
                const int col = nt * 8 + k0;
                if (pi < 2) {
                    float w2a = w2_s[col], w2b = w2_s[col + 1];
                    #pragma unroll
                    for (int s = 0; s < 4; s++) {
                        float v0 = acc[s >> 1][2 * (s & 1)];
                        float v1 = acc[s >> 1][2 * (s & 1) + 1];
                        sacc[s] += mishf(v0 + tpb[tpoff[s] + col]) * w2a
                                 + mishf(v1 + tpb[tpoff[s] + col + 1]) * w2b;
                    }
                } else {
                    #pragma unroll
                    for (int s = 0; s < 4; s++) {
                        int r = rown[s];
                        if (r < 108)
                            *(float2*)(P_s + r * 100 + (col - 64)) =
                                make_float2(acc[s >> 1][2 * (s & 1)], acc[s >> 1][2 * (s & 1) + 1]);
                    }
                }
            }
        }

        // sett/city finalize: every warp reduces its single head
        {
            #pragma unroll
            for (int s = 0; s < 4; s++) {
                sacc[s] += __shfl_xor_sync(0xffffffffu, sacc[s], 1);
                sacc[s] += __shfl_xor_sync(0xffffffffu, sacc[s], 2);
            }
            if ((lane & 3) == 0) {
                #pragma unroll
                for (int s = 0; s < 4; s++) {
                    int r = rown[s];
                    if (r < nrows) {
                        int bl = (r >= 54) ? 1 : 0;
                        int n = r - 54 * bl;
                        out[((size_t)(pair * 2 + bl)) * 397 + 5 + 54 * hd + n] = sacc[s] + b2_s[hd];
                    }
                }
            }
        }
        __syncthreads();

        const int nb = (nrows > 54) ? 2 : 1;
        // ---- road heads: 4 edges per warp-task, 8-lane groups, float4 cols ----
        {
            const int sub = lane >> 3, c = lane & 7;
            for (int t = wid; t < nb * 18; t += 8) {
                int bl = (t >= 18) ? 1 : 0;
                int tg = t - 18 * bl;
                int e = tg * 4 + sub;
                int sN = rp_s[2 * e], dN = rp_s[2 * e + 1];
                float4 tpv = *(const float4*)(tpb + bl * 128 + 64 + c * 4);
                float4 Psv = *(const float4*)(P_s + (bl * 54 + sN) * 100 + c * 4);
                float4 Pdv = *(const float4*)(P_s + (bl * 54 + dN) * 100 + 32 + c * 4);
                float4 w2v = *(const float4*)(w2_s + 64 + c * 4);
                float part = mishf(tpv.x + Psv.x + Pdv.x) * w2v.x
                           + mishf(tpv.y + Psv.y + Pdv.y) * w2v.y
                           + mishf(tpv.z + Psv.z + Pdv.z) * w2v.z
                           + mishf(tpv.w + Psv.w + Pdv.w) * w2v.w;
                part += __shfl_xor_sync(0xffffffffu, part, 1);
                part += __shfl_xor_sync(0xffffffffu, part, 2);
                part += __shfl_xor_sync(0xffffffffu, part, 4);
                if (c == 0) out[((size_t)(pair * 2 + bl)) * 397 + 113 + e] = part + b2_s[2];
            }
        }
        // ---- robber heads ----
        for (int t = wid; t < nb * 19; t += 8) {
            int bl = (t >= 19) ? 1 : 0;
            int tt = t - 19 * bl;
            float a = 0.f;
            #pragma unroll
            for (int i = 0; i < 6; i++)
                a += P_s[(bl * 54 + ti_s[tt * 6 + i]) * 100 + 64 + lane];
            float m = mishf(tpb[bl * 128 + 96 + lane] + a * (1.f / 6.f));
            #pragma unroll
            for (int o = 0; o < 5; o++) {
                float red = warp_sum(m * rob2_s[o * 32 + lane]);
                if (lane == 0)
                    out[((size_t)(pair * 2 + bl)) * 397 + 185 + tt * 5 + o] = red + b2_s[3 + o];
            }
        }
        // (no end barrier: next iteration's top barrier protects P_s/tproj)
    }
}

// ------------------------------ K3: BN + mish + gfc2, 8-row batched ------------------------------
__global__ __launch_bounds__(128) void k3(const float* __restrict__ gfc2_w,
                                          const float* __restrict__ gfc2_b,
                                          float* __restrict__ out, int B) {
    __shared__ __align__(16) float m8[80 * 8];
    __shared__ __align__(16) float Wg[80 * 122];
    __shared__ float bs[122];
    __shared__ float sc[80], sh[80];
    int tid = threadIdx.x;
    for (int i = tid; i < 80 * 122; i += 128) {
        int k = i / 122, t = i % 122;
        int r = (t < 5) ? t : (275 + t);
        Wg[i] = gfc2_w[r * 80 + k];
    }
    if (tid < 122) { int r = (tid < 5) ? tid : (275 + tid); bs[tid] = gfc2_b[r]; }
    if (tid < 80) { sc[tid] = d_bnscale[tid]; sh[tid] = d_bnshift[tid]; }
    __syncthreads();
    int nq = (B + 7) >> 3;
    for (int qb = blockIdx.x; qb < nq; qb += gridDim.x) {
        if (tid < 80) {
            #pragma unroll
            for (int rb = 0; rb < 8; rb++) {
                int b = qb * 8 + rb;
                float v = (b < B) ? d_h[(size_t)b * 80 + tid] : 0.f;
                m8[tid * 8 + rb] = mishf(v * sc[tid] + sh[tid]);
            }
        }
        __syncthreads();
        if (tid < 122) {
            float a[8];
            #pragma unroll
            for (int rb = 0; rb < 8; rb++) a[rb] = bs[tid];
            for (int k = 0; k < 80; k++) {
                float4 mA = *(const float4*)(m8 + k * 8);
                float4 mB = *(const float4*)(m8 + k * 8 + 4);
                float w = Wg[k * 122 + tid];
                a[0] += mA.x * w; a[1] += mA.y * w; a[2] += mA.z * w; a[3] += mA.w * w;
                a[4] += mB.x * w; a[5] += mB.y * w; a[6] += mB.z * w; a[7] += mB.w * w;
            }
            int col = (tid < 5) ? tid : (275 + tid);
            #pragma unroll
            for (int rb = 0; rb < 8; rb++) {
                int b = qb * 8 + rb;
                if (b < B) out[(size_t)b * 397 + col] = a[rb];
            }
        }
        __syncthreads();
    }
}

// ------------------------------ launch ------------------------------
extern "C" void kernel_launch(void* const* d_in, const int* in_sizes, int n_in,
                              void* d_out, int out_size) {
    const float* trunk      = (const float*)d_in[0];
    const float* node_emb   = (const float*)d_in[1];
    const int*   road_pairs = (const int*)d_in[2];
    const int*   tile_nodes = (const int*)d_in[3];
    const float* ln_t_w = (const float*)d_in[4];
    const float* ln_t_b = (const float*)d_in[5];
    const float* ln_n_w = (const float*)d_in[6];
    const float* ln_n_b = (const float*)d_in[7];
    const float* gfc1_w = (const float*)d_in[8];
    const float* gfc1_b = (const float*)d_in[9];
    const float* bn_w   = (const float*)d_in[10];
    const float* bn_b   = (const float*)d_in[11];
    const float* gfc2_w = (const float*)d_in[12];
    const float* gfc2_b = (const float*)d_in[13];
    const float* sett1_w = (const float*)d_in[14];
    const float* sett1_b = (const float*)d_in[15];
    const float* sett2_w = (const float*)d_in[16];
    const float* sett2_b = (const float*)d_in[17];
    const float* city1_w = (const float*)d_in[18];
    const float* city1_b = (const float*)d_in[19];
    const float* city2_w = (const float*)d_in[20];
    const float* city2_b = (const float*)d_in[21];
    const float* road1_w = (const float*)d_in[22];
    const float* road1_b = (const float*)d_in[23];
    const float* road2_w = (const float*)d_in[24];
    const float* road2_b = (const float*)d_in[25];
    const float* rob1_w = (const float*)d_in[26];
    const float* rob1_b = (const float*)d_in[27];
    const float* rob2_w = (const float*)d_in[28];
    const float* rob2_b = (const float*)d_in[29];

    int B = in_sizes[0] / 80;
    if (B > BMAX) B = BMAX;
    float* out = (float*)d_out;
    int nblk1 = (B + 127) / 128;

    cudaFuncSetAttribute(k1, cudaFuncAttributeMaxDynamicSharedMemorySize, K1_SMEM);
    cudaFuncSetAttribute(k2, cudaFuncAttributeMaxDynamicSharedMemorySize, SM_TOTAL);

    k_prep<<<(208 * 80 + 255) / 256, 256>>>(sett1_w, city1_w, road1_w, rob1_w, gfc1_w,
                                            sett1_b, city1_b, road1_b, rob1_b, gfc1_b);
    k1<<<nblk1, 512, K1_SMEM>>>(trunk, ln_t_w, ln_t_b, B);
    k_bn<<<1, 80>>>(bn_w, bn_b, B, nblk1);
    k2<<<K2_GRID, 256, SM_TOTAL>>>(node_emb, ln_n_w, ln_n_b, road_pairs, tile_nodes,
                                   sett2_w, sett2_b, city2_w, city2_b,
                                   road2_w, road2_b, rob2_w, rob2_b, out, B);
    k3<<<K3_GRID, 128>>>(gfc2_w, gfc2_b, out, B);
}

// round 13
// speedup vs baseline: 1.2559x; 1.1350x over previous
#include <cuda_runtime.h>
#include <cuda_fp16.h>
#include <cstdint>
#include <cstddef>

// ---------------------------------------------------------------------------
// SmallSpatialPolicyHead — R12 + k2: float4 robber heads (4 tiles/warp-task),
// 8-col LN-B items (uint4 stores), hoisted invariant head weights.
// ---------------------------------------------------------------------------

#define BMAX 16384
#define K2_GRID 296
#define K3_GRID 592

__device__ float d_tb[208];
__device__ __half d_Wh[160 * 48];    // k2 node proj hi  [n][k]
__device__ __half d_Wl[160 * 48];    // k2 node proj lo
__device__ __half d_Wth[208 * 80];   // k1 trunk proj hi [o][k]
__device__ __half d_Wtl[208 * 80];   // k1 trunk proj lo
__device__ float d_tproj[(size_t)BMAX * 128];
__device__ float d_h[(size_t)BMAX * 80];
__device__ float d_partial[296 * 160];
__device__ float d_bnscale[80];
__device__ float d_bnshift[80];

// ---- k2 smem byte offsets ----
#define SM_XP    0             // P_s 108x100 f = 43200
#define SM_AH    43200         // 128x56 fp16 = 14336
#define SM_AL    57536
#define SM_WH    71872         // 160x56 fp16 = 17920
#define SM_WL    89792
#define WLOFF    17920
#define SM_TPROJ 107712        // 2 x 256 f (double buffer)
#define SM_W2    109760        // 96 f
#define SM_ROB2  110144        // 160 f
#define SM_B2    110784        // 8 f
#define SM_LNW   110816        // 48 f
#define SM_LNB   111008        // 48 f
#define SM_MU    111200        // 2 x 110 f (double buffer, 448B each)
#define SM_IS    112096        // 2 x 110 f
#define SM_RP    112992        // 144 i
#define SM_TI    113568        // 114 i
#define SM_TOTAL 114024

// ---- k1 smem byte offsets ----
#define X1_XS    0             // 128x84 f = 43008 (reused as hs)
#define X1_AH    43008         // 128x88 fp16 = 22528
#define X1_AL    65536
#define X1_WH    88064         // 208x88 fp16 = 36608
#define X1_WL    124672
#define W1OFF    36608
#define X1_TB    161280        // 208 f
#define X1_LNW   162112        // 80 f
#define X1_LNB   162432        // 80 f
#define K1_SMEM  162752

__device__ __forceinline__ uint32_t smem_u32(const void* p) {
    uint32_t a;
    asm("{ .reg .u64 t; cvta.to.shared.u64 t, %1; cvt.u32.u64 %0, t; }" : "=r"(a) : "l"(p));
    return a;
}
__device__ __forceinline__ void cp16(uint32_t dst, const void* src) {
    asm volatile("cp.async.cg.shared.global [%0], [%1], 16;" :: "r"(dst), "l"(src));
}
#define CP_COMMIT() asm volatile("cp.async.commit_group;" ::: "memory")
#define CP_WAIT_ALL() asm volatile("cp.async.wait_group 0;" ::: "memory")
#define CP_COMMIT_WAIT() do { CP_COMMIT(); CP_WAIT_ALL(); } while (0)

#define LDSM_X4(r0,r1,r2,r3,addr) \
    asm volatile("ldmatrix.sync.aligned.m8n8.x4.shared.b16 {%0,%1,%2,%3}, [%4];" \
        : "=r"(r0),"=r"(r1),"=r"(r2),"=r"(r3) : "r"(addr))
#define LDSM_X2(r0,r1,addr) \
    asm volatile("ldmatrix.sync.aligned.m8n8.x2.shared.b16 {%0,%1}, [%2];" \
        : "=r"(r0),"=r"(r1) : "r"(addr))
#define LDSM_X4_NV(r0,r1,r2,r3,addr) \
    asm("ldmatrix.sync.aligned.m8n8.x4.shared.b16 {%0,%1,%2,%3}, [%4];" \
        : "=r"(r0),"=r"(r1),"=r"(r2),"=r"(r3) : "r"(addr))

__device__ __forceinline__ void mma16816(float* d, const uint32_t* a, uint32_t b0, uint32_t b1) {
    asm volatile(
        "mma.sync.aligned.m16n8k16.row.col.f32.f16.f16.f32 "
        "{%0,%1,%2,%3},{%4,%5,%6,%7},{%8,%9},{%0,%1,%2,%3};"
        : "+f"(d[0]), "+f"(d[1]), "+f"(d[2]), "+f"(d[3])
        : "r"(a[0]), "r"(a[1]), "r"(a[2]), "r"(a[3]), "r"(b0), "r"(b1));
}

__device__ __forceinline__ float mishf(float x) {
    float u = __expf(fminf(x, 15.f));
    float d = __fmaf_rn(u, u + 2.f, 2.f);
    return x - __fdividef(2.f * x, d);
}
__device__ __forceinline__ float warp_sum(float v) {
    #pragma unroll
    for (int o = 16; o; o >>= 1) v += __shfl_xor_sync(0xffffffffu, v, o);
    return v;
}

// ------------------------------ prep ------------------------------
__global__ void k_prep(const float* __restrict__ sett1_w, const float* __restrict__ city1_w,
                       const float* __restrict__ road1_w, const float* __restrict__ rob1_w,
                       const float* __restrict__ gfc1_w,
                       const float* __restrict__ sett1_b, const float* __restrict__ city1_b,
                       const float* __restrict__ road1_b, const float* __restrict__ rob1_b,
                       const float* __restrict__ gfc1_b) {
    int i = blockIdx.x * blockDim.x + threadIdx.x;
    if (i < 160 * 48) {
        int j = i / 48, k = i % 48;
        float v;
        if (j < 32)       v = sett1_w[j * 128 + 80 + k];
        else if (j < 64)  v = city1_w[(j - 32) * 128 + 80 + k];
        else if (j < 96)  v = road1_w[(j - 64) * 176 + 80 + k];
        else if (j < 128) v = road1_w[(j - 96) * 176 + 128 + k];
        else              v = rob1_w[(j - 128) * 128 + 80 + k];
        __half h = __float2half(v);
        d_Wh[i] = h;
        d_Wl[i] = __float2half(v - __half2float(h));
    }
    if (i < 208 * 80) {
        int o = i / 80, k = i % 80;
        float v;
        if (o < 32)       v = sett1_w[o * 128 + k];
        else if (o < 64)  v = city1_w[(o - 32) * 128 + k];
        else if (o < 96)  v = road1_w[(o - 64) * 176 + k];
        else if (o < 128) v = rob1_w[(o - 96) * 128 + k];
        else              v = gfc1_w[(o - 128) * 80 + k];
        __half h = __float2half(v);
        d_Wth[i] = h;
        d_Wtl[i] = __float2half(v - __half2float(h));
    }
    if (i < 208) {
        float v;
        if (i < 32)       v = sett1_b[i];
        else if (i < 64)  v = city1_b[i - 32];
        else if (i < 96)  v = road1_b[i - 64];
        else if (i < 128) v = rob1_b[i - 96];
        else              v = gfc1_b[i - 128];
        d_tb[i] = v;
    }
}

// ------------------------------ K1: HMMA trunk kernel (unchanged, proven) ------------------------------
__global__ __launch_bounds__(512, 1) void k1(const float* __restrict__ trunk,
                                             const float* __restrict__ ln_t_w,
                                             const float* __restrict__ ln_t_b, int B) {
    extern __shared__ char smem[];
    const uint32_t sbase = smem_u32(smem);
    const int tid = threadIdx.x, wid = tid >> 5, lane = tid & 31;

    float* xs  = (float*)(smem + X1_XS);
    float* hs  = (float*)(smem + X1_XS);
    float* tb_s = (float*)(smem + X1_TB);
    float* lnw = (float*)(smem + X1_LNW);
    float* lnb = (float*)(smem + X1_LNB);

    for (int i = tid; i < 208 * 80; i += 512) {
        int o = i / 80, k = i % 80;
        *(__half*)(smem + X1_WH + (o * 88 + k) * 2) = d_Wth[i];
        *(__half*)(smem + X1_WL + (o * 88 + k) * 2) = d_Wtl[i];
    }
    for (int i = tid; i < 208; i += 512) tb_s[i] = d_tb[i];
    if (tid < 80) { lnw[tid] = ln_t_w[tid]; lnb[tid] = ln_t_b[tid]; }

    const int rows_valid = min(128, B - (int)blockIdx.x * 128);

    {
        const float4* tr4 = (const float4*)trunk;
        size_t base4 = (size_t)blockIdx.x * 2560;
        #pragma unroll
        for (int q = 0; q < 5; q++) {
            int il = tid + q * 512;
            int row = il / 20, c = il % 20;
            if (row < rows_valid)
                cp16(sbase + X1_XS + (uint32_t)((row * 84 + 4 * c) * 4), tr4 + base4 + il);
        }
        CP_COMMIT_WAIT();
    }
    __syncthreads();

    if (tid < 256) {
        const int r = tid >> 1, h = tid & 1;
        float4 v[10];
        if (r < rows_valid) {
            const float4* xr = (const float4*)(xs + r * 84 + h * 40);
            #pragma unroll
            for (int j = 0; j < 10; j++) v[j] = xr[j];
        } else {
            #pragma unroll
            for (int j = 0; j < 10; j++) v[j] = make_float4(0.f, 0.f, 0.f, 0.f);
        }
        float s = 0.f, q = 0.f;
        #pragma unroll
        for (int j = 0; j < 10; j++) {
            s += v[j].x + v[j].y + v[j].z + v[j].w;
            q += v[j].x * v[j].x + v[j].y * v[j].y + v[j].z * v[j].z + v[j].w * v[j].w;
        }
        s += __shfl_xor_sync(0xffffffffu, s, 1);
        q += __shfl_xor_sync(0xffffffffu, q, 1);
        float mu = s * (1.f / 80.f);
        float is = rsqrtf(q * (1.f / 80.f) - mu * mu + 1e-5f);
        char* dh = smem + X1_AH + (r * 88 + h * 40) * 2;
        char* dl = dh + (X1_AL - X1_AH);
        const float4* lw4 = (const float4*)(lnw + h * 40);
        const float4* lb4 = (const float4*)(lnb + h * 40);
        #pragma unroll
        for (int j = 0; j < 10; j++) {
            float4 w = lw4[j], b = lb4[j];
            float a0 = (v[j].x - mu) * is * w.x + b.x;
            float a1 = (v[j].y - mu) * is * w.y + b.y;
            float a2 = (v[j].z - mu) * is * w.z + b.z;
            float a3 = (v[j].w - mu) * is * w.w + b.w;
            if (r >= rows_valid) { a0 = a1 = a2 = a3 = 0.f; }
            __half2 h01 = __floats2half2_rn(a0, a1), h23 = __floats2half2_rn(a2, a3);
            __half2 l01 = __floats2half2_rn(a0 - __low2float(h01), a1 - __high2float(h01));
            __half2 l23 = __floats2half2_rn(a2 - __low2float(h23), a3 - __high2float(h23));
            uint2 uh; uh.x = *(uint32_t*)&h01; uh.y = *(uint32_t*)&h23;
            uint2 ul; ul.x = *(uint32_t*)&l01; ul.y = *(uint32_t*)&l23;
            *(uint2*)(dh + j * 8) = uh;
            *(uint2*)(dl + j * 8) = ul;
        }
    }
    __syncthreads();

    {
        const int mt = wid & 7, nh = wid >> 3;
        const int g = lane >> 2, k0 = (lane & 3) * 2;
        const uint32_t abase = sbase + X1_AH +
            (uint32_t)((mt * 16 + (lane & 15)) * 176 + (lane >> 4) * 16);
        uint32_t ah[5][4];
        #pragma unroll
        for (int ks = 0; ks < 5; ks++)
            LDSM_X4(ah[ks][0], ah[ks][1], ah[ks][2], ah[ks][3], abase + ks * 32);

        uint32_t wx4 = sbase + X1_WH +
            (uint32_t)((lane & 7) * 176 + (lane >> 3) * 16) + (uint32_t)(nh * 13 * 1408);
        uint32_t wx2 = sbase + X1_WH +
            (uint32_t)((lane & 7) * 176 + ((lane >> 3) & 1) * 16 + 128) + (uint32_t)(nh * 13 * 1408);

        #pragma unroll
        for (int ni = 0; ni < 13; ni++) {
            const int nt = nh * 13 + ni;
            uint32_t bhA[4], bhB[4], bh2[2], blA[4], blB[4], bl2[2];
            LDSM_X4(bhA[0], bhA[1], bhA[2], bhA[3], wx4);
            LDSM_X4(bhB[0], bhB[1], bhB[2], bhB[3], wx4 + 64);
            LDSM_X2(bh2[0], bh2[1], wx2);
            LDSM_X4(blA[0], blA[1], blA[2], blA[3], wx4 + W1OFF);
            LDSM_X4(blB[0], blB[1], blB[2], blB[3], wx4 + 64 + W1OFF);
            LDSM_X2(bl2[0], bl2[1], wx2 + W1OFF);

            float acc[4] = {0.f, 0.f, 0.f, 0.f};
            mma16816(acc, ah[0], bhA[0], bhA[1]);
            mma16816(acc, ah[1], bhA[2], bhA[3]);
            mma16816(acc, ah[2], bhB[0], bhB[1]);
            mma16816(acc, ah[3], bhB[2], bhB[3]);
            mma16816(acc, ah[4], bh2[0], bh2[1]);
            mma16816(acc, ah[0], blA[0], blA[1]);
            mma16816(acc, ah[1], blA[2], blA[3]);
            mma16816(acc, ah[2], blB[0], blB[1]);
            mma16816(acc, ah[3], blB[2], blB[3]);
            mma16816(acc, ah[4], bl2[0], bl2[1]);
            {
                uint32_t al[4];
                const uint32_t albase = abase + (X1_AL - X1_AH);
                LDSM_X4(al[0], al[1], al[2], al[3], albase);
                mma16816(acc, al, bhA[0], bhA[1]);
                LDSM_X4(al[0], al[1], al[2], al[3], albase + 32);
                mma16816(acc, al, bhA[2], bhA[3]);
                LDSM_X4(al[0], al[1], al[2], al[3], albase + 64);
                mma16816(acc, al, bhB[0], bhB[1]);
                LDSM_X4(al[0], al[1], al[2], al[3], albase + 96);
                mma16816(acc, al, bhB[2], bhB[3]);
                LDSM_X4(al[0], al[1], al[2], al[3], albase + 128);
                mma16816(acc, al, bh2[0], bh2[1]);
            }
            wx4 += 1408; wx2 += 1408;

            const int col = nt * 8 + k0;
            const int row0 = mt * 16 + g, row1 = row0 + 8;
            if (col < 128) {
                float b0 = tb_s[col], b1 = tb_s[col + 1];
                if (row0 < rows_valid) {
                    size_t o = (size_t)((size_t)blockIdx.x * 128 + row0) * 128 + col;
                    d_tproj[o] = acc[0] + b0; d_tproj[o + 1] = acc[1] + b1;
                }
                if (row1 < rows_valid) {
                    size_t o = (size_t)((size_t)blockIdx.x * 128 + row1) * 128 + col;
                    d_tproj[o] = acc[2] + b0; d_tproj[o + 1] = acc[3] + b1;
                }
            } else {
                const int ch = col - 128;
                hs[row0 * 84 + ch] = acc[0]; hs[row0 * 84 + ch + 1] = acc[1];
                hs[row1 * 84 + ch] = acc[2]; hs[row1 * 84 + ch + 1] = acc[3];
                if (row0 < rows_valid) {
                    size_t o = (size_t)((size_t)blockIdx.x * 128 + row0) * 80 + ch;
                    d_h[o] = acc[0]; d_h[o + 1] = acc[1];
                }
                if (row1 < rows_valid) {
                    size_t o = (size_t)((size_t)blockIdx.x * 128 + row1) * 80 + ch;
                    d_h[o] = acc[2]; d_h[o + 1] = acc[3];
                }
            }
        }
    }
    __syncthreads();

    if (tid < 80) {
        float s1 = 0.f, s2 = 0.f;
        for (int r = 0; r < rows_valid; r++) {
            float v = hs[r * 84 + tid];
            s1 += v; s2 += v * v;
        }
        d_partial[blockIdx.x * 160 + tid] = s1;
        d_partial[blockIdx.x * 160 + 80 + tid] = s2;
    }
}

// ------------------------------ BN finalize ------------------------------
__global__ void k_bn(const float* __restrict__ bn_w, const float* __restrict__ bn_b,
                     int B, int nblk) {
    int t = threadIdx.x;
    if (t >= 80) return;
    float S1 = 0.f, S2 = 0.f;
    for (int blk = 0; blk < nblk; blk++) {
        S1 += d_partial[blk * 160 + t];
        S2 += d_partial[blk * 160 + 80 + t];
    }
    float invB = 1.f / (float)B;
    float mu = S1 * invB;
    float var = S2 * invB - mu * mu;
    float sc = bn_w[t] * rsqrtf(var + 1e-5f);
    d_bnscale[t] = sc;
    d_bnshift[t] = bn_b[t] - mu * sc;
}

// ------------------------------ K2: HMMA fused node kernel, pipelined ------------------------------
__global__ __launch_bounds__(256, 2) void k2(const float* __restrict__ node_emb,
                                             const float* __restrict__ ln_n_w,
                                             const float* __restrict__ ln_n_b,
                                             const int* __restrict__ road_pairs,
                                             const int* __restrict__ tile_nodes,
                                             const float* __restrict__ sett2_w, const float* __restrict__ sett2_b,
                                             const float* __restrict__ city2_w, const float* __restrict__ city2_b,
                                             const float* __restrict__ road2_w, const float* __restrict__ road2_b,
                                             const float* __restrict__ rob2_w, const float* __restrict__ rob2_b,
                                             float* __restrict__ out, int B) {
    extern __shared__ char smem[];
    const uint32_t sbase = smem_u32(smem);
    const int tid = threadIdx.x, wid = tid >> 5, lane = tid & 31;

    float* P_s     = (float*)(smem + SM_XP);   // rows x 100
    float* w2_s    = (float*)(smem + SM_W2);
    float* rob2_s  = (float*)(smem + SM_ROB2);
    float* b2_s    = (float*)(smem + SM_B2);
    float* lnw     = (float*)(smem + SM_LNW);
    float* lnb     = (float*)(smem + SM_LNB);
    int*   rp_s    = (int*)(smem + SM_RP);
    int*   ti_s    = (int*)(smem + SM_TI);

    for (int i = tid; i < 160 * 48; i += 256) {
        int n = i / 48, k = i % 48;
        *(__half*)(smem + SM_WH + (n * 56 + k) * 2) = d_Wh[i];
        *(__half*)(smem + SM_WL + (n * 56 + k) * 2) = d_Wl[i];
    }
    if (tid < 48) { lnw[tid] = ln_n_w[tid]; lnb[tid] = ln_n_b[tid]; }
    if (tid < 32) { w2_s[tid] = sett2_w[tid]; w2_s[32 + tid] = city2_w[tid]; w2_s[64 + tid] = road2_w[tid]; }
    if (tid < 160) rob2_s[tid] = rob2_w[tid];
    if (tid == 0) { b2_s[0] = sett2_b[0]; b2_s[1] = city2_b[0]; b2_s[2] = road2_b[0]; }
    if (tid < 5) b2_s[3 + tid] = rob2_b[tid];
    if (tid < 144) rp_s[tid] = road_pairs[tid];
    if (tid < 114) ti_s[tid] = tile_nodes[tid];

    const int g = lane >> 2;
    const int k0 = (lane & 3) * 2;
    const int mrow = (wid & 3) * 32;
    const int hd = wid >> 2;              // 0 = sett group, 1 = city group

    int rown[4]; int tpoff[4];
    #pragma unroll
    for (int s = 0; s < 4; s++) {
        rown[s] = mrow + 16 * (s >> 1) + 8 * (s & 1) + g;
        tpoff[s] = (rown[s] >= 54) ? 128 : 0;
    }

    const uint32_t wx4base0 = sbase + SM_WH +
        (uint32_t)((lane & 7) * 112 + (lane >> 3) * 16);
    const uint32_t wpbase0 = sbase + SM_WH +
        (uint32_t)((lane & 7) * 112 + ((lane >> 3) & 1) * 16 + 64 + ((lane >> 4) & 1) * 896);
    const uint32_t abase0 = sbase + SM_AH +
        (uint32_t)((mrow + (lane & 15)) * 112 + (lane >> 4) * 16);

    const long npairs = ((long)B + 1) / 2;
    const size_t totp4 = (size_t)B * 32;
    const float4* tp4 = (const float4*)d_tproj;

    // ---- prologue: LN-A + tproj prefetch for first pair into buf 0 ----
    long pair = blockIdx.x;
    int buf = 0;
    if (pair < npairs) {
        const int nr = (int)((long)B * 54 - pair * 108 >= 108 ? 108 : (long)B * 54 - pair * 108);
        if (tid < nr) {
            const float4* xr = (const float4*)(node_emb + ((size_t)pair * 108 + tid) * 48);
            float s = 0.f, q = 0.f;
            #pragma unroll
            for (int j = 0; j < 12; j++) {
                float4 v = xr[j];
                s += v.x + v.y + v.z + v.w;
                q += v.x * v.x + v.y * v.y + v.z * v.z + v.w * v.w;
            }
            float mu = s * (1.f / 48.f);
            ((float*)(smem + SM_MU))[tid] = mu;
            ((float*)(smem + SM_IS))[tid] = rsqrtf(q * (1.f / 48.f) - mu * mu + 1e-5f);
        }
        if (tid < 64) {
            size_t t4 = (size_t)pair * 64 + tid;
            if (t4 < totp4) cp16(sbase + SM_TPROJ + tid * 16, tp4 + t4);
        }
        CP_COMMIT();
    }
    __syncthreads();   // order init smem writes before hoisted invariant loads

    // hoisted loop-invariant head weights
    const int rc = lane & 7;                                   // road/robber col group
    const float4 w2road = *(const float4*)(w2_s + 64 + rc * 4);
    float2 w2sc[2][2];
    #pragma unroll
    for (int pi = 0; pi < 2; pi++)
        #pragma unroll
        for (int sub = 0; sub < 2; sub++)
            w2sc[pi][sub] = *(const float2*)(w2_s + (4 * hd + 2 * pi + sub) * 8 + k0);

    for (; pair < npairs; pair += gridDim.x, buf ^= 1) {
        const float* mu_s = (const float*)(smem + SM_MU + buf * 448);
        const float* is_s = (const float*)(smem + SM_IS + buf * 448);
        const float* tpb  = (const float*)(smem + SM_TPROJ + buf * 1024);

        CP_WAIT_ALL();
        __syncthreads();

        const int nrows = (int)((long)B * 54 - pair * 108 >= 108 ? 108 : (long)B * 54 - pair * 108);

        // ---- LN phase B: 8 cols per item, uint4 stores ----
        for (int i = tid; i < 648; i += 256) {
            int r = i / 6, c8 = (i % 6) * 8;
            if (r < nrows) {
                const float* src = node_emb + ((size_t)pair * 108 + r) * 48 + c8;
                float4 va = *(const float4*)(src);
                float4 vb = *(const float4*)(src + 4);
                float mu = mu_s[r], is = is_s[r];
                float a0 = (va.x - mu) * is * lnw[c8]     + lnb[c8];
                float a1 = (va.y - mu) * is * lnw[c8 + 1] + lnb[c8 + 1];
                float a2 = (va.z - mu) * is * lnw[c8 + 2] + lnb[c8 + 2];
                float a3 = (va.w - mu) * is * lnw[c8 + 3] + lnb[c8 + 3];
                float a4 = (vb.x - mu) * is * lnw[c8 + 4] + lnb[c8 + 4];
                float a5 = (vb.y - mu) * is * lnw[c8 + 5] + lnb[c8 + 5];
                float a6 = (vb.z - mu) * is * lnw[c8 + 6] + lnb[c8 + 6];
                float a7 = (vb.w - mu) * is * lnw[c8 + 7] + lnb[c8 + 7];
                __half2 h01 = __floats2half2_rn(a0, a1), h23 = __floats2half2_rn(a2, a3);
                __half2 h45 = __floats2half2_rn(a4, a5), h67 = __floats2half2_rn(a6, a7);
                __half2 l01 = __floats2half2_rn(a0 - __low2float(h01), a1 - __high2float(h01));
                __half2 l23 = __floats2half2_rn(a2 - __low2float(h23), a3 - __high2float(h23));
                __half2 l45 = __floats2half2_rn(a4 - __low2float(h45), a5 - __high2float(h45));
                __half2 l67 = __floats2half2_rn(a6 - __low2float(h67), a7 - __high2float(h67));
                uint4 uh; uh.x = *(uint32_t*)&h01; uh.y = *(uint32_t*)&h23;
                uh.z = *(uint32_t*)&h45; uh.w = *(uint32_t*)&h67;
                uint4 ul; ul.x = *(uint32_t*)&l01; ul.y = *(uint32_t*)&l23;
                ul.z = *(uint32_t*)&l45; ul.w = *(uint32_t*)&l67;
                *(uint4*)(smem + SM_AH + (r * 56 + c8) * 2) = uh;
                *(uint4*)(smem + SM_AL + (r * 56 + c8) * 2) = ul;
            }
        }
        __syncthreads();

        // ---- A fragments via ldmatrix (volatile: A changes per iteration) ----
        uint32_t afh[2][3][4], afl[2][3][4];
        #pragma unroll
        for (int t = 0; t < 2; t++) {
            #pragma unroll
            for (int ks = 0; ks < 3; ks++) {
                uint32_t ad = abase0 + (uint32_t)(t * 1792 + ks * 32);
                LDSM_X4(afh[t][ks][0], afh[t][ks][1], afh[t][ks][2], afh[t][ks][3], ad);
                LDSM_X4(afl[t][ks][0], afl[t][ks][1], afl[t][ks][2], afl[t][ks][3],
                        ad + (SM_AL - SM_AH));
            }
        }

        // ---- prefetch next pair: LN-A + tproj into buf^1 (hides under MMA) ----
        {
            long nxt = pair + gridDim.x;
            if (nxt < npairs) {
                const int nr = (int)((long)B * 54 - nxt * 108 >= 108 ? 108 : (long)B * 54 - nxt * 108);
                if (tid < nr) {
                    const float4* xr = (const float4*)(node_emb + ((size_t)nxt * 108 + tid) * 48);
                    float s = 0.f, q = 0.f;
                    #pragma unroll
                    for (int j = 0; j < 12; j++) {
                        float4 v = xr[j];
                        s += v.x + v.y + v.z + v.w;
                        q += v.x * v.x + v.y * v.y + v.z * v.z + v.w * v.w;
                    }
                    float mu = s * (1.f / 48.f);
                    ((float*)(smem + SM_MU + (buf ^ 1) * 448))[tid] = mu;
                    ((float*)(smem + SM_IS + (buf ^ 1) * 448))[tid] =
                        rsqrtf(q * (1.f / 48.f) - mu * mu + 1e-5f);
                }
                if (tid < 64) {
                    size_t t4 = (size_t)nxt * 64 + tid;
                    if (t4 < totp4)
                        cp16(sbase + SM_TPROJ + (buf ^ 1) * 1024 + tid * 16, tp4 + t4);
                }
                CP_COMMIT();
            }
        }

        float sacc[4] = {0.f, 0.f, 0.f, 0.f};

        // nt pairs: hd=0 -> (0,1),(2,3),(8,9),(10,11),(12,13);
        //           hd=1 -> (4,5),(6,7),(14,15),(16,17),(18,19)
        #pragma unroll
        for (int pi = 0; pi < 5; pi++) {
            const int ntA = (pi < 2) ? (4 * hd + 2 * pi) : (8 + 6 * hd + 2 * (pi - 2));
            uint32_t c2h[4], c2l[4];
            LDSM_X4_NV(c2h[0], c2h[1], c2h[2], c2h[3], wpbase0 + ntA * 896);
            LDSM_X4_NV(c2l[0], c2l[1], c2l[2], c2l[3], wpbase0 + ntA * 896 + WLOFF);

            #pragma unroll
            for (int sub = 0; sub < 2; sub++) {
                const int nt = ntA + sub;
                uint32_t bh[4], bl[4];
                LDSM_X4_NV(bh[0], bh[1], bh[2], bh[3], wx4base0 + nt * 896);
                LDSM_X4_NV(bl[0], bl[1], bl[2], bl[3], wx4base0 + nt * 896 + WLOFF);
                const uint32_t bh2a = c2h[2 * sub], bh2b = c2h[2 * sub + 1];
                const uint32_t bl2a = c2l[2 * sub], bl2b = c2l[2 * sub + 1];

                float acc[2][4] = {{0.f, 0.f, 0.f, 0.f}, {0.f, 0.f, 0.f, 0.f}};
                #pragma unroll
                for (int t = 0; t < 2; t++) {
                    mma16816(acc[t], afh[t][0], bh[0], bh[1]);
                    mma16816(acc[t], afh[t][1], bh[2], bh[3]);
                    mma16816(acc[t], afh[t][2], bh2a, bh2b);
                    mma16816(acc[t], afh[t][0], bl[0], bl[1]);
                    mma16816(acc[t], afh[t][1], bl[2], bl[3]);
                    mma16816(acc[t], afh[t][2], bl2a, bl2b);
                    mma16816(acc[t], afl[t][0], bh[0], bh[1]);
                    mma16816(acc[t], afl[t][1], bh[2], bh[3]);
                    mma16816(acc[t], afl[t][2], bh2a, bh2b);
                }
                const int col = nt * 8 + k0;
                if (pi < 2) {
                    float w2a = w2sc[pi][sub].x, w2b = w2sc[pi][sub].y;
                    #pragma unroll
                    for (int s = 0; s < 4; s++) {
                        float2 tpv = *(const float2*)(tpb + tpoff[s] + col);
                        float v0 = acc[s >> 1][2 * (s & 1)];
                        float v1 = acc[s >> 1][2 * (s & 1) + 1];
                        sacc[s] += mishf(v0 + tpv.x) * w2a + mishf(v1 + tpv.y) * w2b;
                    }
                } else {
                    #pragma unroll
                    for (int s = 0; s < 4; s++) {
                        int r = rown[s];
                        if (r < 108)
                            *(float2*)(P_s + r * 100 + (col - 64)) =
                                make_float2(acc[s >> 1][2 * (s & 1)], acc[s >> 1][2 * (s & 1) + 1]);
                    }
                }
            }
        }

        // sett/city finalize
        {
            #pragma unroll
            for (int s = 0; s < 4; s++) {
                sacc[s] += __shfl_xor_sync(0xffffffffu, sacc[s], 1);
                sacc[s] += __shfl_xor_sync(0xffffffffu, sacc[s], 2);
            }
            if ((lane & 3) == 0) {
                #pragma unroll
                for (int s = 0; s < 4; s++) {
                    int r = rown[s];
                    if (r < nrows) {
                        int bl = (r >= 54) ? 1 : 0;
                        int n = r - 54 * bl;
                        out[((size_t)(pair * 2 + bl)) * 397 + 5 + 54 * hd + n] = sacc[s] + b2_s[hd];
                    }
                }
            }
        }
        __syncthreads();

        const int nb = (nrows > 54) ? 2 : 1;
        const int sub = lane >> 3;            // 8-lane group id 0..3
        // ---- road heads: 4 edges per warp-task, float4 cols ----
        for (int t = wid; t < nb * 18; t += 8) {
            int bl = (t >= 18) ? 1 : 0;
            int tg = t - 18 * bl;
            int e = tg * 4 + sub;
            int sN = rp_s[2 * e], dN = rp_s[2 * e + 1];
            float4 tpv = *(const float4*)(tpb + bl * 128 + 64 + rc * 4);
            float4 Psv = *(const float4*)(P_s + (bl * 54 + sN) * 100 + rc * 4);
            float4 Pdv = *(const float4*)(P_s + (bl * 54 + dN) * 100 + 32 + rc * 4);
            float part = mishf(tpv.x + Psv.x + Pdv.x) * w2road.x
                       + mishf(tpv.y + Psv.y + Pdv.y) * w2road.y
                       + mishf(tpv.z + Psv.z + Pdv.z) * w2road.z
                       + mishf(tpv.w + Psv.w + Pdv.w) * w2road.w;
            part += __shfl_xor_sync(0xffffffffu, part, 1);
            part += __shfl_xor_sync(0xffffffffu, part, 2);
            part += __shfl_xor_sync(0xffffffffu, part, 4);
            if (rc == 0) out[((size_t)(pair * 2 + bl)) * 397 + 113 + e] = part + b2_s[2];
        }
        // ---- robber heads: 4 tiles per warp-task, float4 cols ----
        for (int t = wid; t < nb * 5; t += 8) {
            int bl = (t >= 5) ? 1 : 0;
            int tg = t - 5 * bl;
            int tile = tg * 4 + sub;
            bool valid = tile < 19;
            int tix = valid ? tile : 0;
            float4 a = make_float4(0.f, 0.f, 0.f, 0.f);
            #pragma unroll
            for (int i = 0; i < 6; i++) {
                const float4 p = *(const float4*)(P_s + (bl * 54 + ti_s[tix * 6 + i]) * 100 + 64 + rc * 4);
                a.x += p.x; a.y += p.y; a.z += p.z; a.w += p.w;
            }
            float4 tpv = *(const float4*)(tpb + bl * 128 + 96 + rc * 4);
            float m0 = mishf(tpv.x + a.x * (1.f / 6.f));
            float m1 = mishf(tpv.y + a.y * (1.f / 6.f));
            float m2 = mishf(tpv.z + a.z * (1.f / 6.f));
            float m3 = mishf(tpv.w + a.w * (1.f / 6.f));
            #pragma unroll
            for (int o = 0; o < 5; o++) {
                float4 rv = *(const float4*)(rob2_s + o * 32 + rc * 4);
                float part = m0 * rv.x + m1 * rv.y + m2 * rv.z + m3 * rv.w;
                part += __shfl_xor_sync(0xffffffffu, part, 1);
                part += __shfl_xor_sync(0xffffffffu, part, 2);
                part += __shfl_xor_sync(0xffffffffu, part, 4);
                if (rc == 0 && valid)
                    out[((size_t)(pair * 2 + bl)) * 397 + 185 + tile * 5 + o] = part + b2_s[3 + o];
            }
        }
        // (no end barrier: next iteration's top barrier protects P_s/tproj)
    }
}

// ------------------------------ K3: BN + mish + gfc2, 8-row batched ------------------------------
__global__ __launch_bounds__(128) void k3(const float* __restrict__ gfc2_w,
                                          const float* __restrict__ gfc2_b,
                                          float* __restrict__ out, int B) {
    __shared__ __align__(16) float m8[80 * 8];
    __shared__ __align__(16) float Wg[80 * 122];
    __shared__ float bs[122];
    __shared__ float sc[80], sh[80];
    int tid = threadIdx.x;
    for (int i = tid; i < 80 * 122; i += 128) {
        int k = i / 122, t = i % 122;
        int r = (t < 5) ? t : (275 + t);
        Wg[i] = gfc2_w[r * 80 + k];
    }
    if (tid < 122) { int r = (tid < 5) ? tid : (275 + tid); bs[tid] = gfc2_b[r]; }
    if (tid < 80) { sc[tid] = d_bnscale[tid]; sh[tid] = d_bnshift[tid]; }
    __syncthreads();
    int nq = (B + 7) >> 3;
    for (int qb = blockIdx.x; qb < nq; qb += gridDim.x) {
        if (tid < 80) {
            #pragma unroll
            for (int rb = 0; rb < 8; rb++) {
                int b = qb * 8 + rb;
                float v = (b < B) ? d_h[(size_t)b * 80 + tid] : 0.f;
                m8[tid * 8 + rb] = mishf(v * sc[tid] + sh[tid]);
            }
        }
        __syncthreads();
        if (tid < 122) {
            float a[8];
            #pragma unroll
            for (int rb = 0; rb < 8; rb++) a[rb] = bs[tid];
            for (int k = 0; k < 80; k++) {
                float4 mA = *(const float4*)(m8 + k * 8);
                float4 mB = *(const float4*)(m8 + k * 8 + 4);
                float w = Wg[k * 122 + tid];
                a[0] += mA.x * w; a[1] += mA.y * w; a[2] += mA.z * w; a[3] += mA.w * w;
                a[4] += mB.x * w; a[5] += mB.y * w; a[6] += mB.z * w; a[7] += mB.w * w;
            }
            int col = (tid < 5) ? tid : (275 + tid);
            #pragma unroll
            for (int rb = 0; rb < 8; rb++) {
                int b = qb * 8 + rb;
                if (b < B) out[(size_t)b * 397 + col] = a[rb];
            }
        }
        __syncthreads();
    }
}

// ------------------------------ launch ------------------------------
extern "C" void kernel_launch(void* const* d_in, const int* in_sizes, int n_in,
                              void* d_out, int out_size) {
    const float* trunk      = (const float*)d_in[0];
    const float* node_emb   = (const float*)d_in[1];
    const int*   road_pairs = (const int*)d_in[2];
    const int*   tile_nodes = (const int*)d_in[3];
    const float* ln_t_w = (const float*)d_in[4];
    const float* ln_t_b = (const float*)d_in[5];
    const float* ln_n_w = (const float*)d_in[6];
    const float* ln_n_b = (const float*)d_in[7];
    const float* gfc1_w = (const float*)d_in[8];
    const float* gfc1_b = (const float*)d_in[9];
    const float* bn_w   = (const float*)d_in[10];
    const float* bn_b   = (const float*)d_in[11];
    const float* gfc2_w = (const float*)d_in[12];
    const float* gfc2_b = (const float*)d_in[13];
    const float* sett1_w = (const float*)d_in[14];
    const float* sett1_b = (const float*)d_in[15];
    const float* sett2_w = (const float*)d_in[16];
    const float* sett2_b = (const float*)d_in[17];
    const float* city1_w = (const float*)d_in[18];
    const float* city1_b = (const float*)d_in[19];
    const float* city2_w = (const float*)d_in[20];
    const float* city2_b = (const float*)d_in[21];
    const float* road1_w = (const float*)d_in[22];
    const float* road1_b = (const float*)d_in[23];
    const float* road2_w = (const float*)d_in[24];
    const float* road2_b = (const float*)d_in[25];
    const float* rob1_w = (const float*)d_in[26];
    const float* rob1_b = (const float*)d_in[27];
    const float* rob2_w = (const float*)d_in[28];
    const float* rob2_b = (const float*)d_in[29];

    int B = in_sizes[0] / 80;
    if (B > BMAX) B = BMAX;
    float* out = (float*)d_out;
    int nblk1 = (B + 127) / 128;

    cudaFuncSetAttribute(k1, cudaFuncAttributeMaxDynamicSharedMemorySize, K1_SMEM);
    cudaFuncSetAttribute(k2, cudaFuncAttributeMaxDynamicSharedMemorySize, SM_TOTAL);

    k_prep<<<(208 * 80 + 255) / 256, 256>>>(sett1_w, city1_w, road1_w, rob1_w, gfc1_w,
                                            sett1_b, city1_b, road1_b, rob1_b, gfc1_b);
    k1<<<nblk1, 512, K1_SMEM>>>(trunk, ln_t_w, ln_t_b, B);
    k_bn<<<1, 80>>>(bn_w, bn_b, B, nblk1);
    k2<<<K2_GRID, 256, SM_TOTAL>>>(node_emb, ln_n_w, ln_n_b, road_pairs, tile_nodes,
                                   sett2_w, sett2_b, city2_w, city2_b,
                                   road2_w, road2_b, rob2_w, rob2_b, out, B);
    k3<<<K3_GRID, 128>>>(gfc2_w, gfc2_b, out, B);
}

// round 14
// speedup vs baseline: 1.3424x; 1.0689x over previous
#include <cuda_runtime.h>
#include <cuda_fp16.h>
#include <cstdint>
#include <cstddef>

// ---------------------------------------------------------------------------
// SmallSpatialPolicyHead — R13 + k2: 2-term compensated MMA (Ah*Wh + Ah*Wl;
// Al*Wh dropped — error budget ~1.4e-4 << 1e-3). Deletes AL tile, lo-half of
// LN-B, 60 MMAs and 6 LDSM per warp-iter.
// ---------------------------------------------------------------------------

#define BMAX 16384
#define K2_GRID 296
#define K3_GRID 592

__device__ float d_tb[208];
__device__ __half d_Wh[160 * 48];    // k2 node proj hi  [n][k]
__device__ __half d_Wl[160 * 48];    // k2 node proj lo
__device__ __half d_Wth[208 * 80];   // k1 trunk proj hi [o][k]
__device__ __half d_Wtl[208 * 80];   // k1 trunk proj lo
__device__ float d_tproj[(size_t)BMAX * 128];
__device__ float d_h[(size_t)BMAX * 80];
__device__ float d_partial[296 * 160];
__device__ float d_bnscale[80];
__device__ float d_bnshift[80];

// ---- k2 smem byte offsets ----
#define SM_XP    0             // P_s 108x100 f = 43200
#define SM_AH    43200         // 128x56 fp16 = 14336
#define SM_WH    57536         // 160x56 fp16 = 17920
#define SM_WL    75456
#define WLOFF    17920
#define SM_TPROJ 93376         // 2 x 256 f (double buffer)
#define SM_W2    95424         // 96 f
#define SM_ROB2  95808         // 160 f
#define SM_B2    96448         // 8 f
#define SM_LNW   96480         // 48 f
#define SM_LNB   96672         // 48 f
#define SM_MU    96864         // 2 x 110 f (double buffer, 448B each)
#define SM_IS    97760         // 2 x 110 f
#define SM_RP    98656         // 144 i
#define SM_TI    99232         // 114 i
#define SM_TOTAL 99688

// ---- k1 smem byte offsets ----
#define X1_XS    0             // 128x84 f = 43008 (reused as hs)
#define X1_AH    43008         // 128x88 fp16 = 22528
#define X1_AL    65536
#define X1_WH    88064         // 208x88 fp16 = 36608
#define X1_WL    124672
#define W1OFF    36608
#define X1_TB    161280        // 208 f
#define X1_LNW   162112        // 80 f
#define X1_LNB   162432        // 80 f
#define K1_SMEM  162752

__device__ __forceinline__ uint32_t smem_u32(const void* p) {
    uint32_t a;
    asm("{ .reg .u64 t; cvta.to.shared.u64 t, %1; cvt.u32.u64 %0, t; }" : "=r"(a) : "l"(p));
    return a;
}
__device__ __forceinline__ void cp16(uint32_t dst, const void* src) {
    asm volatile("cp.async.cg.shared.global [%0], [%1], 16;" :: "r"(dst), "l"(src));
}
#define CP_COMMIT() asm volatile("cp.async.commit_group;" ::: "memory")
#define CP_WAIT_ALL() asm volatile("cp.async.wait_group 0;" ::: "memory")
#define CP_COMMIT_WAIT() do { CP_COMMIT(); CP_WAIT_ALL(); } while (0)

#define LDSM_X4(r0,r1,r2,r3,addr) \
    asm volatile("ldmatrix.sync.aligned.m8n8.x4.shared.b16 {%0,%1,%2,%3}, [%4];" \
        : "=r"(r0),"=r"(r1),"=r"(r2),"=r"(r3) : "r"(addr))
#define LDSM_X2(r0,r1,addr) \
    asm volatile("ldmatrix.sync.aligned.m8n8.x2.shared.b16 {%0,%1}, [%2];" \
        : "=r"(r0),"=r"(r1) : "r"(addr))
#define LDSM_X4_NV(r0,r1,r2,r3,addr) \
    asm("ldmatrix.sync.aligned.m8n8.x4.shared.b16 {%0,%1,%2,%3}, [%4];" \
        : "=r"(r0),"=r"(r1),"=r"(r2),"=r"(r3) : "r"(addr))

__device__ __forceinline__ void mma16816(float* d, const uint32_t* a, uint32_t b0, uint32_t b1) {
    asm volatile(
        "mma.sync.aligned.m16n8k16.row.col.f32.f16.f16.f32 "
        "{%0,%1,%2,%3},{%4,%5,%6,%7},{%8,%9},{%0,%1,%2,%3};"
        : "+f"(d[0]), "+f"(d[1]), "+f"(d[2]), "+f"(d[3])
        : "r"(a[0]), "r"(a[1]), "r"(a[2]), "r"(a[3]), "r"(b0), "r"(b1));
}

__device__ __forceinline__ float mishf(float x) {
    float u = __expf(fminf(x, 15.f));
    float d = __fmaf_rn(u, u + 2.f, 2.f);
    return x - __fdividef(2.f * x, d);
}
__device__ __forceinline__ float warp_sum(float v) {
    #pragma unroll
    for (int o = 16; o; o >>= 1) v += __shfl_xor_sync(0xffffffffu, v, o);
    return v;
}

// ------------------------------ prep ------------------------------
__global__ void k_prep(const float* __restrict__ sett1_w, const float* __restrict__ city1_w,
                       const float* __restrict__ road1_w, const float* __restrict__ rob1_w,
                       const float* __restrict__ gfc1_w,
                       const float* __restrict__ sett1_b, const float* __restrict__ city1_b,
                       const float* __restrict__ road1_b, const float* __restrict__ rob1_b,
                       const float* __restrict__ gfc1_b) {
    int i = blockIdx.x * blockDim.x + threadIdx.x;
    if (i < 160 * 48) {
        int j = i / 48, k = i % 48;
        float v;
        if (j < 32)       v = sett1_w[j * 128 + 80 + k];
        else if (j < 64)  v = city1_w[(j - 32) * 128 + 80 + k];
        else if (j < 96)  v = road1_w[(j - 64) * 176 + 80 + k];
        else if (j < 128) v = road1_w[(j - 96) * 176 + 128 + k];
        else              v = rob1_w[(j - 128) * 128 + 80 + k];
        __half h = __float2half(v);
        d_Wh[i] = h;
        d_Wl[i] = __float2half(v - __half2float(h));
    }
    if (i < 208 * 80) {
        int o = i / 80, k = i % 80;
        float v;
        if (o < 32)       v = sett1_w[o * 128 + k];
        else if (o < 64)  v = city1_w[(o - 32) * 128 + k];
        else if (o < 96)  v = road1_w[(o - 64) * 176 + k];
        else if (o < 128) v = rob1_w[(o - 96) * 128 + k];
        else              v = gfc1_w[(o - 128) * 80 + k];
        __half h = __float2half(v);
        d_Wth[i] = h;
        d_Wtl[i] = __float2half(v - __half2float(h));
    }
    if (i < 208) {
        float v;
        if (i < 32)       v = sett1_b[i];
        else if (i < 64)  v = city1_b[i - 32];
        else if (i < 96)  v = road1_b[i - 64];
        else if (i < 128) v = rob1_b[i - 96];
        else              v = gfc1_b[i - 128];
        d_tb[i] = v;
    }
}

// ------------------------------ K1: HMMA trunk kernel (unchanged, proven) ------------------------------
__global__ __launch_bounds__(512, 1) void k1(const float* __restrict__ trunk,
                                             const float* __restrict__ ln_t_w,
                                             const float* __restrict__ ln_t_b, int B) {
    extern __shared__ char smem[];
    const uint32_t sbase = smem_u32(smem);
    const int tid = threadIdx.x, wid = tid >> 5, lane = tid & 31;

    float* xs  = (float*)(smem + X1_XS);
    float* hs  = (float*)(smem + X1_XS);
    float* tb_s = (float*)(smem + X1_TB);
    float* lnw = (float*)(smem + X1_LNW);
    float* lnb = (float*)(smem + X1_LNB);

    for (int i = tid; i < 208 * 80; i += 512) {
        int o = i / 80, k = i % 80;
        *(__half*)(smem + X1_WH + (o * 88 + k) * 2) = d_Wth[i];
        *(__half*)(smem + X1_WL + (o * 88 + k) * 2) = d_Wtl[i];
    }
    for (int i = tid; i < 208; i += 512) tb_s[i] = d_tb[i];
    if (tid < 80) { lnw[tid] = ln_t_w[tid]; lnb[tid] = ln_t_b[tid]; }

    const int rows_valid = min(128, B - (int)blockIdx.x * 128);

    {
        const float4* tr4 = (const float4*)trunk;
        size_t base4 = (size_t)blockIdx.x * 2560;
        #pragma unroll
        for (int q = 0; q < 5; q++) {
            int il = tid + q * 512;
            int row = il / 20, c = il % 20;
            if (row < rows_valid)
                cp16(sbase + X1_XS + (uint32_t)((row * 84 + 4 * c) * 4), tr4 + base4 + il);
        }
        CP_COMMIT_WAIT();
    }
    __syncthreads();

    if (tid < 256) {
        const int r = tid >> 1, h = tid & 1;
        float4 v[10];
        if (r < rows_valid) {
            const float4* xr = (const float4*)(xs + r * 84 + h * 40);
            #pragma unroll
            for (int j = 0; j < 10; j++) v[j] = xr[j];
        } else {
            #pragma unroll
            for (int j = 0; j < 10; j++) v[j] = make_float4(0.f, 0.f, 0.f, 0.f);
        }
        float s = 0.f, q = 0.f;
        #pragma unroll
        for (int j = 0; j < 10; j++) {
            s += v[j].x + v[j].y + v[j].z + v[j].w;
            q += v[j].x * v[j].x + v[j].y * v[j].y + v[j].z * v[j].z + v[j].w * v[j].w;
        }
        s += __shfl_xor_sync(0xffffffffu, s, 1);
        q += __shfl_xor_sync(0xffffffffu, q, 1);
        float mu = s * (1.f / 80.f);
        float is = rsqrtf(q * (1.f / 80.f) - mu * mu + 1e-5f);
        char* dh = smem + X1_AH + (r * 88 + h * 40) * 2;
        char* dl = dh + (X1_AL - X1_AH);
        const float4* lw4 = (const float4*)(lnw + h * 40);
        const float4* lb4 = (const float4*)(lnb + h * 40);
        #pragma unroll
        for (int j = 0; j < 10; j++) {
            float4 w = lw4[j], b = lb4[j];
            float a0 = (v[j].x - mu) * is * w.x + b.x;
            float a1 = (v[j].y - mu) * is * w.y + b.y;
            float a2 = (v[j].z - mu) * is * w.z + b.z;
            float a3 = (v[j].w - mu) * is * w.w + b.w;
            if (r >= rows_valid) { a0 = a1 = a2 = a3 = 0.f; }
            __half2 h01 = __floats2half2_rn(a0, a1), h23 = __floats2half2_rn(a2, a3);
            __half2 l01 = __floats2half2_rn(a0 - __low2float(h01), a1 - __high2float(h01));
            __half2 l23 = __floats2half2_rn(a2 - __low2float(h23), a3 - __high2float(h23));
            uint2 uh; uh.x = *(uint32_t*)&h01; uh.y = *(uint32_t*)&h23;
            uint2 ul; ul.x = *(uint32_t*)&l01; ul.y = *(uint32_t*)&l23;
            *(uint2*)(dh + j * 8) = uh;
            *(uint2*)(dl + j * 8) = ul;
        }
    }
    __syncthreads();

    {
        const int mt = wid & 7, nh = wid >> 3;
        const int g = lane >> 2, k0 = (lane & 3) * 2;
        const uint32_t abase = sbase + X1_AH +
            (uint32_t)((mt * 16 + (lane & 15)) * 176 + (lane >> 4) * 16);
        uint32_t ah[5][4];
        #pragma unroll
        for (int ks = 0; ks < 5; ks++)
            LDSM_X4(ah[ks][0], ah[ks][1], ah[ks][2], ah[ks][3], abase + ks * 32);

        uint32_t wx4 = sbase + X1_WH +
            (uint32_t)((lane & 7) * 176 + (lane >> 3) * 16) + (uint32_t)(nh * 13 * 1408);
        uint32_t wx2 = sbase + X1_WH +
            (uint32_t)((lane & 7) * 176 + ((lane >> 3) & 1) * 16 + 128) + (uint32_t)(nh * 13 * 1408);

        #pragma unroll
        for (int ni = 0; ni < 13; ni++) {
            const int nt = nh * 13 + ni;
            uint32_t bhA[4], bhB[4], bh2[2], blA[4], blB[4], bl2[2];
            LDSM_X4(bhA[0], bhA[1], bhA[2], bhA[3], wx4);
            LDSM_X4(bhB[0], bhB[1], bhB[2], bhB[3], wx4 + 64);
            LDSM_X2(bh2[0], bh2[1], wx2);
            LDSM_X4(blA[0], blA[1], blA[2], blA[3], wx4 + W1OFF);
            LDSM_X4(blB[0], blB[1], blB[2], blB[3], wx4 + 64 + W1OFF);
            LDSM_X2(bl2[0], bl2[1], wx2 + W1OFF);

            float acc[4] = {0.f, 0.f, 0.f, 0.f};
            mma16816(acc, ah[0], bhA[0], bhA[1]);
            mma16816(acc, ah[1], bhA[2], bhA[3]);
            mma16816(acc, ah[2], bhB[0], bhB[1]);
            mma16816(acc, ah[3], bhB[2], bhB[3]);
            mma16816(acc, ah[4], bh2[0], bh2[1]);
            mma16816(acc, ah[0], blA[0], blA[1]);
            mma16816(acc, ah[1], blA[2], blA[3]);
            mma16816(acc, ah[2], blB[0], blB[1]);
            mma16816(acc, ah[3], blB[2], blB[3]);
            mma16816(acc, ah[4], bl2[0], bl2[1]);
            {
                uint32_t al[4];
                const uint32_t albase = abase + (X1_AL - X1_AH);
                LDSM_X4(al[0], al[1], al[2], al[3], albase);
                mma16816(acc, al, bhA[0], bhA[1]);
                LDSM_X4(al[0], al[1], al[2], al[3], albase + 32);
                mma16816(acc, al, bhA[2], bhA[3]);
                LDSM_X4(al[0], al[1], al[2], al[3], albase + 64);
                mma16816(acc, al, bhB[0], bhB[1]);
                LDSM_X4(al[0], al[1], al[2], al[3], albase + 96);
                mma16816(acc, al, bhB[2], bhB[3]);
                LDSM_X4(al[0], al[1], al[2], al[3], albase + 128);
                mma16816(acc, al, bh2[0], bh2[1]);
            }
            wx4 += 1408; wx2 += 1408;

            const int col = nt * 8 + k0;
            const int row0 = mt * 16 + g, row1 = row0 + 8;
            if (col < 128) {
                float b0 = tb_s[col], b1 = tb_s[col + 1];
                if (row0 < rows_valid) {
                    size_t o = (size_t)((size_t)blockIdx.x * 128 + row0) * 128 + col;
                    d_tproj[o] = acc[0] + b0; d_tproj[o + 1] = acc[1] + b1;
                }
                if (row1 < rows_valid) {
                    size_t o = (size_t)((size_t)blockIdx.x * 128 + row1) * 128 + col;
                    d_tproj[o] = acc[2] + b0; d_tproj[o + 1] = acc[3] + b1;
                }
            } else {
                const int ch = col - 128;
                hs[row0 * 84 + ch] = acc[0]; hs[row0 * 84 + ch + 1] = acc[1];
                hs[row1 * 84 + ch] = acc[2]; hs[row1 * 84 + ch + 1] = acc[3];
                if (row0 < rows_valid) {
                    size_t o = (size_t)((size_t)blockIdx.x * 128 + row0) * 80 + ch;
                    d_h[o] = acc[0]; d_h[o + 1] = acc[1];
                }
                if (row1 < rows_valid) {
                    size_t o = (size_t)((size_t)blockIdx.x * 128 + row1) * 80 + ch;
                    d_h[o] = acc[2]; d_h[o + 1] = acc[3];
                }
            }
        }
    }
    __syncthreads();

    if (tid < 80) {
        float s1 = 0.f, s2 = 0.f;
        for (int r = 0; r < rows_valid; r++) {
            float v = hs[r * 84 + tid];
            s1 += v; s2 += v * v;
        }
        d_partial[blockIdx.x * 160 + tid] = s1;
        d_partial[blockIdx.x * 160 + 80 + tid] = s2;
    }
}

// ------------------------------ BN finalize ------------------------------
__global__ void k_bn(const float* __restrict__ bn_w, const float* __restrict__ bn_b,
                     int B, int nblk) {
    int t = threadIdx.x;
    if (t >= 80) return;
    float S1 = 0.f, S2 = 0.f;
    for (int blk = 0; blk < nblk; blk++) {
        S1 += d_partial[blk * 160 + t];
        S2 += d_partial[blk * 160 + 80 + t];
    }
    float invB = 1.f / (float)B;
    float mu = S1 * invB;
    float var = S2 * invB - mu * mu;
    float sc = bn_w[t] * rsqrtf(var + 1e-5f);
    d_bnscale[t] = sc;
    d_bnshift[t] = bn_b[t] - mu * sc;
}

// ------------------------------ K2: HMMA fused node kernel, pipelined ------------------------------
__global__ __launch_bounds__(256, 2) void k2(const float* __restrict__ node_emb,
                                             const float* __restrict__ ln_n_w,
                                             const float* __restrict__ ln_n_b,
                                             const int* __restrict__ road_pairs,
                                             const int* __restrict__ tile_nodes,
                                             const float* __restrict__ sett2_w, const float* __restrict__ sett2_b,
                                             const float* __restrict__ city2_w, const float* __restrict__ city2_b,
                                             const float* __restrict__ road2_w, const float* __restrict__ road2_b,
                                             const float* __restrict__ rob2_w, const float* __restrict__ rob2_b,
                                             float* __restrict__ out, int B) {
    extern __shared__ char smem[];
    const uint32_t sbase = smem_u32(smem);
    const int tid = threadIdx.x, wid = tid >> 5, lane = tid & 31;

    float* P_s     = (float*)(smem + SM_XP);   // rows x 100
    float* w2_s    = (float*)(smem + SM_W2);
    float* rob2_s  = (float*)(smem + SM_ROB2);
    float* b2_s    = (float*)(smem + SM_B2);
    float* lnw     = (float*)(smem + SM_LNW);
    float* lnb     = (float*)(smem + SM_LNB);
    int*   rp_s    = (int*)(smem + SM_RP);
    int*   ti_s    = (int*)(smem + SM_TI);

    for (int i = tid; i < 160 * 48; i += 256) {
        int n = i / 48, k = i % 48;
        *(__half*)(smem + SM_WH + (n * 56 + k) * 2) = d_Wh[i];
        *(__half*)(smem + SM_WL + (n * 56 + k) * 2) = d_Wl[i];
    }
    if (tid < 48) { lnw[tid] = ln_n_w[tid]; lnb[tid] = ln_n_b[tid]; }
    if (tid < 32) { w2_s[tid] = sett2_w[tid]; w2_s[32 + tid] = city2_w[tid]; w2_s[64 + tid] = road2_w[tid]; }
    if (tid < 160) rob2_s[tid] = rob2_w[tid];
    if (tid == 0) { b2_s[0] = sett2_b[0]; b2_s[1] = city2_b[0]; b2_s[2] = road2_b[0]; }
    if (tid < 5) b2_s[3 + tid] = rob2_b[tid];
    if (tid < 144) rp_s[tid] = road_pairs[tid];
    if (tid < 114) ti_s[tid] = tile_nodes[tid];

    const int g = lane >> 2;
    const int k0 = (lane & 3) * 2;
    const int mrow = (wid & 3) * 32;
    const int hd = wid >> 2;              // 0 = sett group, 1 = city group

    int rown[4]; int tpoff[4];
    #pragma unroll
    for (int s = 0; s < 4; s++) {
        rown[s] = mrow + 16 * (s >> 1) + 8 * (s & 1) + g;
        tpoff[s] = (rown[s] >= 54) ? 128 : 0;
    }

    const uint32_t wx4base0 = sbase + SM_WH +
        (uint32_t)((lane & 7) * 112 + (lane >> 3) * 16);
    const uint32_t wpbase0 = sbase + SM_WH +
        (uint32_t)((lane & 7) * 112 + ((lane >> 3) & 1) * 16 + 64 + ((lane >> 4) & 1) * 896);
    const uint32_t abase0 = sbase + SM_AH +
        (uint32_t)((mrow + (lane & 15)) * 112 + (lane >> 4) * 16);

    const long npairs = ((long)B + 1) / 2;
    const size_t totp4 = (size_t)B * 32;
    const float4* tp4 = (const float4*)d_tproj;

    // ---- prologue: LN-A + tproj prefetch for first pair into buf 0 ----
    long pair = blockIdx.x;
    int buf = 0;
    if (pair < npairs) {
        const int nr = (int)((long)B * 54 - pair * 108 >= 108 ? 108 : (long)B * 54 - pair * 108);
        if (tid < nr) {
            const float4* xr = (const float4*)(node_emb + ((size_t)pair * 108 + tid) * 48);
            float s = 0.f, q = 0.f;
            #pragma unroll
            for (int j = 0; j < 12; j++) {
                float4 v = xr[j];
                s += v.x + v.y + v.z + v.w;
                q += v.x * v.x + v.y * v.y + v.z * v.z + v.w * v.w;
            }
            float mu = s * (1.f / 48.f);
            ((float*)(smem + SM_MU))[tid] = mu;
            ((float*)(smem + SM_IS))[tid] = rsqrtf(q * (1.f / 48.f) - mu * mu + 1e-5f);
        }
        if (tid < 64) {
            size_t t4 = (size_t)pair * 64 + tid;
            if (t4 < totp4) cp16(sbase + SM_TPROJ + tid * 16, tp4 + t4);
        }
        CP_COMMIT();
    }
    __syncthreads();   // order init smem writes before hoisted invariant loads

    // hoisted loop-invariant head weights
    const int rc = lane & 7;
    const float4 w2road = *(const float4*)(w2_s + 64 + rc * 4);
    float2 w2sc[2][2];
    #pragma unroll
    for (int pi = 0; pi < 2; pi++)
        #pragma unroll
        for (int sub = 0; sub < 2; sub++)
            w2sc[pi][sub] = *(const float2*)(w2_s + (4 * hd + 2 * pi + sub) * 8 + k0);

    for (; pair < npairs; pair += gridDim.x, buf ^= 1) {
        const float* mu_s = (const float*)(smem + SM_MU + buf * 448);
        const float* is_s = (const float*)(smem + SM_IS + buf * 448);
        const float* tpb  = (const float*)(smem + SM_TPROJ + buf * 1024);

        CP_WAIT_ALL();
        __syncthreads();

        const int nrows = (int)((long)B * 54 - pair * 108 >= 108 ? 108 : (long)B * 54 - pair * 108);

        // ---- LN phase B: 8 cols per item, hi only (uint4 store) ----
        for (int i = tid; i < 648; i += 256) {
            int r = i / 6, c8 = (i % 6) * 8;
            if (r < nrows) {
                const float* src = node_emb + ((size_t)pair * 108 + r) * 48 + c8;
                float4 va = *(const float4*)(src);
                float4 vb = *(const float4*)(src + 4);
                float mu = mu_s[r], is = is_s[r];
                float a0 = (va.x - mu) * is * lnw[c8]     + lnb[c8];
                float a1 = (va.y - mu) * is * lnw[c8 + 1] + lnb[c8 + 1];
                float a2 = (va.z - mu) * is * lnw[c8 + 2] + lnb[c8 + 2];
                float a3 = (va.w - mu) * is * lnw[c8 + 3] + lnb[c8 + 3];
                float a4 = (vb.x - mu) * is * lnw[c8 + 4] + lnb[c8 + 4];
                float a5 = (vb.y - mu) * is * lnw[c8 + 5] + lnb[c8 + 5];
                float a6 = (vb.z - mu) * is * lnw[c8 + 6] + lnb[c8 + 6];
                float a7 = (vb.w - mu) * is * lnw[c8 + 7] + lnb[c8 + 7];
                __half2 h01 = __floats2half2_rn(a0, a1), h23 = __floats2half2_rn(a2, a3);
                __half2 h45 = __floats2half2_rn(a4, a5), h67 = __floats2half2_rn(a6, a7);
                uint4 uh; uh.x = *(uint32_t*)&h01; uh.y = *(uint32_t*)&h23;
                uh.z = *(uint32_t*)&h45; uh.w = *(uint32_t*)&h67;
                *(uint4*)(smem + SM_AH + (r * 56 + c8) * 2) = uh;
            }
        }
        __syncthreads();

        // ---- A fragments via ldmatrix (hi only) ----
        uint32_t afh[2][3][4];
        #pragma unroll
        for (int t = 0; t < 2; t++) {
            #pragma unroll
            for (int ks = 0; ks < 3; ks++) {
                uint32_t ad = abase0 + (uint32_t)(t * 1792 + ks * 32);
                LDSM_X4(afh[t][ks][0], afh[t][ks][1], afh[t][ks][2], afh[t][ks][3], ad);
            }
        }

        // ---- prefetch next pair: LN-A + tproj into buf^1 (hides under MMA) ----
        {
            long nxt = pair + gridDim.x;
            if (nxt < npairs) {
                const int nr = (int)((long)B * 54 - nxt * 108 >= 108 ? 108 : (long)B * 54 - nxt * 108);
                if (tid < nr) {
                    const float4* xr = (const float4*)(node_emb + ((size_t)nxt * 108 + tid) * 48);
                    float s = 0.f, q = 0.f;
                    #pragma unroll
                    for (int j = 0; j < 12; j++) {
                        float4 v = xr[j];
                        s += v.x + v.y + v.z + v.w;
                        q += v.x * v.x + v.y * v.y + v.z * v.z + v.w * v.w;
                    }
                    float mu = s * (1.f / 48.f);
                    ((float*)(smem + SM_MU + (buf ^ 1) * 448))[tid] = mu;
                    ((float*)(smem + SM_IS + (buf ^ 1) * 448))[tid] =
                        rsqrtf(q * (1.f / 48.f) - mu * mu + 1e-5f);
                }
                if (tid < 64) {
                    size_t t4 = (size_t)nxt * 64 + tid;
                    if (t4 < totp4)
                        cp16(sbase + SM_TPROJ + (buf ^ 1) * 1024 + tid * 16, tp4 + t4);
                }
                CP_COMMIT();
            }
        }

        float sacc[4] = {0.f, 0.f, 0.f, 0.f};

        // nt pairs: hd=0 -> (0,1),(2,3),(8,9),(10,11),(12,13);
        //           hd=1 -> (4,5),(6,7),(14,15),(16,17),(18,19)
        #pragma unroll
        for (int pi = 0; pi < 5; pi++) {
            const int ntA = (pi < 2) ? (4 * hd + 2 * pi) : (8 + 6 * hd + 2 * (pi - 2));
            uint32_t c2h[4], c2l[4];
            LDSM_X4_NV(c2h[0], c2h[1], c2h[2], c2h[3], wpbase0 + ntA * 896);
            LDSM_X4_NV(c2l[0], c2l[1], c2l[2], c2l[3], wpbase0 + ntA * 896 + WLOFF);

            #pragma unroll
            for (int sub = 0; sub < 2; sub++) {
                const int nt = ntA + sub;
                uint32_t bh[4], bl[4];
                LDSM_X4_NV(bh[0], bh[1], bh[2], bh[3], wx4base0 + nt * 896);
                LDSM_X4_NV(bl[0], bl[1], bl[2], bl[3], wx4base0 + nt * 896 + WLOFF);
                const uint32_t bh2a = c2h[2 * sub], bh2b = c2h[2 * sub + 1];
                const uint32_t bl2a = c2l[2 * sub], bl2b = c2l[2 * sub + 1];

                float acc[2][4] = {{0.f, 0.f, 0.f, 0.f}, {0.f, 0.f, 0.f, 0.f}};
                #pragma unroll
                for (int t = 0; t < 2; t++) {
                    mma16816(acc[t], afh[t][0], bh[0], bh[1]);
                    mma16816(acc[t], afh[t][1], bh[2], bh[3]);
                    mma16816(acc[t], afh[t][2], bh2a, bh2b);
                    mma16816(acc[t], afh[t][0], bl[0], bl[1]);
                    mma16816(acc[t], afh[t][1], bl[2], bl[3]);
                    mma16816(acc[t], afh[t][2], bl2a, bl2b);
                }
                const int col = nt * 8 + k0;
                if (pi < 2) {
                    float w2a = w2sc[pi][sub].x, w2b = w2sc[pi][sub].y;
                    #pragma unroll
                    for (int s = 0; s < 4; s++) {
                        float2 tpv = *(const float2*)(tpb + tpoff[s] + col);
                        float v0 = acc[s >> 1][2 * (s & 1)];
                        float v1 = acc[s >> 1][2 * (s & 1) + 1];
                        sacc[s] += mishf(v0 + tpv.x) * w2a + mishf(v1 + tpv.y) * w2b;
                    }
                } else {
                    #pragma unroll
                    for (int s = 0; s < 4; s++) {
                        int r = rown[s];
                        if (r < 108)
                            *(float2*)(P_s + r * 100 + (col - 64)) =
                                make_float2(acc[s >> 1][2 * (s & 1)], acc[s >> 1][2 * (s & 1) + 1]);
                    }
                }
            }
        }

        // sett/city finalize
        {
            #pragma unroll
            for (int s = 0; s < 4; s++) {
                sacc[s] += __shfl_xor_sync(0xffffffffu, sacc[s], 1);
                sacc[s] += __shfl_xor_sync(0xffffffffu, sacc[s], 2);
            }
            if ((lane & 3) == 0) {
                #pragma unroll
                for (int s = 0; s < 4; s++) {
                    int r = rown[s];
                    if (r < nrows) {
                        int bl = (r >= 54) ? 1 : 0;
                        int n = r - 54 * bl;
                        out[((size_t)(pair * 2 + bl)) * 397 + 5 + 54 * hd + n] = sacc[s] + b2_s[hd];
                    }
                }
            }
        }
        __syncthreads();

        const int nb = (nrows > 54) ? 2 : 1;
        const int sub = lane >> 3;
        // ---- road heads: 4 edges per warp-task, float4 cols ----
        for (int t = wid; t < nb * 18; t += 8) {
            int bl = (t >= 18) ? 1 : 0;
            int tg = t - 18 * bl;
            int e = tg * 4 + sub;
            int sN = rp_s[2 * e], dN = rp_s[2 * e + 1];
            float4 tpv = *(const float4*)(tpb + bl * 128 + 64 + rc * 4);
            float4 Psv = *(const float4*)(P_s + (bl * 54 + sN) * 100 + rc * 4);
            float4 Pdv = *(const float4*)(P_s + (bl * 54 + dN) * 100 + 32 + rc * 4);
            float part = mishf(tpv.x + Psv.x + Pdv.x) * w2road.x
                       + mishf(tpv.y + Psv.y + Pdv.y) * w2road.y
                       + mishf(tpv.z + Psv.z + Pdv.z) * w2road.z
                       + mishf(tpv.w + Psv.w + Pdv.w) * w2road.w;
            part += __shfl_xor_sync(0xffffffffu, part, 1);
            part += __shfl_xor_sync(0xffffffffu, part, 2);
            part += __shfl_xor_sync(0xffffffffu, part, 4);
            if (rc == 0) out[((size_t)(pair * 2 + bl)) * 397 + 113 + e] = part + b2_s[2];
        }
        // ---- robber heads: 4 tiles per warp-task, float4 cols ----
        for (int t = wid; t < nb * 5; t += 8) {
            int bl = (t >= 5) ? 1 : 0;
            int tg = t - 5 * bl;
            int tile = tg * 4 + sub;
            bool valid = tile < 19;
            int tix = valid ? tile : 0;
            float4 a = make_float4(0.f, 0.f, 0.f, 0.f);
            #pragma unroll
            for (int i = 0; i < 6; i++) {
                const float4 p = *(const float4*)(P_s + (bl * 54 + ti_s[tix * 6 + i]) * 100 + 64 + rc * 4);
                a.x += p.x; a.y += p.y; a.z += p.z; a.w += p.w;
            }
            float4 tpv = *(const float4*)(tpb + bl * 128 + 96 + rc * 4);
            float m0 = mishf(tpv.x + a.x * (1.f / 6.f));
            float m1 = mishf(tpv.y + a.y * (1.f / 6.f));
            float m2 = mishf(tpv.z + a.z * (1.f / 6.f));
            float m3 = mishf(tpv.w + a.w * (1.f / 6.f));
            #pragma unroll
            for (int o = 0; o < 5; o++) {
                float4 rv = *(const float4*)(rob2_s + o * 32 + rc * 4);
                float part = m0 * rv.x + m1 * rv.y + m2 * rv.z + m3 * rv.w;
                part += __shfl_xor_sync(0xffffffffu, part, 1);
                part += __shfl_xor_sync(0xffffffffu, part, 2);
                part += __shfl_xor_sync(0xffffffffu, part, 4);
                if (rc == 0 && valid)
                    out[((size_t)(pair * 2 + bl)) * 397 + 185 + tile * 5 + o] = part + b2_s[3 + o];
            }
        }
        // (no end barrier: next iteration's top barrier protects P_s/tproj)
    }
}

// ------------------------------ K3: BN + mish + gfc2, 8-row batched ------------------------------
__global__ __launch_bounds__(128) void k3(const float* __restrict__ gfc2_w,
                                          const float* __restrict__ gfc2_b,
                                          float* __restrict__ out, int B) {
    __shared__ __align__(16) float m8[80 * 8];
    __shared__ __align__(16) float Wg[80 * 122];
    __shared__ float bs[122];
    __shared__ float sc[80], sh[80];
    int tid = threadIdx.x;
    for (int i = tid; i < 80 * 122; i += 128) {
        int k = i / 122, t = i % 122;
        int r = (t < 5) ? t : (275 + t);
        Wg[i] = gfc2_w[r * 80 + k];
    }
    if (tid < 122) { int r = (tid < 5) ? tid : (275 + tid); bs[tid] = gfc2_b[r]; }
    if (tid < 80) { sc[tid] = d_bnscale[tid]; sh[tid] = d_bnshift[tid]; }
    __syncthreads();
    int nq = (B + 7) >> 3;
    for (int qb = blockIdx.x; qb < nq; qb += gridDim.x) {
        if (tid < 80) {
            #pragma unroll
            for (int rb = 0; rb < 8; rb++) {
                int b = qb * 8 + rb;
                float v = (b < B) ? d_h[(size_t)b * 80 + tid] : 0.f;
                m8[tid * 8 + rb] = mishf(v * sc[tid] + sh[tid]);
            }
        }
        __syncthreads();
        if (tid < 122) {
            float a[8];
            #pragma unroll
            for (int rb = 0; rb < 8; rb++) a[rb] = bs[tid];
            for (int k = 0; k < 80; k++) {
                float4 mA = *(const float4*)(m8 + k * 8);
                float4 mB = *(const float4*)(m8 + k * 8 + 4);
                float w = Wg[k * 122 + tid];
                a[0] += mA.x * w; a[1] += mA.y * w; a[2] += mA.z * w; a[3] += mA.w * w;
                a[4] += mB.x * w; a[5] += mB.y * w; a[6] += mB.z * w; a[7] += mB.w * w;
            }
            int col = (tid < 5) ? tid : (275 + tid);
            #pragma unroll
            for (int rb = 0; rb < 8; rb++) {
                int b = qb * 8 + rb;
                if (b < B) out[(size_t)b * 397 + col] = a[rb];
            }
        }
        __syncthreads();
    }
}

// ------------------------------ launch ------------------------------
extern "C" void kernel_launch(void* const* d_in, const int* in_sizes, int n_in,
                              void* d_out, int out_size) {
    const float* trunk      = (const float*)d_in[0];
    const float* node_emb   = (const float*)d_in[1];
    const int*   road_pairs = (const int*)d_in[2];
    const int*   tile_nodes = (const int*)d_in[3];
    const float* ln_t_w = (const float*)d_in[4];
    const float* ln_t_b = (const float*)d_in[5];
    const float* ln_n_w = (const float*)d_in[6];
    const float* ln_n_b = (const float*)d_in[7];
    const float* gfc1_w = (const float*)d_in[8];
    const float* gfc1_b = (const float*)d_in[9];
    const float* bn_w   = (const float*)d_in[10];
    const float* bn_b   = (const float*)d_in[11];
    const float* gfc2_w = (const float*)d_in[12];
    const float* gfc2_b = (const float*)d_in[13];
    const float* sett1_w = (const float*)d_in[14];
    const float* sett1_b = (const float*)d_in[15];
    const float* sett2_w = (const float*)d_in[16];
    const float* sett2_b = (const float*)d_in[17];
    const float* city1_w = (const float*)d_in[18];
    const float* city1_b = (const float*)d_in[19];
    const float* city2_w = (const float*)d_in[20];
    const float* city2_b = (const float*)d_in[21];
    const float* road1_w = (const float*)d_in[22];
    const float* road1_b = (const float*)d_in[23];
    const float* road2_w = (const float*)d_in[24];
    const float* road2_b = (const float*)d_in[25];
    const float* rob1_w = (const float*)d_in[26];
    const float* rob1_b = (const float*)d_in[27];
    const float* rob2_w = (const float*)d_in[28];
    const float* rob2_b = (const float*)d_in[29];

    int B = in_sizes[0] / 80;
    if (B > BMAX) B = BMAX;
    float* out = (float*)d_out;
    int nblk1 = (B + 127) / 128;

    cudaFuncSetAttribute(k1, cudaFuncAttributeMaxDynamicSharedMemorySize, K1_SMEM);
    cudaFuncSetAttribute(k2, cudaFuncAttributeMaxDynamicSharedMemorySize, SM_TOTAL);

    k_prep<<<(208 * 80 + 255) / 256, 256>>>(sett1_w, city1_w, road1_w, rob1_w, gfc1_w,
                                            sett1_b, city1_b, road1_b, rob1_b, gfc1_b);
    k1<<<nblk1, 512, K1_SMEM>>>(trunk, ln_t_w, ln_t_b, B);
    k_bn<<<1, 80>>>(bn_w, bn_b, B, nblk1);
    k2<<<K2_GRID, 256, SM_TOTAL>>>(node_emb, ln_n_w, ln_n_b, road_pairs, tile_nodes,
                                   sett2_w, sett2_b, city2_w, city2_b,
                                   road2_w, road2_b, rob2_w, rob2_b, out, B);
    k3<<<K3_GRID, 128>>>(gfc2_w, gfc2_b, out, B);
}

// round 15
// speedup vs baseline: 1.4716x; 1.0962x over previous
#include <cuda_runtime.h>
#include <cuda_fp16.h>
#include <cstdint>
#include <cstddef>

// ---------------------------------------------------------------------------
// SmallSpatialPolicyHead — R14 + k2: LN scale/bias folded into W' and tb at
// prep time; LN fused into the per-row prefetch which writes the fp16 A tile
// directly (double-buffered). Deletes LN-B phase, mu/is smem, one barrier/iter.
// ---------------------------------------------------------------------------

#define BMAX 16384
#define K2_GRID 296
#define K3_GRID 592

__device__ float d_tb[208];
__device__ __half d_Wh[160 * 48];    // k2 node proj hi  [n][k] (lnw-scaled)
__device__ __half d_Wl[160 * 48];    // k2 node proj lo
__device__ __half d_Wth[208 * 80];   // k1 trunk proj hi [o][k]
__device__ __half d_Wtl[208 * 80];   // k1 trunk proj lo
__device__ float d_tproj[(size_t)BMAX * 128];
__device__ float d_h[(size_t)BMAX * 80];
__device__ float d_partial[296 * 160];
__device__ float d_bnscale[80];
__device__ float d_bnshift[80];

// ---- k2 smem byte offsets ----
#define SM_XP    0             // P_s 108x100 f = 43200
#define SM_AH    43200         // 2 x (128x56 fp16 = 14336), double buffer
#define ABUF     14336
#define SM_WH    71872         // 160x56 fp16 = 17920
#define SM_WL    89792
#define WLOFF    17920
#define SM_TPROJ 107712        // 2 x 256 f (double buffer)
#define SM_W2    109760        // 96 f
#define SM_ROB2  110144        // 160 f
#define SM_B2    110784        // 8 f
#define SM_RP    110816        // 144 i
#define SM_TI    111392        // 114 i
#define SM_TOTAL 111848

// ---- k1 smem byte offsets ----
#define X1_XS    0             // 128x84 f = 43008 (reused as hs)
#define X1_AH    43008         // 128x88 fp16 = 22528
#define X1_AL    65536
#define X1_WH    88064         // 208x88 fp16 = 36608
#define X1_WL    124672
#define W1OFF    36608
#define X1_TB    161280        // 208 f
#define X1_LNW   162112        // 80 f
#define X1_LNB   162432        // 80 f
#define K1_SMEM  162752

__device__ __forceinline__ uint32_t smem_u32(const void* p) {
    uint32_t a;
    asm("{ .reg .u64 t; cvta.to.shared.u64 t, %1; cvt.u32.u64 %0, t; }" : "=r"(a) : "l"(p));
    return a;
}
__device__ __forceinline__ void cp16(uint32_t dst, const void* src) {
    asm volatile("cp.async.cg.shared.global [%0], [%1], 16;" :: "r"(dst), "l"(src));
}
#define CP_COMMIT() asm volatile("cp.async.commit_group;" ::: "memory")
#define CP_WAIT_ALL() asm volatile("cp.async.wait_group 0;" ::: "memory")
#define CP_COMMIT_WAIT() do { CP_COMMIT(); CP_WAIT_ALL(); } while (0)

#define LDSM_X4(r0,r1,r2,r3,addr) \
    asm volatile("ldmatrix.sync.aligned.m8n8.x4.shared.b16 {%0,%1,%2,%3}, [%4];" \
        : "=r"(r0),"=r"(r1),"=r"(r2),"=r"(r3) : "r"(addr))
#define LDSM_X2(r0,r1,addr) \
    asm volatile("ldmatrix.sync.aligned.m8n8.x2.shared.b16 {%0,%1}, [%2];" \
        : "=r"(r0),"=r"(r1) : "r"(addr))
#define LDSM_X4_NV(r0,r1,r2,r3,addr) \
    asm("ldmatrix.sync.aligned.m8n8.x4.shared.b16 {%0,%1,%2,%3}, [%4];" \
        : "=r"(r0),"=r"(r1),"=r"(r2),"=r"(r3) : "r"(addr))

__device__ __forceinline__ void mma16816(float* d, const uint32_t* a, uint32_t b0, uint32_t b1) {
    asm volatile(
        "mma.sync.aligned.m16n8k16.row.col.f32.f16.f16.f32 "
        "{%0,%1,%2,%3},{%4,%5,%6,%7},{%8,%9},{%0,%1,%2,%3};"
        : "+f"(d[0]), "+f"(d[1]), "+f"(d[2]), "+f"(d[3])
        : "r"(a[0]), "r"(a[1]), "r"(a[2]), "r"(a[3]), "r"(b0), "r"(b1));
}

__device__ __forceinline__ float mishf(float x) {
    float u = __expf(fminf(x, 15.f));
    float d = __fmaf_rn(u, u + 2.f, 2.f);
    return x - __fdividef(2.f * x, d);
}
__device__ __forceinline__ float warp_sum(float v) {
    #pragma unroll
    for (int o = 16; o; o >>= 1) v += __shfl_xor_sync(0xffffffffu, v, o);
    return v;
}

// ------------------------------ prep ------------------------------
__global__ void k_prep(const float* __restrict__ sett1_w, const float* __restrict__ city1_w,
                       const float* __restrict__ road1_w, const float* __restrict__ rob1_w,
                       const float* __restrict__ gfc1_w,
                       const float* __restrict__ sett1_b, const float* __restrict__ city1_b,
                       const float* __restrict__ road1_b, const float* __restrict__ rob1_b,
                       const float* __restrict__ gfc1_b,
                       const float* __restrict__ ln_n_w, const float* __restrict__ ln_n_b) {
    int i = blockIdx.x * blockDim.x + threadIdx.x;
    if (i < 160 * 48) {          // node-proj W' = lnw * W, hi/lo split
        int j = i / 48, k = i % 48;
        float v;
        if (j < 32)       v = sett1_w[j * 128 + 80 + k];
        else if (j < 64)  v = city1_w[(j - 32) * 128 + 80 + k];
        else if (j < 96)  v = road1_w[(j - 64) * 176 + 80 + k];
        else if (j < 128) v = road1_w[(j - 96) * 176 + 128 + k];
        else              v = rob1_w[(j - 128) * 128 + 80 + k];
        v *= ln_n_w[k];
        __half h = __float2half(v);
        d_Wh[i] = h;
        d_Wl[i] = __float2half(v - __half2float(h));
    }
    if (i < 208 * 80) {
        int o = i / 80, k = i % 80;
        float v;
        if (o < 32)       v = sett1_w[o * 128 + k];
        else if (o < 64)  v = city1_w[(o - 32) * 128 + k];
        else if (o < 96)  v = road1_w[(o - 64) * 176 + k];
        else if (o < 128) v = rob1_w[(o - 96) * 128 + k];
        else              v = gfc1_w[(o - 128) * 80 + k];
        __half h = __float2half(v);
        d_Wth[i] = h;
        d_Wtl[i] = __float2half(v - __half2float(h));
    }
    if (i < 208) {               // first-layer biases + folded LN-bias bP terms
        float v;
        if (i < 32) {
            v = sett1_b[i];
            for (int c = 0; c < 48; c++) v += ln_n_b[c] * sett1_w[i * 128 + 80 + c];
        } else if (i < 64) {
            v = city1_b[i - 32];
            for (int c = 0; c < 48; c++) v += ln_n_b[c] * city1_w[(i - 32) * 128 + 80 + c];
        } else if (i < 96) {
            v = road1_b[i - 64];
            for (int c = 0; c < 48; c++)
                v += ln_n_b[c] * (road1_w[(i - 64) * 176 + 80 + c] +
                                  road1_w[(i - 64) * 176 + 128 + c]);
        } else if (i < 128) {
            v = rob1_b[i - 96];
            for (int c = 0; c < 48; c++) v += ln_n_b[c] * rob1_w[(i - 96) * 128 + 80 + c];
        } else {
            v = gfc1_b[i - 128];
        }
        d_tb[i] = v;
    }
}

// ------------------------------ K1: HMMA trunk kernel (unchanged, proven) ------------------------------
__global__ __launch_bounds__(512, 1) void k1(const float* __restrict__ trunk,
                                             const float* __restrict__ ln_t_w,
                                             const float* __restrict__ ln_t_b, int B) {
    extern __shared__ char smem[];
    const uint32_t sbase = smem_u32(smem);
    const int tid = threadIdx.x, wid = tid >> 5, lane = tid & 31;

    float* xs  = (float*)(smem + X1_XS);
    float* hs  = (float*)(smem + X1_XS);
    float* tb_s = (float*)(smem + X1_TB);
    float* lnw = (float*)(smem + X1_LNW);
    float* lnb = (float*)(smem + X1_LNB);

    for (int i = tid; i < 208 * 80; i += 512) {
        int o = i / 80, k = i % 80;
        *(__half*)(smem + X1_WH + (o * 88 + k) * 2) = d_Wth[i];
        *(__half*)(smem + X1_WL + (o * 88 + k) * 2) = d_Wtl[i];
    }
    for (int i = tid; i < 208; i += 512) tb_s[i] = d_tb[i];
    if (tid < 80) { lnw[tid] = ln_t_w[tid]; lnb[tid] = ln_t_b[tid]; }

    const int rows_valid = min(128, B - (int)blockIdx.x * 128);

    {
        const float4* tr4 = (const float4*)trunk;
        size_t base4 = (size_t)blockIdx.x * 2560;
        #pragma unroll
        for (int q = 0; q < 5; q++) {
            int il = tid + q * 512;
            int row = il / 20, c = il % 20;
            if (row < rows_valid)
                cp16(sbase + X1_XS + (uint32_t)((row * 84 + 4 * c) * 4), tr4 + base4 + il);
        }
        CP_COMMIT_WAIT();
    }
    __syncthreads();

    if (tid < 256) {
        const int r = tid >> 1, h = tid & 1;
        float4 v[10];
        if (r < rows_valid) {
            const float4* xr = (const float4*)(xs + r * 84 + h * 40);
            #pragma unroll
            for (int j = 0; j < 10; j++) v[j] = xr[j];
        } else {
            #pragma unroll
            for (int j = 0; j < 10; j++) v[j] = make_float4(0.f, 0.f, 0.f, 0.f);
        }
        float s = 0.f, q = 0.f;
        #pragma unroll
        for (int j = 0; j < 10; j++) {
            s += v[j].x + v[j].y + v[j].z + v[j].w;
            q += v[j].x * v[j].x + v[j].y * v[j].y + v[j].z * v[j].z + v[j].w * v[j].w;
        }
        s += __shfl_xor_sync(0xffffffffu, s, 1);
        q += __shfl_xor_sync(0xffffffffu, q, 1);
        float mu = s * (1.f / 80.f);
        float is = rsqrtf(q * (1.f / 80.f) - mu * mu + 1e-5f);
        char* dh = smem + X1_AH + (r * 88 + h * 40) * 2;
        char* dl = dh + (X1_AL - X1_AH);
        const float4* lw4 = (const float4*)(lnw + h * 40);
        const float4* lb4 = (const float4*)(lnb + h * 40);
        #pragma unroll
        for (int j = 0; j < 10; j++) {
            float4 w = lw4[j], b = lb4[j];
            float a0 = (v[j].x - mu) * is * w.x + b.x;
            float a1 = (v[j].y - mu) * is * w.y + b.y;
            float a2 = (v[j].z - mu) * is * w.z + b.z;
            float a3 = (v[j].w - mu) * is * w.w + b.w;
            if (r >= rows_valid) { a0 = a1 = a2 = a3 = 0.f; }
            __half2 h01 = __floats2half2_rn(a0, a1), h23 = __floats2half2_rn(a2, a3);
            __half2 l01 = __floats2half2_rn(a0 - __low2float(h01), a1 - __high2float(h01));
            __half2 l23 = __floats2half2_rn(a2 - __low2float(h23), a3 - __high2float(h23));
            uint2 uh; uh.x = *(uint32_t*)&h01; uh.y = *(uint32_t*)&h23;
            uint2 ul; ul.x = *(uint32_t*)&l01; ul.y = *(uint32_t*)&l23;
            *(uint2*)(dh + j * 8) = uh;
            *(uint2*)(dl + j * 8) = ul;
        }
    }
    __syncthreads();

    {
        const int mt = wid & 7, nh = wid >> 3;
        const int g = lane >> 2, k0 = (lane & 3) * 2;
        const uint32_t abase = sbase + X1_AH +
            (uint32_t)((mt * 16 + (lane & 15)) * 176 + (lane >> 4) * 16);
        uint32_t ah[5][4];
        #pragma unroll
        for (int ks = 0; ks < 5; ks++)
            LDSM_X4(ah[ks][0], ah[ks][1], ah[ks][2], ah[ks][3], abase + ks * 32);

        uint32_t wx4 = sbase + X1_WH +
            (uint32_t)((lane & 7) * 176 + (lane >> 3) * 16) + (uint32_t)(nh * 13 * 1408);
        uint32_t wx2 = sbase + X1_WH +
            (uint32_t)((lane & 7) * 176 + ((lane >> 3) & 1) * 16 + 128) + (uint32_t)(nh * 13 * 1408);

        #pragma unroll
        for (int ni = 0; ni < 13; ni++) {
            const int nt = nh * 13 + ni;
            uint32_t bhA[4], bhB[4], bh2[2], blA[4], blB[4], bl2[2];
            LDSM_X4(bhA[0], bhA[1], bhA[2], bhA[3], wx4);
            LDSM_X4(bhB[0], bhB[1], bhB[2], bhB[3], wx4 + 64);
            LDSM_X2(bh2[0], bh2[1], wx2);
            LDSM_X4(blA[0], blA[1], blA[2], blA[3], wx4 + W1OFF);
            LDSM_X4(blB[0], blB[1], blB[2], blB[3], wx4 + 64 + W1OFF);
            LDSM_X2(bl2[0], bl2[1], wx2 + W1OFF);

            float acc[4] = {0.f, 0.f, 0.f, 0.f};
            mma16816(acc, ah[0], bhA[0], bhA[1]);
            mma16816(acc, ah[1], bhA[2], bhA[3]);
            mma16816(acc, ah[2], bhB[0], bhB[1]);
            mma16816(acc, ah[3], bhB[2], bhB[3]);
            mma16816(acc, ah[4], bh2[0], bh2[1]);
            mma16816(acc, ah[0], blA[0], blA[1]);
            mma16816(acc, ah[1], blA[2], blA[3]);
            mma16816(acc, ah[2], blB[0], blB[1]);
            mma16816(acc, ah[3], blB[2], blB[3]);
            mma16816(acc, ah[4], bl2[0], bl2[1]);
            {
                uint32_t al[4];
                const uint32_t albase = abase + (X1_AL - X1_AH);
                LDSM_X4(al[0], al[1], al[2], al[3], albase);
                mma16816(acc, al, bhA[0], bhA[1]);
                LDSM_X4(al[0], al[1], al[2], al[3], albase + 32);
                mma16816(acc, al, bhA[2], bhA[3]);
                LDSM_X4(al[0], al[1], al[2], al[3], albase + 64);
                mma16816(acc, al, bhB[0], bhB[1]);
                LDSM_X4(al[0], al[1], al[2], al[3], albase + 96);
                mma16816(acc, al, bhB[2], bhB[3]);
                LDSM_X4(al[0], al[1], al[2], al[3], albase + 128);
                mma16816(acc, al, bh2[0], bh2[1]);
            }
            wx4 += 1408; wx2 += 1408;

            const int col = nt * 8 + k0;
            const int row0 = mt * 16 + g, row1 = row0 + 8;
            if (col < 128) {
                float b0 = tb_s[col], b1 = tb_s[col + 1];
                if (row0 < rows_valid) {
                    size_t o = (size_t)((size_t)blockIdx.x * 128 + row0) * 128 + col;
                    d_tproj[o] = acc[0] + b0; d_tproj[o + 1] = acc[1] + b1;
                }
                if (row1 < rows_valid) {
                    size_t o = (size_t)((size_t)blockIdx.x * 128 + row1) * 128 + col;
                    d_tproj[o] = acc[2] + b0; d_tproj[o + 1] = acc[3] + b1;
                }
            } else {
                const int ch = col - 128;
                hs[row0 * 84 + ch] = acc[0]; hs[row0 * 84 + ch + 1] = acc[1];
                hs[row1 * 84 + ch] = acc[2]; hs[row1 * 84 + ch + 1] = acc[3];
                if (row0 < rows_valid) {
                    size_t o = (size_t)((size_t)blockIdx.x * 128 + row0) * 80 + ch;
                    d_h[o] = acc[0]; d_h[o + 1] = acc[1];
                }
                if (row1 < rows_valid) {
                    size_t o = (size_t)((size_t)blockIdx.x * 128 + row1) * 80 + ch;
                    d_h[o] = acc[2]; d_h[o + 1] = acc[3];
                }
            }
        }
    }
    __syncthreads();

    if (tid < 80) {
        float s1 = 0.f, s2 = 0.f;
        for (int r = 0; r < rows_valid; r++) {
            float v = hs[r * 84 + tid];
            s1 += v; s2 += v * v;
        }
        d_partial[blockIdx.x * 160 + tid] = s1;
        d_partial[blockIdx.x * 160 + 80 + tid] = s2;
    }
}

// ------------------------------ BN finalize ------------------------------
__global__ void k_bn(const float* __restrict__ bn_w, const float* __restrict__ bn_b,
                     int B, int nblk) {
    int t = threadIdx.x;
    if (t >= 80) return;
    float S1 = 0.f, S2 = 0.f;
    for (int blk = 0; blk < nblk; blk++) {
        S1 += d_partial[blk * 160 + t];
        S2 += d_partial[blk * 160 + 80 + t];
    }
    float invB = 1.f / (float)B;
    float mu = S1 * invB;
    float var = S2 * invB - mu * mu;
    float sc = bn_w[t] * rsqrtf(var + 1e-5f);
    d_bnscale[t] = sc;
    d_bnshift[t] = bn_b[t] - mu * sc;
}

// ------------------------------ K2: HMMA fused node kernel, pipelined ------------------------------
__global__ __launch_bounds__(256, 2) void k2(const float* __restrict__ node_emb,
                                             const int* __restrict__ road_pairs,
                                             const int* __restrict__ tile_nodes,
                                             const float* __restrict__ sett2_w, const float* __restrict__ sett2_b,
                                             const float* __restrict__ city2_w, const float* __restrict__ city2_b,
                                             const float* __restrict__ road2_w, const float* __restrict__ road2_b,
                                             const float* __restrict__ rob2_w, const float* __restrict__ rob2_b,
                                             float* __restrict__ out, int B) {
    extern __shared__ char smem[];
    const uint32_t sbase = smem_u32(smem);
    const int tid = threadIdx.x, wid = tid >> 5, lane = tid & 31;

    float* P_s     = (float*)(smem + SM_XP);   // rows x 100 = P cols 64:160
    float* w2_s    = (float*)(smem + SM_W2);
    float* rob2_s  = (float*)(smem + SM_ROB2);
    float* b2_s    = (float*)(smem + SM_B2);
    int*   rp_s    = (int*)(smem + SM_RP);
    int*   ti_s    = (int*)(smem + SM_TI);

    for (int i = tid; i < 160 * 48; i += 256) {
        int n = i / 48, k = i % 48;
        *(__half*)(smem + SM_WH + (n * 56 + k) * 2) = d_Wh[i];
        *(__half*)(smem + SM_WL + (n * 56 + k) * 2) = d_Wl[i];
    }
    if (tid < 32) { w2_s[tid] = sett2_w[tid]; w2_s[32 + tid] = city2_w[tid]; w2_s[64 + tid] = road2_w[tid]; }
    if (tid < 160) rob2_s[tid] = rob2_w[tid];
    if (tid == 0) { b2_s[0] = sett2_b[0]; b2_s[1] = city2_b[0]; b2_s[2] = road2_b[0]; }
    if (tid < 5) b2_s[3 + tid] = rob2_b[tid];
    if (tid < 144) rp_s[tid] = road_pairs[tid];
    if (tid < 114) ti_s[tid] = tile_nodes[tid];

    const int g = lane >> 2;
    const int k0 = (lane & 3) * 2;
    const int mrow = (wid & 3) * 32;
    const int hd = wid >> 2;              // 0 = sett group, 1 = city group

    int rown[4]; int tpoff[4];
    #pragma unroll
    for (int s = 0; s < 4; s++) {
        rown[s] = mrow + 16 * (s >> 1) + 8 * (s & 1) + g;
        tpoff[s] = (rown[s] >= 54) ? 128 : 0;
    }

    const uint32_t wx4base0 = sbase + SM_WH +
        (uint32_t)((lane & 7) * 112 + (lane >> 3) * 16);
    const uint32_t wpbase0 = sbase + SM_WH +
        (uint32_t)((lane & 7) * 112 + ((lane >> 3) & 1) * 16 + 64 + ((lane >> 4) & 1) * 896);
    const uint32_t abase0 = sbase + SM_AH +
        (uint32_t)((mrow + (lane & 15)) * 112 + (lane >> 4) * 16);

    const long npairs = ((long)B + 1) / 2;
    const size_t totp4 = (size_t)B * 32;
    const float4* tp4 = (const float4*)d_tproj;

    // ---- fused LN prefetch: row -> fp16 A tile (hi only), A' = (x-mu)*is ----
    auto ln_prefetch = [&](long p, int dstbuf) {
        const int nr = (int)((long)B * 54 - p * 108 >= 108 ? 108 : (long)B * 54 - p * 108);
        if (tid < nr) {
            const float4* xr = (const float4*)(node_emb + ((size_t)p * 108 + tid) * 48);
            float4 v[12];
            #pragma unroll
            for (int j = 0; j < 12; j++) v[j] = xr[j];
            float s = 0.f, q = 0.f;
            #pragma unroll
            for (int j = 0; j < 12; j++) {
                s += v[j].x + v[j].y + v[j].z + v[j].w;
                q += v[j].x * v[j].x + v[j].y * v[j].y + v[j].z * v[j].z + v[j].w * v[j].w;
            }
            float mu = s * (1.f / 48.f);
            float is = rsqrtf(q * (1.f / 48.f) - mu * mu + 1e-5f);
            char* dst = smem + SM_AH + dstbuf * ABUF + tid * 112;
            #pragma unroll
            for (int j = 0; j < 6; j++) {
                float4 va = v[2 * j], vb = v[2 * j + 1];
                __half2 h01 = __floats2half2_rn((va.x - mu) * is, (va.y - mu) * is);
                __half2 h23 = __floats2half2_rn((va.z - mu) * is, (va.w - mu) * is);
                __half2 h45 = __floats2half2_rn((vb.x - mu) * is, (vb.y - mu) * is);
                __half2 h67 = __floats2half2_rn((vb.z - mu) * is, (vb.w - mu) * is);
                uint4 uh; uh.x = *(uint32_t*)&h01; uh.y = *(uint32_t*)&h23;
                uh.z = *(uint32_t*)&h45; uh.w = *(uint32_t*)&h67;
                *(uint4*)(dst + j * 16) = uh;
            }
        }
        if (tid < 64) {
            size_t t4 = (size_t)p * 64 + tid;
            if (t4 < totp4) cp16(sbase + SM_TPROJ + dstbuf * 1024 + tid * 16, tp4 + t4);
        }
        CP_COMMIT();
    };

    // ---- prologue: first pair into buf 0 ----
    long pair = blockIdx.x;
    int buf = 0;
    if (pair < npairs) ln_prefetch(pair, 0);
    __syncthreads();   // order init smem writes before hoisted invariant loads

    // hoisted loop-invariant head weights
    const int rc = lane & 7;
    const float4 w2road = *(const float4*)(w2_s + 64 + rc * 4);
    float2 w2sc[2][2];
    #pragma unroll
    for (int pi = 0; pi < 2; pi++)
        #pragma unroll
        for (int sub = 0; sub < 2; sub++)
            w2sc[pi][sub] = *(const float2*)(w2_s + (4 * hd + 2 * pi + sub) * 8 + k0);

    for (; pair < npairs; pair += gridDim.x, buf ^= 1) {
        const float* tpb = (const float*)(smem + SM_TPROJ + buf * 1024);

        CP_WAIT_ALL();
        __syncthreads();   // AH(buf)/tproj(buf) ready; prev heads done with P_s

        const int nrows = (int)((long)B * 54 - pair * 108 >= 108 ? 108 : (long)B * 54 - pair * 108);

        // ---- A fragments via ldmatrix (hi only, from AH[buf]) ----
        uint32_t afh[2][3][4];
        {
            const uint32_t ab = abase0 + (uint32_t)(buf * ABUF);
            #pragma unroll
            for (int t = 0; t < 2; t++) {
                #pragma unroll
                for (int ks = 0; ks < 3; ks++) {
                    LDSM_X4(afh[t][ks][0], afh[t][ks][1], afh[t][ks][2], afh[t][ks][3],
                            ab + (uint32_t)(t * 1792 + ks * 32));
                }
            }
        }

        // ---- prefetch next pair into buf^1 (hides under MMA) ----
        {
            long nxt = pair + gridDim.x;
            if (nxt < npairs) ln_prefetch(nxt, buf ^ 1);
        }

        float sacc[4] = {0.f, 0.f, 0.f, 0.f};

        // nt pairs: hd=0 -> (0,1),(2,3),(8,9),(10,11),(12,13);
        //           hd=1 -> (4,5),(6,7),(14,15),(16,17),(18,19)
        #pragma unroll
        for (int pi = 0; pi < 5; pi++) {
            const int ntA = (pi < 2) ? (4 * hd + 2 * pi) : (8 + 6 * hd + 2 * (pi - 2));
            uint32_t c2h[4], c2l[4];
            LDSM_X4_NV(c2h[0], c2h[1], c2h[2], c2h[3], wpbase0 + ntA * 896);
            LDSM_X4_NV(c2l[0], c2l[1], c2l[2], c2l[3], wpbase0 + ntA * 896 + WLOFF);

            #pragma unroll
            for (int sub = 0; sub < 2; sub++) {
                const int nt = ntA + sub;
                uint32_t bh[4], bl[4];
                LDSM_X4_NV(bh[0], bh[1], bh[2], bh[3], wx4base0 + nt * 896);
                LDSM_X4_NV(bl[0], bl[1], bl[2], bl[3], wx4base0 + nt * 896 + WLOFF);
                const uint32_t bh2a = c2h[2 * sub], bh2b = c2h[2 * sub + 1];
                const uint32_t bl2a = c2l[2 * sub], bl2b = c2l[2 * sub + 1];

                float acc[2][4] = {{0.f, 0.f, 0.f, 0.f}, {0.f, 0.f, 0.f, 0.f}};
                #pragma unroll
                for (int t = 0; t < 2; t++) {
                    mma16816(acc[t], afh[t][0], bh[0], bh[1]);
                    mma16816(acc[t], afh[t][1], bh[2], bh[3]);
                    mma16816(acc[t], afh[t][2], bh2a, bh2b);
                    mma16816(acc[t], afh[t][0], bl[0], bl[1]);
                    mma16816(acc[t], afh[t][1], bl[2], bl[3]);
                    mma16816(acc[t], afh[t][2], bl2a, bl2b);
                }
                const int col = nt * 8 + k0;
                if (pi < 2) {
                    float w2a = w2sc[pi][sub].x, w2b = w2sc[pi][sub].y;
                    #pragma unroll
                    for (int s = 0; s < 4; s++) {
                        float2 tpv = *(const float2*)(tpb + tpoff[s] + col);
                        float v0 = acc[s >> 1][2 * (s & 1)];
                        float v1 = acc[s >> 1][2 * (s & 1) + 1];
                        sacc[s] += mishf(v0 + tpv.x) * w2a + mishf(v1 + tpv.y) * w2b;
                    }
                } else {
                    #pragma unroll
                    for (int s = 0; s < 4; s++) {
                        int r = rown[s];
                        if (r < 108)
                            *(float2*)(P_s + r * 100 + (col - 64)) =
                                make_float2(acc[s >> 1][2 * (s & 1)], acc[s >> 1][2 * (s & 1) + 1]);
                    }
                }
            }
        }

        // sett/city finalize
        {
            #pragma unroll
            for (int s = 0; s < 4; s++) {
                sacc[s] += __shfl_xor_sync(0xffffffffu, sacc[s], 1);
                sacc[s] += __shfl_xor_sync(0xffffffffu, sacc[s], 2);
            }
            if ((lane & 3) == 0) {
                #pragma unroll
                for (int s = 0; s < 4; s++) {
                    int r = rown[s];
                    if (r < nrows) {
                        int bl = (r >= 54) ? 1 : 0;
                        int n = r - 54 * bl;
                        out[((size_t)(pair * 2 + bl)) * 397 + 5 + 54 * hd + n] = sacc[s] + b2_s[hd];
                    }
                }
            }
        }
        __syncthreads();

        const int nb = (nrows > 54) ? 2 : 1;
        const int sub = lane >> 3;
        // ---- road heads: 4 edges per warp-task, float4 cols ----
        for (int t = wid; t < nb * 18; t += 8) {
            int bl = (t >= 18) ? 1 : 0;
            int tg = t - 18 * bl;
            int e = tg * 4 + sub;
            int sN = rp_s[2 * e], dN = rp_s[2 * e + 1];
            float4 tpv = *(const float4*)(tpb + bl * 128 + 64 + rc * 4);
            float4 Psv = *(const float4*)(P_s + (bl * 54 + sN) * 100 + rc * 4);
            float4 Pdv = *(const float4*)(P_s + (bl * 54 + dN) * 100 + 32 + rc * 4);
            float part = mishf(tpv.x + Psv.x + Pdv.x) * w2road.x
                       + mishf(tpv.y + Psv.y + Pdv.y) * w2road.y
                       + mishf(tpv.z + Psv.z + Pdv.z) * w2road.z
                       + mishf(tpv.w + Psv.w + Pdv.w) * w2road.w;
            part += __shfl_xor_sync(0xffffffffu, part, 1);
            part += __shfl_xor_sync(0xffffffffu, part, 2);
            part += __shfl_xor_sync(0xffffffffu, part, 4);
            if (rc == 0) out[((size_t)(pair * 2 + bl)) * 397 + 113 + e] = part + b2_s[2];
        }
        // ---- robber heads: 4 tiles per warp-task, float4 cols ----
        for (int t = wid; t < nb * 5; t += 8) {
            int bl = (t >= 5) ? 1 : 0;
            int tg = t - 5 * bl;
            int tile = tg * 4 + sub;
            bool valid = tile < 19;
            int tix = valid ? tile : 0;
            float4 a = make_float4(0.f, 0.f, 0.f, 0.f);
            #pragma unroll
            for (int i = 0; i < 6; i++) {
                const float4 p = *(const float4*)(P_s + (bl * 54 + ti_s[tix * 6 + i]) * 100 + 64 + rc * 4);
                a.x += p.x; a.y += p.y; a.z += p.z; a.w += p.w;
            }
            float4 tpv = *(const float4*)(tpb + bl * 128 + 96 + rc * 4);
            float m0 = mishf(tpv.x + a.x * (1.f / 6.f));
            float m1 = mishf(tpv.y + a.y * (1.f / 6.f));
            float m2 = mishf(tpv.z + a.z * (1.f / 6.f));
            float m3 = mishf(tpv.w + a.w * (1.f / 6.f));
            #pragma unroll
            for (int o = 0; o < 5; o++) {
                float4 rv = *(const float4*)(rob2_s + o * 32 + rc * 4);
                float part = m0 * rv.x + m1 * rv.y + m2 * rv.z + m3 * rv.w;
                part += __shfl_xor_sync(0xffffffffu, part, 1);
                part += __shfl_xor_sync(0xffffffffu, part, 2);
                part += __shfl_xor_sync(0xffffffffu, part, 4);
                if (rc == 0 && valid)
                    out[((size_t)(pair * 2 + bl)) * 397 + 185 + tile * 5 + o] = part + b2_s[3 + o];
            }
        }
        // (no end barrier: next iteration's top barrier protects P_s/tproj/AH)
    }
}

// ------------------------------ K3: BN + mish + gfc2, 8-row batched ------------------------------
__global__ __launch_bounds__(128) void k3(const float* __restrict__ gfc2_w,
                                          const float* __restrict__ gfc2_b,
                                          float* __restrict__ out, int B) {
    __shared__ __align__(16) float m8[80 * 8];
    __shared__ __align__(16) float Wg[80 * 122];
    __shared__ float bs[122];
    __shared__ float sc[80], sh[80];
    int tid = threadIdx.x;
    for (int i = tid; i < 80 * 122; i += 128) {
        int k = i / 122, t = i % 122;
        int r = (t < 5) ? t : (275 + t);
        Wg[i] = gfc2_w[r * 80 + k];
    }
    if (tid < 122) { int r = (tid < 5) ? tid : (275 + tid); bs[tid] = gfc2_b[r]; }
    if (tid < 80) { sc[tid] = d_bnscale[tid]; sh[tid] = d_bnshift[tid]; }
    __syncthreads();
    int nq = (B + 7) >> 3;
    for (int qb = blockIdx.x; qb < nq; qb += gridDim.x) {
        if (tid < 80) {
            #pragma unroll
            for (int rb = 0; rb < 8; rb++) {
                int b = qb * 8 + rb;
                float v = (b < B) ? d_h[(size_t)b * 80 + tid] : 0.f;
                m8[tid * 8 + rb] = mishf(v * sc[tid] + sh[tid]);
            }
        }
        __syncthreads();
        if (tid < 122) {
            float a[8];
            #pragma unroll
            for (int rb = 0; rb < 8; rb++) a[rb] = bs[tid];
            for (int k = 0; k < 80; k++) {
                float4 mA = *(const float4*)(m8 + k * 8);
                float4 mB = *(const float4*)(m8 + k * 8 + 4);
                float w = Wg[k * 122 + tid];
                a[0] += mA.x * w; a[1] += mA.y * w; a[2] += mA.z * w; a[3] += mA.w * w;
                a[4] += mB.x * w; a[5] += mB.y * w; a[6] += mB.z * w; a[7] += mB.w * w;
            }
            int col = (tid < 5) ? tid : (275 + tid);
            #pragma unroll
            for (int rb = 0; rb < 8; rb++) {
                int b = qb * 8 + rb;
                if (b < B) out[(size_t)b * 397 + col] = a[rb];
            }
        }
        __syncthreads();
    }
}

// ------------------------------ launch ------------------------------
extern "C" void kernel_launch(void* const* d_in, const int* in_sizes, int n_in,
                              void* d_out, int out_size) {
    const float* trunk      = (const float*)d_in[0];
    const float* node_emb   = (const float*)d_in[1];
    const int*   road_pairs = (const int*)d_in[2];
    const int*   tile_nodes = (const int*)d_in[3];
    const float* ln_t_w = (const float*)d_in[4];
    const float* ln_t_b = (const float*)d_in[5];
    const float* ln_n_w = (const float*)d_in[6];
    const float* ln_n_b = (const float*)d_in[7];
    const float* gfc1_w = (const float*)d_in[8];
    const float* gfc1_b = (const float*)d_in[9];
    const float* bn_w   = (const float*)d_in[10];
    const float* bn_b   = (const float*)d_in[11];
    const float* gfc2_w = (const float*)d_in[12];
    const float* gfc2_b = (const float*)d_in[13];
    const float* sett1_w = (const float*)d_in[14];
    const float* sett1_b = (const float*)d_in[15];
    const float* sett2_w = (const float*)d_in[16];
    const float* sett2_b = (const float*)d_in[17];
    const float* city1_w = (const float*)d_in[18];
    const float* city1_b = (const float*)d_in[19];
    const float* city2_w = (const float*)d_in[20];
    const float* city2_b = (const float*)d_in[21];
    const float* road1_w = (const float*)d_in[22];
    const float* road1_b = (const float*)d_in[23];
    const float* road2_w = (const float*)d_in[24];
    const float* road2_b = (const float*)d_in[25];
    const float* rob1_w = (const float*)d_in[26];
    const float* rob1_b = (const float*)d_in[27];
    const float* rob2_w = (const float*)d_in[28];
    const float* rob2_b = (const float*)d_in[29];

    int B = in_sizes[0] / 80;
    if (B > BMAX) B = BMAX;
    float* out = (float*)d_out;
    int nblk1 = (B + 127) / 128;

    cudaFuncSetAttribute(k1, cudaFuncAttributeMaxDynamicSharedMemorySize, K1_SMEM);
    cudaFuncSetAttribute(k2, cudaFuncAttributeMaxDynamicSharedMemorySize, SM_TOTAL);

    k_prep<<<(208 * 80 + 255) / 256, 256>>>(sett1_w, city1_w, road1_w, rob1_w, gfc1_w,
                                            sett1_b, city1_b, road1_b, rob1_b, gfc1_b,
                                            ln_n_w, ln_n_b);
    k1<<<nblk1, 512, K1_SMEM>>>(trunk, ln_t_w, ln_t_b, B);
    k_bn<<<1, 80>>>(bn_w, bn_b, B, nblk1);
    k2<<<K2_GRID, 256, SM_TOTAL>>>(node_emb, road_pairs, tile_nodes,
                                   sett2_w, sett2_b, city2_w, city2_b,
                                   road2_w, road2_b, rob2_w, rob2_b, out, B);
    k3<<<K3_GRID, 128>>>(gfc2_w, gfc2_b, out, B);
}

// round 16
// speedup vs baseline: 1.6349x; 1.1110x over previous
#include <cuda_runtime.h>
#include <cuda_fp16.h>
#include <cstdint>
#include <cstddef>

// ---------------------------------------------------------------------------
// SmallSpatialPolicyHead — R15 + k2: pure fp16 GEMM (Ah*Wh only; both
// compensation terms dropped — measured A-drop error 5.8e-5, symmetric W-drop
// adds in quadrature -> ~1e-4 << 1e-3). MMAs 120->60, W-LDSM 30->15/warp-iter.
// ---------------------------------------------------------------------------

#define BMAX 16384
#define K2_GRID 296
#define K3_GRID 592

__device__ float d_tb[208];
__device__ __half d_Wh[160 * 48];    // k2 node proj [n][k] (lnw-scaled, fp16)
__device__ __half d_Wth[208 * 80];   // k1 trunk proj hi [o][k]
__device__ __half d_Wtl[208 * 80];   // k1 trunk proj lo
__device__ float d_tproj[(size_t)BMAX * 128];
__device__ float d_h[(size_t)BMAX * 80];
__device__ float d_partial[296 * 160];
__device__ float d_bnscale[80];
__device__ float d_bnshift[80];

// ---- k2 smem byte offsets ----
#define SM_XP    0             // P_s 108x100 f = 43200
#define SM_AH    43200         // 2 x (128x56 fp16 = 14336), double buffer
#define ABUF     14336
#define SM_WH    71872         // 160x56 fp16 = 17920
#define SM_TPROJ 89792         // 2 x 256 f (double buffer)
#define SM_W2    91840         // 96 f
#define SM_ROB2  92224         // 160 f
#define SM_B2    92864         // 8 f
#define SM_RP    92896         // 144 i
#define SM_TI    93472         // 114 i
#define SM_TOTAL 93928

// ---- k1 smem byte offsets ----
#define X1_XS    0             // 128x84 f = 43008 (reused as hs)
#define X1_AH    43008         // 128x88 fp16 = 22528
#define X1_AL    65536
#define X1_WH    88064         // 208x88 fp16 = 36608
#define X1_WL    124672
#define W1OFF    36608
#define X1_TB    161280        // 208 f
#define X1_LNW   162112        // 80 f
#define X1_LNB   162432        // 80 f
#define K1_SMEM  162752

__device__ __forceinline__ uint32_t smem_u32(const void* p) {
    uint32_t a;
    asm("{ .reg .u64 t; cvta.to.shared.u64 t, %1; cvt.u32.u64 %0, t; }" : "=r"(a) : "l"(p));
    return a;
}
__device__ __forceinline__ void cp16(uint32_t dst, const void* src) {
    asm volatile("cp.async.cg.shared.global [%0], [%1], 16;" :: "r"(dst), "l"(src));
}
#define CP_COMMIT() asm volatile("cp.async.commit_group;" ::: "memory")
#define CP_WAIT_ALL() asm volatile("cp.async.wait_group 0;" ::: "memory")
#define CP_COMMIT_WAIT() do { CP_COMMIT(); CP_WAIT_ALL(); } while (0)

#define LDSM_X4(r0,r1,r2,r3,addr) \
    asm volatile("ldmatrix.sync.aligned.m8n8.x4.shared.b16 {%0,%1,%2,%3}, [%4];" \
        : "=r"(r0),"=r"(r1),"=r"(r2),"=r"(r3) : "r"(addr))
#define LDSM_X2(r0,r1,addr) \
    asm volatile("ldmatrix.sync.aligned.m8n8.x2.shared.b16 {%0,%1}, [%2];" \
        : "=r"(r0),"=r"(r1) : "r"(addr))
#define LDSM_X4_NV(r0,r1,r2,r3,addr) \
    asm("ldmatrix.sync.aligned.m8n8.x4.shared.b16 {%0,%1,%2,%3}, [%4];" \
        : "=r"(r0),"=r"(r1),"=r"(r2),"=r"(r3) : "r"(addr))

__device__ __forceinline__ void mma16816(float* d, const uint32_t* a, uint32_t b0, uint32_t b1) {
    asm volatile(
        "mma.sync.aligned.m16n8k16.row.col.f32.f16.f16.f32 "
        "{%0,%1,%2,%3},{%4,%5,%6,%7},{%8,%9},{%0,%1,%2,%3};"
        : "+f"(d[0]), "+f"(d[1]), "+f"(d[2]), "+f"(d[3])
        : "r"(a[0]), "r"(a[1]), "r"(a[2]), "r"(a[3]), "r"(b0), "r"(b1));
}

__device__ __forceinline__ float mishf(float x) {
    float u = __expf(fminf(x, 15.f));
    float d = __fmaf_rn(u, u + 2.f, 2.f);
    return x - __fdividef(2.f * x, d);
}
__device__ __forceinline__ float warp_sum(float v) {
    #pragma unroll
    for (int o = 16; o; o >>= 1) v += __shfl_xor_sync(0xffffffffu, v, o);
    return v;
}

// ------------------------------ prep ------------------------------
__global__ void k_prep(const float* __restrict__ sett1_w, const float* __restrict__ city1_w,
                       const float* __restrict__ road1_w, const float* __restrict__ rob1_w,
                       const float* __restrict__ gfc1_w,
                       const float* __restrict__ sett1_b, const float* __restrict__ city1_b,
                       const float* __restrict__ road1_b, const float* __restrict__ rob1_b,
                       const float* __restrict__ gfc1_b,
                       const float* __restrict__ ln_n_w, const float* __restrict__ ln_n_b) {
    int i = blockIdx.x * blockDim.x + threadIdx.x;
    if (i < 160 * 48) {          // node-proj W' = lnw * W (fp16)
        int j = i / 48, k = i % 48;
        float v;
        if (j < 32)       v = sett1_w[j * 128 + 80 + k];
        else if (j < 64)  v = city1_w[(j - 32) * 128 + 80 + k];
        else if (j < 96)  v = road1_w[(j - 64) * 176 + 80 + k];
        else if (j < 128) v = road1_w[(j - 96) * 176 + 128 + k];
        else              v = rob1_w[(j - 128) * 128 + 80 + k];
        d_Wh[i] = __float2half(v * ln_n_w[k]);
    }
    if (i < 208 * 80) {
        int o = i / 80, k = i % 80;
        float v;
        if (o < 32)       v = sett1_w[o * 128 + k];
        else if (o < 64)  v = city1_w[(o - 32) * 128 + k];
        else if (o < 96)  v = road1_w[(o - 64) * 176 + k];
        else if (o < 128) v = rob1_w[(o - 96) * 128 + k];
        else              v = gfc1_w[(o - 128) * 80 + k];
        __half h = __float2half(v);
        d_Wth[i] = h;
        d_Wtl[i] = __float2half(v - __half2float(h));
    }
    if (i < 208) {               // first-layer biases + folded LN-bias bP terms
        float v;
        if (i < 32) {
            v = sett1_b[i];
            for (int c = 0; c < 48; c++) v += ln_n_b[c] * sett1_w[i * 128 + 80 + c];
        } else if (i < 64) {
            v = city1_b[i - 32];
            for (int c = 0; c < 48; c++) v += ln_n_b[c] * city1_w[(i - 32) * 128 + 80 + c];
        } else if (i < 96) {
            v = road1_b[i - 64];
            for (int c = 0; c < 48; c++)
                v += ln_n_b[c] * (road1_w[(i - 64) * 176 + 80 + c] +
                                  road1_w[(i - 64) * 176 + 128 + c]);
        } else if (i < 128) {
            v = rob1_b[i - 96];
            for (int c = 0; c < 48; c++) v += ln_n_b[c] * rob1_w[(i - 96) * 128 + 80 + c];
        } else {
            v = gfc1_b[i - 128];
        }
        d_tb[i] = v;
    }
}

// ------------------------------ K1: HMMA trunk kernel (unchanged, proven) ------------------------------
__global__ __launch_bounds__(512, 1) void k1(const float* __restrict__ trunk,
                                             const float* __restrict__ ln_t_w,
                                             const float* __restrict__ ln_t_b, int B) {
    extern __shared__ char smem[];
    const uint32_t sbase = smem_u32(smem);
    const int tid = threadIdx.x, wid = tid >> 5, lane = tid & 31;

    float* xs  = (float*)(smem + X1_XS);
    float* hs  = (float*)(smem + X1_XS);
    float* tb_s = (float*)(smem + X1_TB);
    float* lnw = (float*)(smem + X1_LNW);
    float* lnb = (float*)(smem + X1_LNB);

    for (int i = tid; i < 208 * 80; i += 512) {
        int o = i / 80, k = i % 80;
        *(__half*)(smem + X1_WH + (o * 88 + k) * 2) = d_Wth[i];
        *(__half*)(smem + X1_WL + (o * 88 + k) * 2) = d_Wtl[i];
    }
    for (int i = tid; i < 208; i += 512) tb_s[i] = d_tb[i];
    if (tid < 80) { lnw[tid] = ln_t_w[tid]; lnb[tid] = ln_t_b[tid]; }

    const int rows_valid = min(128, B - (int)blockIdx.x * 128);

    {
        const float4* tr4 = (const float4*)trunk;
        size_t base4 = (size_t)blockIdx.x * 2560;
        #pragma unroll
        for (int q = 0; q < 5; q++) {
            int il = tid + q * 512;
            int row = il / 20, c = il % 20;
            if (row < rows_valid)
                cp16(sbase + X1_XS + (uint32_t)((row * 84 + 4 * c) * 4), tr4 + base4 + il);
        }
        CP_COMMIT_WAIT();
    }
    __syncthreads();

    if (tid < 256) {
        const int r = tid >> 1, h = tid & 1;
        float4 v[10];
        if (r < rows_valid) {
            const float4* xr = (const float4*)(xs + r * 84 + h * 40);
            #pragma unroll
            for (int j = 0; j < 10; j++) v[j] = xr[j];
        } else {
            #pragma unroll
            for (int j = 0; j < 10; j++) v[j] = make_float4(0.f, 0.f, 0.f, 0.f);
        }
        float s = 0.f, q = 0.f;
        #pragma unroll
        for (int j = 0; j < 10; j++) {
            s += v[j].x + v[j].y + v[j].z + v[j].w;
            q += v[j].x * v[j].x + v[j].y * v[j].y + v[j].z * v[j].z + v[j].w * v[j].w;
        }
        s += __shfl_xor_sync(0xffffffffu, s, 1);
        q += __shfl_xor_sync(0xffffffffu, q, 1);
        float mu = s * (1.f / 80.f);
        float is = rsqrtf(q * (1.f / 80.f) - mu * mu + 1e-5f);
        char* dh = smem + X1_AH + (r * 88 + h * 40) * 2;
        char* dl = dh + (X1_AL - X1_AH);
        const float4* lw4 = (const float4*)(lnw + h * 40);
        const float4* lb4 = (const float4*)(lnb + h * 40);
        #pragma unroll
        for (int j = 0; j < 10; j++) {
            float4 w = lw4[j], b = lb4[j];
            float a0 = (v[j].x - mu) * is * w.x + b.x;
            float a1 = (v[j].y - mu) * is * w.y + b.y;
            float a2 = (v[j].z - mu) * is * w.z + b.z;
            float a3 = (v[j].w - mu) * is * w.w + b.w;
            if (r >= rows_valid) { a0 = a1 = a2 = a3 = 0.f; }
            __half2 h01 = __floats2half2_rn(a0, a1), h23 = __floats2half2_rn(a2, a3);
            __half2 l01 = __floats2half2_rn(a0 - __low2float(h01), a1 - __high2float(h01));
            __half2 l23 = __floats2half2_rn(a2 - __low2float(h23), a3 - __high2float(h23));
            uint2 uh; uh.x = *(uint32_t*)&h01; uh.y = *(uint32_t*)&h23;
            uint2 ul; ul.x = *(uint32_t*)&l01; ul.y = *(uint32_t*)&l23;
            *(uint2*)(dh + j * 8) = uh;
            *(uint2*)(dl + j * 8) = ul;
        }
    }
    __syncthreads();

    {
        const int mt = wid & 7, nh = wid >> 3;
        const int g = lane >> 2, k0 = (lane & 3) * 2;
        const uint32_t abase = sbase + X1_AH +
            (uint32_t)((mt * 16 + (lane & 15)) * 176 + (lane >> 4) * 16);
        uint32_t ah[5][4];
        #pragma unroll
        for (int ks = 0; ks < 5; ks++)
            LDSM_X4(ah[ks][0], ah[ks][1], ah[ks][2], ah[ks][3], abase + ks * 32);

        uint32_t wx4 = sbase + X1_WH +
            (uint32_t)((lane & 7) * 176 + (lane >> 3) * 16) + (uint32_t)(nh * 13 * 1408);
        uint32_t wx2 = sbase + X1_WH +
            (uint32_t)((lane & 7) * 176 + ((lane >> 3) & 1) * 16 + 128) + (uint32_t)(nh * 13 * 1408);

        #pragma unroll
        for (int ni = 0; ni < 13; ni++) {
            const int nt = nh * 13 + ni;
            uint32_t bhA[4], bhB[4], bh2[2], blA[4], blB[4], bl2[2];
            LDSM_X4(bhA[0], bhA[1], bhA[2], bhA[3], wx4);
            LDSM_X4(bhB[0], bhB[1], bhB[2], bhB[3], wx4 + 64);
            LDSM_X2(bh2[0], bh2[1], wx2);
            LDSM_X4(blA[0], blA[1], blA[2], blA[3], wx4 + W1OFF);
            LDSM_X4(blB[0], blB[1], blB[2], blB[3], wx4 + 64 + W1OFF);
            LDSM_X2(bl2[0], bl2[1], wx2 + W1OFF);

            float acc[4] = {0.f, 0.f, 0.f, 0.f};
            mma16816(acc, ah[0], bhA[0], bhA[1]);
            mma16816(acc, ah[1], bhA[2], bhA[3]);
            mma16816(acc, ah[2], bhB[0], bhB[1]);
            mma16816(acc, ah[3], bhB[2], bhB[3]);
            mma16816(acc, ah[4], bh2[0], bh2[1]);
            mma16816(acc, ah[0], blA[0], blA[1]);
            mma16816(acc, ah[1], blA[2], blA[3]);
            mma16816(acc, ah[2], blB[0], blB[1]);
            mma16816(acc, ah[3], blB[2], blB[3]);
            mma16816(acc, ah[4], bl2[0], bl2[1]);
            {
                uint32_t al[4];
                const uint32_t albase = abase + (X1_AL - X1_AH);
                LDSM_X4(al[0], al[1], al[2], al[3], albase);
                mma16816(acc, al, bhA[0], bhA[1]);
                LDSM_X4(al[0], al[1], al[2], al[3], albase + 32);
                mma16816(acc, al, bhA[2], bhA[3]);
                LDSM_X4(al[0], al[1], al[2], al[3], albase + 64);
                mma16816(acc, al, bhB[0], bhB[1]);
                LDSM_X4(al[0], al[1], al[2], al[3], albase + 96);
                mma16816(acc, al, bhB[2], bhB[3]);
                LDSM_X4(al[0], al[1], al[2], al[3], albase + 128);
                mma16816(acc, al, bh2[0], bh2[1]);
            }
            wx4 += 1408; wx2 += 1408;

            const int col = nt * 8 + k0;
            const int row0 = mt * 16 + g, row1 = row0 + 8;
            if (col < 128) {
                float b0 = tb_s[col], b1 = tb_s[col + 1];
                if (row0 < rows_valid) {
                    size_t o = (size_t)((size_t)blockIdx.x * 128 + row0) * 128 + col;
                    d_tproj[o] = acc[0] + b0; d_tproj[o + 1] = acc[1] + b1;
                }
                if (row1 < rows_valid) {
                    size_t o = (size_t)((size_t)blockIdx.x * 128 + row1) * 128 + col;
                    d_tproj[o] = acc[2] + b0; d_tproj[o + 1] = acc[3] + b1;
                }
            } else {
                const int ch = col - 128;
                hs[row0 * 84 + ch] = acc[0]; hs[row0 * 84 + ch + 1] = acc[1];
                hs[row1 * 84 + ch] = acc[2]; hs[row1 * 84 + ch + 1] = acc[3];
                if (row0 < rows_valid) {
                    size_t o = (size_t)((size_t)blockIdx.x * 128 + row0) * 80 + ch;
                    d_h[o] = acc[0]; d_h[o + 1] = acc[1];
                }
                if (row1 < rows_valid) {
                    size_t o = (size_t)((size_t)blockIdx.x * 128 + row1) * 80 + ch;
                    d_h[o] = acc[2]; d_h[o + 1] = acc[3];
                }
            }
        }
    }
    __syncthreads();

    if (tid < 80) {
        float s1 = 0.f, s2 = 0.f;
        for (int r = 0; r < rows_valid; r++) {
            float v = hs[r * 84 + tid];
            s1 += v; s2 += v * v;
        }
        d_partial[blockIdx.x * 160 + tid] = s1;
        d_partial[blockIdx.x * 160 + 80 + tid] = s2;
    }
}

// ------------------------------ BN finalize ------------------------------
__global__ void k_bn(const float* __restrict__ bn_w, const float* __restrict__ bn_b,
                     int B, int nblk) {
    int t = threadIdx.x;
    if (t >= 80) return;
    float S1 = 0.f, S2 = 0.f;
    for (int blk = 0; blk < nblk; blk++) {
        S1 += d_partial[blk * 160 + t];
        S2 += d_partial[blk * 160 + 80 + t];
    }
    float invB = 1.f / (float)B;
    float mu = S1 * invB;
    float var = S2 * invB - mu * mu;
    float sc = bn_w[t] * rsqrtf(var + 1e-5f);
    d_bnscale[t] = sc;
    d_bnshift[t] = bn_b[t] - mu * sc;
}

// ------------------------------ K2: pure-fp16 HMMA fused node kernel ------------------------------
__global__ __launch_bounds__(256, 2) void k2(const float* __restrict__ node_emb,
                                             const int* __restrict__ road_pairs,
                                             const int* __restrict__ tile_nodes,
                                             const float* __restrict__ sett2_w, const float* __restrict__ sett2_b,
                                             const float* __restrict__ city2_w, const float* __restrict__ city2_b,
                                             const float* __restrict__ road2_w, const float* __restrict__ road2_b,
                                             const float* __restrict__ rob2_w, const float* __restrict__ rob2_b,
                                             float* __restrict__ out, int B) {
    extern __shared__ char smem[];
    const uint32_t sbase = smem_u32(smem);
    const int tid = threadIdx.x, wid = tid >> 5, lane = tid & 31;

    float* P_s     = (float*)(smem + SM_XP);   // rows x 100 = P cols 64:160
    float* w2_s    = (float*)(smem + SM_W2);
    float* rob2_s  = (float*)(smem + SM_ROB2);
    float* b2_s    = (float*)(smem + SM_B2);
    int*   rp_s    = (int*)(smem + SM_RP);
    int*   ti_s    = (int*)(smem + SM_TI);

    for (int i = tid; i < 160 * 48; i += 256) {
        int n = i / 48, k = i % 48;
        *(__half*)(smem + SM_WH + (n * 56 + k) * 2) = d_Wh[i];
    }
    if (tid < 32) { w2_s[tid] = sett2_w[tid]; w2_s[32 + tid] = city2_w[tid]; w2_s[64 + tid] = road2_w[tid]; }
    if (tid < 160) rob2_s[tid] = rob2_w[tid];
    if (tid == 0) { b2_s[0] = sett2_b[0]; b2_s[1] = city2_b[0]; b2_s[2] = road2_b[0]; }
    if (tid < 5) b2_s[3 + tid] = rob2_b[tid];
    if (tid < 144) rp_s[tid] = road_pairs[tid];
    if (tid < 114) ti_s[tid] = tile_nodes[tid];

    const int g = lane >> 2;
    const int k0 = (lane & 3) * 2;
    const int mrow = (wid & 3) * 32;
    const int hd = wid >> 2;              // 0 = sett group, 1 = city group

    int rown[4]; int tpoff[4];
    #pragma unroll
    for (int s = 0; s < 4; s++) {
        rown[s] = mrow + 16 * (s >> 1) + 8 * (s & 1) + g;
        tpoff[s] = (rown[s] >= 54) ? 128 : 0;
    }

    const uint32_t wx4base0 = sbase + SM_WH +
        (uint32_t)((lane & 7) * 112 + (lane >> 3) * 16);
    const uint32_t wpbase0 = sbase + SM_WH +
        (uint32_t)((lane & 7) * 112 + ((lane >> 3) & 1) * 16 + 64 + ((lane >> 4) & 1) * 896);
    const uint32_t abase0 = sbase + SM_AH +
        (uint32_t)((mrow + (lane & 15)) * 112 + (lane >> 4) * 16);

    const long npairs = ((long)B + 1) / 2;
    const size_t totp4 = (size_t)B * 32;
    const float4* tp4 = (const float4*)d_tproj;

    // ---- fused LN prefetch: row -> fp16 A tile, A' = (x-mu)*is ----
    auto ln_prefetch = [&](long p, int dstbuf) {
        const int nr = (int)((long)B * 54 - p * 108 >= 108 ? 108 : (long)B * 54 - p * 108);
        if (tid < nr) {
            const float4* xr = (const float4*)(node_emb + ((size_t)p * 108 + tid) * 48);
            float4 v[12];
            #pragma unroll
            for (int j = 0; j < 12; j++) v[j] = xr[j];
            float s = 0.f, q = 0.f;
            #pragma unroll
            for (int j = 0; j < 12; j++) {
                s += v[j].x + v[j].y + v[j].z + v[j].w;
                q += v[j].x * v[j].x + v[j].y * v[j].y + v[j].z * v[j].z + v[j].w * v[j].w;
            }
            float mu = s * (1.f / 48.f);
            float is = rsqrtf(q * (1.f / 48.f) - mu * mu + 1e-5f);
            char* dst = smem + SM_AH + dstbuf * ABUF + tid * 112;
            #pragma unroll
            for (int j = 0; j < 6; j++) {
                float4 va = v[2 * j], vb = v[2 * j + 1];
                __half2 h01 = __floats2half2_rn((va.x - mu) * is, (va.y - mu) * is);
                __half2 h23 = __floats2half2_rn((va.z - mu) * is, (va.w - mu) * is);
                __half2 h45 = __floats2half2_rn((vb.x - mu) * is, (vb.y - mu) * is);
                __half2 h67 = __floats2half2_rn((vb.z - mu) * is, (vb.w - mu) * is);
                uint4 uh; uh.x = *(uint32_t*)&h01; uh.y = *(uint32_t*)&h23;
                uh.z = *(uint32_t*)&h45; uh.w = *(uint32_t*)&h67;
                *(uint4*)(dst + j * 16) = uh;
            }
        }
        if (tid < 64) {
            size_t t4 = (size_t)p * 64 + tid;
            if (t4 < totp4) cp16(sbase + SM_TPROJ + dstbuf * 1024 + tid * 16, tp4 + t4);
        }
        CP_COMMIT();
    };

    // ---- prologue: first pair into buf 0 ----
    long pair = blockIdx.x;
    int buf = 0;
    if (pair < npairs) ln_prefetch(pair, 0);
    __syncthreads();   // order init smem writes before hoisted invariant loads

    // hoisted loop-invariant head weights
    const int rc = lane & 7;
    const float4 w2road = *(const float4*)(w2_s + 64 + rc * 4);
    float2 w2sc[2][2];
    #pragma unroll
    for (int pi = 0; pi < 2; pi++)
        #pragma unroll
        for (int sub = 0; sub < 2; sub++)
            w2sc[pi][sub] = *(const float2*)(w2_s + (4 * hd + 2 * pi + sub) * 8 + k0);

    for (; pair < npairs; pair += gridDim.x, buf ^= 1) {
        const float* tpb = (const float*)(smem + SM_TPROJ + buf * 1024);

        CP_WAIT_ALL();
        __syncthreads();   // AH(buf)/tproj(buf) ready; prev heads done with P_s

        const int nrows = (int)((long)B * 54 - pair * 108 >= 108 ? 108 : (long)B * 54 - pair * 108);

        // ---- A fragments via ldmatrix (from AH[buf]) ----
        uint32_t afh[2][3][4];
        {
            const uint32_t ab = abase0 + (uint32_t)(buf * ABUF);
            #pragma unroll
            for (int t = 0; t < 2; t++) {
                #pragma unroll
                for (int ks = 0; ks < 3; ks++) {
                    LDSM_X4(afh[t][ks][0], afh[t][ks][1], afh[t][ks][2], afh[t][ks][3],
                            ab + (uint32_t)(t * 1792 + ks * 32));
                }
            }
        }

        // ---- prefetch next pair into buf^1 (hides under MMA) ----
        {
            long nxt = pair + gridDim.x;
            if (nxt < npairs) ln_prefetch(nxt, buf ^ 1);
        }

        float sacc[4] = {0.f, 0.f, 0.f, 0.f};

        // nt pairs: hd=0 -> (0,1),(2,3),(8,9),(10,11),(12,13);
        //           hd=1 -> (4,5),(6,7),(14,15),(16,17),(18,19)
        #pragma unroll
        for (int pi = 0; pi < 5; pi++) {
            const int ntA = (pi < 2) ? (4 * hd + 2 * pi) : (8 + 6 * hd + 2 * (pi - 2));
            uint32_t c2h[4];
            LDSM_X4_NV(c2h[0], c2h[1], c2h[2], c2h[3], wpbase0 + ntA * 896);

            #pragma unroll
            for (int sub = 0; sub < 2; sub++) {
                const int nt = ntA + sub;
                uint32_t bh[4];
                LDSM_X4_NV(bh[0], bh[1], bh[2], bh[3], wx4base0 + nt * 896);
                const uint32_t bh2a = c2h[2 * sub], bh2b = c2h[2 * sub + 1];

                float acc[2][4] = {{0.f, 0.f, 0.f, 0.f}, {0.f, 0.f, 0.f, 0.f}};
                #pragma unroll
                for (int t = 0; t < 2; t++) {
                    mma16816(acc[t], afh[t][0], bh[0], bh[1]);
                    mma16816(acc[t], afh[t][1], bh[2], bh[3]);
                    mma16816(acc[t], afh[t][2], bh2a, bh2b);
                }
                const int col = nt * 8 + k0;
                if (pi < 2) {
                    float w2a = w2sc[pi][sub].x, w2b = w2sc[pi][sub].y;
                    #pragma unroll
                    for (int s = 0; s < 4; s++) {
                        float2 tpv = *(const float2*)(tpb + tpoff[s] + col);
                        float v0 = acc[s >> 1][2 * (s & 1)];
                        float v1 = acc[s >> 1][2 * (s & 1) + 1];
                        sacc[s] += mishf(v0 + tpv.x) * w2a + mishf(v1 + tpv.y) * w2b;
                    }
                } else {
                    #pragma unroll
                    for (int s = 0; s < 4; s++) {
                        int r = rown[s];
                        if (r < 108)
                            *(float2*)(P_s + r * 100 + (col - 64)) =
                                make_float2(acc[s >> 1][2 * (s & 1)], acc[s >> 1][2 * (s & 1) + 1]);
                    }
                }
            }
        }

        // sett/city finalize
        {
            #pragma unroll
            for (int s = 0; s < 4; s++) {
                sacc[s] += __shfl_xor_sync(0xffffffffu, sacc[s], 1);
                sacc[s] += __shfl_xor_sync(0xffffffffu, sacc[s], 2);
            }
            if ((lane & 3) == 0) {
                #pragma unroll
                for (int s = 0; s < 4; s++) {
                    int r = rown[s];
                    if (r < nrows) {
                        int bl = (r >= 54) ? 1 : 0;
                        int n = r - 54 * bl;
                        out[((size_t)(pair * 2 + bl)) * 397 + 5 + 54 * hd + n] = sacc[s] + b2_s[hd];
                    }
                }
            }
        }
        __syncthreads();

        const int nb = (nrows > 54) ? 2 : 1;
        const int sub = lane >> 3;
        // ---- road heads: 4 edges per warp-task, float4 cols ----
        for (int t = wid; t < nb * 18; t += 8) {
            int bl = (t >= 18) ? 1 : 0;
            int tg = t - 18 * bl;
            int e = tg * 4 + sub;
            int sN = rp_s[2 * e], dN = rp_s[2 * e + 1];
            float4 tpv = *(const float4*)(tpb + bl * 128 + 64 + rc * 4);
            float4 Psv = *(const float4*)(P_s + (bl * 54 + sN) * 100 + rc * 4);
            float4 Pdv = *(const float4*)(P_s + (bl * 54 + dN) * 100 + 32 + rc * 4);
            float part = mishf(tpv.x + Psv.x + Pdv.x) * w2road.x
                       + mishf(tpv.y + Psv.y + Pdv.y) * w2road.y
                       + mishf(tpv.z + Psv.z + Pdv.z) * w2road.z
                       + mishf(tpv.w + Psv.w + Pdv.w) * w2road.w;
            part += __shfl_xor_sync(0xffffffffu, part, 1);
            part += __shfl_xor_sync(0xffffffffu, part, 2);
            part += __shfl_xor_sync(0xffffffffu, part, 4);
            if (rc == 0) out[((size_t)(pair * 2 + bl)) * 397 + 113 + e] = part + b2_s[2];
        }
        // ---- robber heads: 4 tiles per warp-task, float4 cols ----
        for (int t = wid; t < nb * 5; t += 8) {
            int bl = (t >= 5) ? 1 : 0;
            int tg = t - 5 * bl;
            int tile = tg * 4 + sub;
            bool valid = tile < 19;
            int tix = valid ? tile : 0;
            float4 a = make_float4(0.f, 0.f, 0.f, 0.f);
            #pragma unroll
            for (int i = 0; i < 6; i++) {
                const float4 p = *(const float4*)(P_s + (bl * 54 + ti_s[tix * 6 + i]) * 100 + 64 + rc * 4);
                a.x += p.x; a.y += p.y; a.z += p.z; a.w += p.w;
            }
            float4 tpv = *(const float4*)(tpb + bl * 128 + 96 + rc * 4);
            float m0 = mishf(tpv.x + a.x * (1.f / 6.f));
            float m1 = mishf(tpv.y + a.y * (1.f / 6.f));
            float m2 = mishf(tpv.z + a.z * (1.f / 6.f));
            float m3 = mishf(tpv.w + a.w * (1.f / 6.f));
            #pragma unroll
            for (int o = 0; o < 5; o++) {
                float4 rv = *(const float4*)(rob2_s + o * 32 + rc * 4);
                float part = m0 * rv.x + m1 * rv.y + m2 * rv.z + m3 * rv.w;
                part += __shfl_xor_sync(0xffffffffu, part, 1);
                part += __shfl_xor_sync(0xffffffffu, part, 2);
                part += __shfl_xor_sync(0xffffffffu, part, 4);
                if (rc == 0 && valid)
                    out[((size_t)(pair * 2 + bl)) * 397 + 185 + tile * 5 + o] = part + b2_s[3 + o];
            }
        }
        // (no end barrier: next iteration's top barrier protects P_s/tproj/AH)
    }
}

// ------------------------------ K3: BN + mish + gfc2, 8-row batched ------------------------------
__global__ __launch_bounds__(128) void k3(const float* __restrict__ gfc2_w,
                                          const float* __restrict__ gfc2_b,
                                          float* __restrict__ out, int B) {
    __shared__ __align__(16) float m8[80 * 8];
    __shared__ __align__(16) float Wg[80 * 122];
    __shared__ float bs[122];
    __shared__ float sc[80], sh[80];
    int tid = threadIdx.x;
    for (int i = tid; i < 80 * 122; i += 128) {
        int k = i / 122, t = i % 122;
        int r = (t < 5) ? t : (275 + t);
        Wg[i] = gfc2_w[r * 80 + k];
    }
    if (tid < 122) { int r = (tid < 5) ? tid : (275 + tid); bs[tid] = gfc2_b[r]; }
    if (tid < 80) { sc[tid] = d_bnscale[tid]; sh[tid] = d_bnshift[tid]; }
    __syncthreads();
    int nq = (B + 7) >> 3;
    for (int qb = blockIdx.x; qb < nq; qb += gridDim.x) {
        if (tid < 80) {
            #pragma unroll
            for (int rb = 0; rb < 8; rb++) {
                int b = qb * 8 + rb;
                float v = (b < B) ? d_h[(size_t)b * 80 + tid] : 0.f;
                m8[tid * 8 + rb] = mishf(v * sc[tid] + sh[tid]);
            }
        }
        __syncthreads();
        if (tid < 122) {
            float a[8];
            #pragma unroll
            for (int rb = 0; rb < 8; rb++) a[rb] = bs[tid];
            for (int k = 0; k < 80; k++) {
                float4 mA = *(const float4*)(m8 + k * 8);
                float4 mB = *(const float4*)(m8 + k * 8 + 4);
                float w = Wg[k * 122 + tid];
                a[0] += mA.x * w; a[1] += mA.y * w; a[2] += mA.z * w; a[3] += mA.w * w;
                a[4] += mB.x * w; a[5] += mB.y * w; a[6] += mB.z * w; a[7] += mB.w * w;
            }
            int col = (tid < 5) ? tid : (275 + tid);
            #pragma unroll
            for (int rb = 0; rb < 8; rb++) {
                int b = qb * 8 + rb;
                if (b < B) out[(size_t)b * 397 + col] = a[rb];
            }
        }
        __syncthreads();
    }
}

// ------------------------------ launch ------------------------------
extern "C" void kernel_launch(void* const* d_in, const int* in_sizes, int n_in,
                              void* d_out, int out_size) {
    const float* trunk      = (const float*)d_in[0];
    const float* node_emb   = (const float*)d_in[1];
    const int*   road_pairs = (const int*)d_in[2];
    const int*   tile_nodes = (const int*)d_in[3];
    const float* ln_t_w = (const float*)d_in[4];
    const float* ln_t_b = (const float*)d_in[5];
    const float* ln_n_w = (const float*)d_in[6];
    const float* ln_n_b = (const float*)d_in[7];
    const float* gfc1_w = (const float*)d_in[8];
    const float* gfc1_b = (const float*)d_in[9];
    const float* bn_w   = (const float*)d_in[10];
    const float* bn_b   = (const float*)d_in[11];
    const float* gfc2_w = (const float*)d_in[12];
    const float* gfc2_b = (const float*)d_in[13];
    const float* sett1_w = (const float*)d_in[14];
    const float* sett1_b = (const float*)d_in[15];
    const float* sett2_w = (const float*)d_in[16];
    const float* sett2_b = (const float*)d_in[17];
    const float* city1_w = (const float*)d_in[18];
    const float* city1_b = (const float*)d_in[19];
    const float* city2_w = (const float*)d_in[20];
    const float* city2_b = (const float*)d_in[21];
    const float* road1_w = (const float*)d_in[22];
    const float* road1_b = (const float*)d_in[23];
    const float* road2_w = (const float*)d_in[24];
    const float* road2_b = (const float*)d_in[25];
    const float* rob1_w = (const float*)d_in[26];
    const float* rob1_b = (const float*)d_in[27];
    const float* rob2_w = (const float*)d_in[28];
    const float* rob2_b = (const float*)d_in[29];

    int B = in_sizes[0] / 80;
    if (B > BMAX) B = BMAX;
    float* out = (float*)d_out;
    int nblk1 = (B + 127) / 128;

    cudaFuncSetAttribute(k1, cudaFuncAttributeMaxDynamicSharedMemorySize, K1_SMEM);
    cudaFuncSetAttribute(k2, cudaFuncAttributeMaxDynamicSharedMemorySize, SM_TOTAL);

    k_prep<<<(208 * 80 + 255) / 256, 256>>>(sett1_w, city1_w, road1_w, rob1_w, gfc1_w,
                                            sett1_b, city1_b, road1_b, rob1_b, gfc1_b,
                                            ln_n_w, ln_n_b);
    k1<<<nblk1, 512, K1_SMEM>>>(trunk, ln_t_w, ln_t_b, B);
    k_bn<<<1, 80>>>(bn_w, bn_b, B, nblk1);
    k2<<<K2_GRID, 256, SM_TOTAL>>>(node_emb, road_pairs, tile_nodes,
                                   sett2_w, sett2_b, city2_w, city2_b,
                                   road2_w, road2_b, rob2_w, rob2_b, out, B);
    k3<<<K3_GRID, 128>>>(gfc2_w, gfc2_b, out, B);
}

// round 17
// speedup vs baseline: 1.6636x; 1.0175x over previous
#include <cuda_runtime.h>
#include <cuda_fp16.h>
#include <cstdint>
#include <cstddef>

// ---------------------------------------------------------------------------
// SmallSpatialPolicyHead — R16 + k1: pure fp16 trunk GEMM (compensation terms
// dropped; same validated precision trade as k2 — quadrature rel_err ~1.3e-4).
// ---------------------------------------------------------------------------

#define BMAX 16384
#define K2_GRID 296
#define K3_GRID 592

__device__ float d_tb[208];
__device__ __half d_Wh[160 * 48];    // k2 node proj [n][k] (lnw-scaled, fp16)
__device__ __half d_Wth[208 * 80];   // k1 trunk proj [o][k] (fp16)
__device__ float d_tproj[(size_t)BMAX * 128];
__device__ float d_h[(size_t)BMAX * 80];
__device__ float d_partial[296 * 160];
__device__ float d_bnscale[80];
__device__ float d_bnshift[80];

// ---- k2 smem byte offsets ----
#define SM_XP    0             // P_s 108x100 f = 43200
#define SM_AH    43200         // 2 x (128x56 fp16 = 14336), double buffer
#define ABUF     14336
#define SM_WH    71872         // 160x56 fp16 = 17920
#define SM_TPROJ 89792         // 2 x 256 f (double buffer)
#define SM_W2    91840         // 96 f
#define SM_ROB2  92224         // 160 f
#define SM_B2    92864         // 8 f
#define SM_RP    92896         // 144 i
#define SM_TI    93472         // 114 i
#define SM_TOTAL 93928

// ---- k1 smem byte offsets ----
#define X1_XS    0             // 128x84 f = 43008 (reused as hs)
#define X1_AH    43008         // 128x88 fp16 = 22528
#define X1_WH    65536         // 208x88 fp16 = 36608
#define X1_TB    102144        // 208 f
#define X1_LNW   102976        // 80 f
#define X1_LNB   103296        // 80 f
#define K1_SMEM  103616

__device__ __forceinline__ uint32_t smem_u32(const void* p) {
    uint32_t a;
    asm("{ .reg .u64 t; cvta.to.shared.u64 t, %1; cvt.u32.u64 %0, t; }" : "=r"(a) : "l"(p));
    return a;
}
__device__ __forceinline__ void cp16(uint32_t dst, const void* src) {
    asm volatile("cp.async.cg.shared.global [%0], [%1], 16;" :: "r"(dst), "l"(src));
}
#define CP_COMMIT() asm volatile("cp.async.commit_group;" ::: "memory")
#define CP_WAIT_ALL() asm volatile("cp.async.wait_group 0;" ::: "memory")
#define CP_COMMIT_WAIT() do { CP_COMMIT(); CP_WAIT_ALL(); } while (0)

#define LDSM_X4(r0,r1,r2,r3,addr) \
    asm volatile("ldmatrix.sync.aligned.m8n8.x4.shared.b16 {%0,%1,%2,%3}, [%4];" \
        : "=r"(r0),"=r"(r1),"=r"(r2),"=r"(r3) : "r"(addr))
#define LDSM_X2(r0,r1,addr) \
    asm volatile("ldmatrix.sync.aligned.m8n8.x2.shared.b16 {%0,%1}, [%2];" \
        : "=r"(r0),"=r"(r1) : "r"(addr))
#define LDSM_X4_NV(r0,r1,r2,r3,addr) \
    asm("ldmatrix.sync.aligned.m8n8.x4.shared.b16 {%0,%1,%2,%3}, [%4];" \
        : "=r"(r0),"=r"(r1),"=r"(r2),"=r"(r3) : "r"(addr))

__device__ __forceinline__ void mma16816(float* d, const uint32_t* a, uint32_t b0, uint32_t b1) {
    asm volatile(
        "mma.sync.aligned.m16n8k16.row.col.f32.f16.f16.f32 "
        "{%0,%1,%2,%3},{%4,%5,%6,%7},{%8,%9},{%0,%1,%2,%3};"
        : "+f"(d[0]), "+f"(d[1]), "+f"(d[2]), "+f"(d[3])
        : "r"(a[0]), "r"(a[1]), "r"(a[2]), "r"(a[3]), "r"(b0), "r"(b1));
}

__device__ __forceinline__ float mishf(float x) {
    float u = __expf(fminf(x, 15.f));
    float d = __fmaf_rn(u, u + 2.f, 2.f);
    return x - __fdividef(2.f * x, d);
}
__device__ __forceinline__ float warp_sum(float v) {
    #pragma unroll
    for (int o = 16; o; o >>= 1) v += __shfl_xor_sync(0xffffffffu, v, o);
    return v;
}

// ------------------------------ prep ------------------------------
__global__ void k_prep(const float* __restrict__ sett1_w, const float* __restrict__ city1_w,
                       const float* __restrict__ road1_w, const float* __restrict__ rob1_w,
                       const float* __restrict__ gfc1_w,
                       const float* __restrict__ sett1_b, const float* __restrict__ city1_b,
                       const float* __restrict__ road1_b, const float* __restrict__ rob1_b,
                       const float* __restrict__ gfc1_b,
                       const float* __restrict__ ln_n_w, const float* __restrict__ ln_n_b) {
    int i = blockIdx.x * blockDim.x + threadIdx.x;
    if (i < 160 * 48) {          // node-proj W' = lnw * W (fp16)
        int j = i / 48, k = i % 48;
        float v;
        if (j < 32)       v = sett1_w[j * 128 + 80 + k];
        else if (j < 64)  v = city1_w[(j - 32) * 128 + 80 + k];
        else if (j < 96)  v = road1_w[(j - 64) * 176 + 80 + k];
        else if (j < 128) v = road1_w[(j - 96) * 176 + 128 + k];
        else              v = rob1_w[(j - 128) * 128 + 80 + k];
        d_Wh[i] = __float2half(v * ln_n_w[k]);
    }
    if (i < 208 * 80) {          // k1 trunk proj (fp16)
        int o = i / 80, k = i % 80;
        float v;
        if (o < 32)       v = sett1_w[o * 128 + k];
        else if (o < 64)  v = city1_w[(o - 32) * 128 + k];
        else if (o < 96)  v = road1_w[(o - 64) * 176 + k];
        else if (o < 128) v = rob1_w[(o - 96) * 128 + k];
        else              v = gfc1_w[(o - 128) * 80 + k];
        d_Wth[i] = __float2half(v);
    }
    if (i < 208) {               // first-layer biases + folded LN-bias bP terms
        float v;
        if (i < 32) {
            v = sett1_b[i];
            for (int c = 0; c < 48; c++) v += ln_n_b[c] * sett1_w[i * 128 + 80 + c];
        } else if (i < 64) {
            v = city1_b[i - 32];
            for (int c = 0; c < 48; c++) v += ln_n_b[c] * city1_w[(i - 32) * 128 + 80 + c];
        } else if (i < 96) {
            v = road1_b[i - 64];
            for (int c = 0; c < 48; c++)
                v += ln_n_b[c] * (road1_w[(i - 64) * 176 + 80 + c] +
                                  road1_w[(i - 64) * 176 + 128 + c]);
        } else if (i < 128) {
            v = rob1_b[i - 96];
            for (int c = 0; c < 48; c++) v += ln_n_b[c] * rob1_w[(i - 96) * 128 + 80 + c];
        } else {
            v = gfc1_b[i - 128];
        }
        d_tb[i] = v;
    }
}

// ------------------------------ K1: pure-fp16 HMMA trunk kernel ------------------------------
__global__ __launch_bounds__(512, 1) void k1(const float* __restrict__ trunk,
                                             const float* __restrict__ ln_t_w,
                                             const float* __restrict__ ln_t_b, int B) {
    extern __shared__ char smem[];
    const uint32_t sbase = smem_u32(smem);
    const int tid = threadIdx.x, wid = tid >> 5, lane = tid & 31;

    float* xs  = (float*)(smem + X1_XS);
    float* hs  = (float*)(smem + X1_XS);
    float* tb_s = (float*)(smem + X1_TB);
    float* lnw = (float*)(smem + X1_LNW);
    float* lnb = (float*)(smem + X1_LNB);

    for (int i = tid; i < 208 * 80; i += 512) {
        int o = i / 80, k = i % 80;
        *(__half*)(smem + X1_WH + (o * 88 + k) * 2) = d_Wth[i];
    }
    for (int i = tid; i < 208; i += 512) tb_s[i] = d_tb[i];
    if (tid < 80) { lnw[tid] = ln_t_w[tid]; lnb[tid] = ln_t_b[tid]; }

    const int rows_valid = min(128, B - (int)blockIdx.x * 128);

    {
        const float4* tr4 = (const float4*)trunk;
        size_t base4 = (size_t)blockIdx.x * 2560;
        #pragma unroll
        for (int q = 0; q < 5; q++) {
            int il = tid + q * 512;
            int row = il / 20, c = il % 20;
            if (row < rows_valid)
                cp16(sbase + X1_XS + (uint32_t)((row * 84 + 4 * c) * 4), tr4 + base4 + il);
        }
        CP_COMMIT_WAIT();
    }
    __syncthreads();

    if (tid < 256) {
        const int r = tid >> 1, h = tid & 1;
        float4 v[10];
        if (r < rows_valid) {
            const float4* xr = (const float4*)(xs + r * 84 + h * 40);
            #pragma unroll
            for (int j = 0; j < 10; j++) v[j] = xr[j];
        } else {
            #pragma unroll
            for (int j = 0; j < 10; j++) v[j] = make_float4(0.f, 0.f, 0.f, 0.f);
        }
        float s = 0.f, q = 0.f;
        #pragma unroll
        for (int j = 0; j < 10; j++) {
            s += v[j].x + v[j].y + v[j].z + v[j].w;
            q += v[j].x * v[j].x + v[j].y * v[j].y + v[j].z * v[j].z + v[j].w * v[j].w;
        }
        s += __shfl_xor_sync(0xffffffffu, s, 1);
        q += __shfl_xor_sync(0xffffffffu, q, 1);
        float mu = s * (1.f / 80.f);
        float is = rsqrtf(q * (1.f / 80.f) - mu * mu + 1e-5f);
        char* dh = smem + X1_AH + (r * 88 + h * 40) * 2;
        const float4* lw4 = (const float4*)(lnw + h * 40);
        const float4* lb4 = (const float4*)(lnb + h * 40);
        #pragma unroll
        for (int j = 0; j < 10; j++) {
            float4 w = lw4[j], b = lb4[j];
            float a0 = (v[j].x - mu) * is * w.x + b.x;
            float a1 = (v[j].y - mu) * is * w.y + b.y;
            float a2 = (v[j].z - mu) * is * w.z + b.z;
            float a3 = (v[j].w - mu) * is * w.w + b.w;
            if (r >= rows_valid) { a0 = a1 = a2 = a3 = 0.f; }
            __half2 h01 = __floats2half2_rn(a0, a1), h23 = __floats2half2_rn(a2, a3);
            uint2 uh; uh.x = *(uint32_t*)&h01; uh.y = *(uint32_t*)&h23;
            *(uint2*)(dh + j * 8) = uh;
        }
    }
    __syncthreads();

    {
        const int mt = wid & 7, nh = wid >> 3;
        const int g = lane >> 2, k0 = (lane & 3) * 2;
        const uint32_t abase = sbase + X1_AH +
            (uint32_t)((mt * 16 + (lane & 15)) * 176 + (lane >> 4) * 16);
        uint32_t ah[5][4];
        #pragma unroll
        for (int ks = 0; ks < 5; ks++)
            LDSM_X4(ah[ks][0], ah[ks][1], ah[ks][2], ah[ks][3], abase + ks * 32);

        uint32_t wx4 = sbase + X1_WH +
            (uint32_t)((lane & 7) * 176 + (lane >> 3) * 16) + (uint32_t)(nh * 13 * 1408);
        uint32_t wx2 = sbase + X1_WH +
            (uint32_t)((lane & 7) * 176 + ((lane >> 3) & 1) * 16 + 128) + (uint32_t)(nh * 13 * 1408);

        #pragma unroll
        for (int ni = 0; ni < 13; ni++) {
            const int nt = nh * 13 + ni;
            uint32_t bhA[4], bhB[4], bh2[2];
            LDSM_X4(bhA[0], bhA[1], bhA[2], bhA[3], wx4);
            LDSM_X4(bhB[0], bhB[1], bhB[2], bhB[3], wx4 + 64);
            LDSM_X2(bh2[0], bh2[1], wx2);

            float acc[4] = {0.f, 0.f, 0.f, 0.f};
            mma16816(acc, ah[0], bhA[0], bhA[1]);
            mma16816(acc, ah[1], bhA[2], bhA[3]);
            mma16816(acc, ah[2], bhB[0], bhB[1]);
            mma16816(acc, ah[3], bhB[2], bhB[3]);
            mma16816(acc, ah[4], bh2[0], bh2[1]);
            wx4 += 1408; wx2 += 1408;

            const int col = nt * 8 + k0;
            const int row0 = mt * 16 + g, row1 = row0 + 8;
            if (col < 128) {
                float b0 = tb_s[col], b1 = tb_s[col + 1];
                if (row0 < rows_valid) {
                    size_t o = (size_t)((size_t)blockIdx.x * 128 + row0) * 128 + col;
                    d_tproj[o] = acc[0] + b0; d_tproj[o + 1] = acc[1] + b1;
                }
                if (row1 < rows_valid) {
                    size_t o = (size_t)((size_t)blockIdx.x * 128 + row1) * 128 + col;
                    d_tproj[o] = acc[2] + b0; d_tproj[o + 1] = acc[3] + b1;
                }
            } else {
                const int ch = col - 128;
                hs[row0 * 84 + ch] = acc[0]; hs[row0 * 84 + ch + 1] = acc[1];
                hs[row1 * 84 + ch] = acc[2]; hs[row1 * 84 + ch + 1] = acc[3];
                if (row0 < rows_valid) {
                    size_t o = (size_t)((size_t)blockIdx.x * 128 + row0) * 80 + ch;
                    d_h[o] = acc[0]; d_h[o + 1] = acc[1];
                }
                if (row1 < rows_valid) {
                    size_t o = (size_t)((size_t)blockIdx.x * 128 + row1) * 80 + ch;
                    d_h[o] = acc[2]; d_h[o + 1] = acc[3];
                }
            }
        }
    }
    __syncthreads();

    if (tid < 80) {
        float s1 = 0.f, s2 = 0.f;
        for (int r = 0; r < rows_valid; r++) {
            float v = hs[r * 84 + tid];
            s1 += v; s2 += v * v;
        }
        d_partial[blockIdx.x * 160 + tid] = s1;
        d_partial[blockIdx.x * 160 + 80 + tid] = s2;
    }
}

// ------------------------------ BN finalize ------------------------------
__global__ void k_bn(const float* __restrict__ bn_w, const float* __restrict__ bn_b,
                     int B, int nblk) {
    int t = threadIdx.x;
    if (t >= 80) return;
    float S1 = 0.f, S2 = 0.f;
    for (int blk = 0; blk < nblk; blk++) {
        S1 += d_partial[blk * 160 + t];
        S2 += d_partial[blk * 160 + 80 + t];
    }
    float invB = 1.f / (float)B;
    float mu = S1 * invB;
    float var = S2 * invB - mu * mu;
    float sc = bn_w[t] * rsqrtf(var + 1e-5f);
    d_bnscale[t] = sc;
    d_bnshift[t] = bn_b[t] - mu * sc;
}

// ------------------------------ K2: pure-fp16 HMMA fused node kernel (R16, proven) ------------------------------
__global__ __launch_bounds__(256, 2) void k2(const float* __restrict__ node_emb,
                                             const int* __restrict__ road_pairs,
                                             const int* __restrict__ tile_nodes,
                                             const float* __restrict__ sett2_w, const float* __restrict__ sett2_b,
                                             const float* __restrict__ city2_w, const float* __restrict__ city2_b,
                                             const float* __restrict__ road2_w, const float* __restrict__ road2_b,
                                             const float* __restrict__ rob2_w, const float* __restrict__ rob2_b,
                                             float* __restrict__ out, int B) {
    extern __shared__ char smem[];
    const uint32_t sbase = smem_u32(smem);
    const int tid = threadIdx.x, wid = tid >> 5, lane = tid & 31;

    float* P_s     = (float*)(smem + SM_XP);   // rows x 100 = P cols 64:160
    float* w2_s    = (float*)(smem + SM_W2);
    float* rob2_s  = (float*)(smem + SM_ROB2);
    float* b2_s    = (float*)(smem + SM_B2);
    int*   rp_s    = (int*)(smem + SM_RP);
    int*   ti_s    = (int*)(smem + SM_TI);

    for (int i = tid; i < 160 * 48; i += 256) {
        int n = i / 48, k = i % 48;
        *(__half*)(smem + SM_WH + (n * 56 + k) * 2) = d_Wh[i];
    }
    if (tid < 32) { w2_s[tid] = sett2_w[tid]; w2_s[32 + tid] = city2_w[tid]; w2_s[64 + tid] = road2_w[tid]; }
    if (tid < 160) rob2_s[tid] = rob2_w[tid];
    if (tid == 0) { b2_s[0] = sett2_b[0]; b2_s[1] = city2_b[0]; b2_s[2] = road2_b[0]; }
    if (tid < 5) b2_s[3 + tid] = rob2_b[tid];
    if (tid < 144) rp_s[tid] = road_pairs[tid];
    if (tid < 114) ti_s[tid] = tile_nodes[tid];

    const int g = lane >> 2;
    const int k0 = (lane & 3) * 2;
    const int mrow = (wid & 3) * 32;
    const int hd = wid >> 2;              // 0 = sett group, 1 = city group

    int rown[4]; int tpoff[4];
    #pragma unroll
    for (int s = 0; s < 4; s++) {
        rown[s] = mrow + 16 * (s >> 1) + 8 * (s & 1) + g;
        tpoff[s] = (rown[s] >= 54) ? 128 : 0;
    }

    const uint32_t wx4base0 = sbase + SM_WH +
        (uint32_t)((lane & 7) * 112 + (lane >> 3) * 16);
    const uint32_t wpbase0 = sbase + SM_WH +
        (uint32_t)((lane & 7) * 112 + ((lane >> 3) & 1) * 16 + 64 + ((lane >> 4) & 1) * 896);
    const uint32_t abase0 = sbase + SM_AH +
        (uint32_t)((mrow + (lane & 15)) * 112 + (lane >> 4) * 16);

    const long npairs = ((long)B + 1) / 2;
    const size_t totp4 = (size_t)B * 32;
    const float4* tp4 = (const float4*)d_tproj;

    // ---- fused LN prefetch: row -> fp16 A tile, A' = (x-mu)*is ----
    auto ln_prefetch = [&](long p, int dstbuf) {
        const int nr = (int)((long)B * 54 - p * 108 >= 108 ? 108 : (long)B * 54 - p * 108);
        if (tid < nr) {
            const float4* xr = (const float4*)(node_emb + ((size_t)p * 108 + tid) * 48);
            float4 v[12];
            #pragma unroll
            for (int j = 0; j < 12; j++) v[j] = xr[j];
            float s = 0.f, q = 0.f;
            #pragma unroll
            for (int j = 0; j < 12; j++) {
                s += v[j].x + v[j].y + v[j].z + v[j].w;
                q += v[j].x * v[j].x + v[j].y * v[j].y + v[j].z * v[j].z + v[j].w * v[j].w;
            }
            float mu = s * (1.f / 48.f);
            float is = rsqrtf(q * (1.f / 48.f) - mu * mu + 1e-5f);
            char* dst = smem + SM_AH + dstbuf * ABUF + tid * 112;
            #pragma unroll
            for (int j = 0; j < 6; j++) {
                float4 va = v[2 * j], vb = v[2 * j + 1];
                __half2 h01 = __floats2half2_rn((va.x - mu) * is, (va.y - mu) * is);
                __half2 h23 = __floats2half2_rn((va.z - mu) * is, (va.w - mu) * is);
                __half2 h45 = __floats2half2_rn((vb.x - mu) * is, (vb.y - mu) * is);
                __half2 h67 = __floats2half2_rn((vb.z - mu) * is, (vb.w - mu) * is);
                uint4 uh; uh.x = *(uint32_t*)&h01; uh.y = *(uint32_t*)&h23;
                uh.z = *(uint32_t*)&h45; uh.w = *(uint32_t*)&h67;
                *(uint4*)(dst + j * 16) = uh;
            }
        }
        if (tid < 64) {
            size_t t4 = (size_t)p * 64 + tid;
            if (t4 < totp4) cp16(sbase + SM_TPROJ + dstbuf * 1024 + tid * 16, tp4 + t4);
        }
        CP_COMMIT();
    };

    // ---- prologue: first pair into buf 0 ----
    long pair = blockIdx.x;
    int buf = 0;
    if (pair < npairs) ln_prefetch(pair, 0);
    __syncthreads();   // order init smem writes before hoisted invariant loads

    // hoisted loop-invariant head weights
    const int rc = lane & 7;
    const float4 w2road = *(const float4*)(w2_s + 64 + rc * 4);
    float2 w2sc[2][2];
    #pragma unroll
    for (int pi = 0; pi < 2; pi++)
        #pragma unroll
        for (int sub = 0; sub < 2; sub++)
            w2sc[pi][sub] = *(const float2*)(w2_s + (4 * hd + 2 * pi + sub) * 8 + k0);

    for (; pair < npairs; pair += gridDim.x, buf ^= 1) {
        const float* tpb = (const float*)(smem + SM_TPROJ + buf * 1024);

        CP_WAIT_ALL();
        __syncthreads();   // AH(buf)/tproj(buf) ready; prev heads done with P_s

        const int nrows = (int)((long)B * 54 - pair * 108 >= 108 ? 108 : (long)B * 54 - pair * 108);

        // ---- A fragments via ldmatrix (from AH[buf]) ----
        uint32_t afh[2][3][4];
        {
            const uint32_t ab = abase0 + (uint32_t)(buf * ABUF);
            #pragma unroll
            for (int t = 0; t < 2; t++) {
                #pragma unroll
                for (int ks = 0; ks < 3; ks++) {
                    LDSM_X4(afh[t][ks][0], afh[t][ks][1], afh[t][ks][2], afh[t][ks][3],
                            ab + (uint32_t)(t * 1792 + ks * 32));
                }
            }
        }

        // ---- prefetch next pair into buf^1 (hides under MMA) ----
        {
            long nxt = pair + gridDim.x;
            if (nxt < npairs) ln_prefetch(nxt, buf ^ 1);
        }

        float sacc[4] = {0.f, 0.f, 0.f, 0.f};

        // nt pairs: hd=0 -> (0,1),(2,3),(8,9),(10,11),(12,13);
        //           hd=1 -> (4,5),(6,7),(14,15),(16,17),(18,19)
        #pragma unroll
        for (int pi = 0; pi < 5; pi++) {
            const int ntA = (pi < 2) ? (4 * hd + 2 * pi) : (8 + 6 * hd + 2 * (pi - 2));
            uint32_t c2h[4];
            LDSM_X4_NV(c2h[0], c2h[1], c2h[2], c2h[3], wpbase0 + ntA * 896);

            #pragma unroll
            for (int sub = 0; sub < 2; sub++) {
                const int nt = ntA + sub;
                uint32_t bh[4];
                LDSM_X4_NV(bh[0], bh[1], bh[2], bh[3], wx4base0 + nt * 896);
                const uint32_t bh2a = c2h[2 * sub], bh2b = c2h[2 * sub + 1];

                float acc[2][4] = {{0.f, 0.f, 0.f, 0.f}, {0.f, 0.f, 0.f, 0.f}};
                #pragma unroll
                for (int t = 0; t < 2; t++) {
                    mma16816(acc[t], afh[t][0], bh[0], bh[1]);
                    mma16816(acc[t], afh[t][1], bh[2], bh[3]);
                    mma16816(acc[t], afh[t][2], bh2a, bh2b);
                }
                const int col = nt * 8 + k0;
                if (pi < 2) {
                    float w2a = w2sc[pi][sub].x, w2b = w2sc[pi][sub].y;
                    #pragma unroll
                    for (int s = 0; s < 4; s++) {
                        float2 tpv = *(const float2*)(tpb + tpoff[s] + col);
                        float v0 = acc[s >> 1][2 * (s & 1)];
                        float v1 = acc[s >> 1][2 * (s & 1) + 1];
                        sacc[s] += mishf(v0 + tpv.x) * w2a + mishf(v1 + tpv.y) * w2b;
                    }
                } else {
                    #pragma unroll
                    for (int s = 0; s < 4; s++) {
                        int r = rown[s];
                        if (r < 108)
                            *(float2*)(P_s + r * 100 + (col - 64)) =
                                make_float2(acc[s >> 1][2 * (s & 1)], acc[s >> 1][2 * (s & 1) + 1]);
                    }
                }
            }
        }

        // sett/city finalize
        {
            #pragma unroll
            for (int s = 0; s < 4; s++) {
                sacc[s] += __shfl_xor_sync(0xffffffffu, sacc[s], 1);
                sacc[s] += __shfl_xor_sync(0xffffffffu, sacc[s], 2);
            }
            if ((lane & 3) == 0) {
                #pragma unroll
                for (int s = 0; s < 4; s++) {
                    int r = rown[s];
                    if (r < nrows) {
                        int bl = (r >= 54) ? 1 : 0;
                        int n = r - 54 * bl;
                        out[((size_t)(pair * 2 + bl)) * 397 + 5 + 54 * hd + n] = sacc[s] + b2_s[hd];
                    }
                }
            }
        }
        __syncthreads();

        const int nb = (nrows > 54) ? 2 : 1;
        const int sub = lane >> 3;
        // ---- road heads: 4 edges per warp-task, float4 cols ----
        for (int t = wid; t < nb * 18; t += 8) {
            int bl = (t >= 18) ? 1 : 0;
            int tg = t - 18 * bl;
            int e = tg * 4 + sub;
            int sN = rp_s[2 * e], dN = rp_s[2 * e + 1];
            float4 tpv = *(const float4*)(tpb + bl * 128 + 64 + rc * 4);
            float4 Psv = *(const float4*)(P_s + (bl * 54 + sN) * 100 + rc * 4);
            float4 Pdv = *(const float4*)(P_s + (bl * 54 + dN) * 100 + 32 + rc * 4);
            float part = mishf(tpv.x + Psv.x + Pdv.x) * w2road.x
                       + mishf(tpv.y + Psv.y + Pdv.y) * w2road.y
                       + mishf(tpv.z + Psv.z + Pdv.z) * w2road.z
                       + mishf(tpv.w + Psv.w + Pdv.w) * w2road.w;
            part += __shfl_xor_sync(0xffffffffu, part, 1);
            part += __shfl_xor_sync(0xffffffffu, part, 2);
            part += __shfl_xor_sync(0xffffffffu, part, 4);
            if (rc == 0) out[((size_t)(pair * 2 + bl)) * 397 + 113 + e] = part + b2_s[2];
        }
        // ---- robber heads: 4 tiles per warp-task, float4 cols ----
        for (int t = wid; t < nb * 5; t += 8) {
            int bl = (t >= 5) ? 1 : 0;
            int tg = t - 5 * bl;
            int tile = tg * 4 + sub;
            bool valid = tile < 19;
            int tix = valid ? tile : 0;
            float4 a = make_float4(0.f, 0.f, 0.f, 0.f);
            #pragma unroll
            for (int i = 0; i < 6; i++) {
                const float4 p = *(const float4*)(P_s + (bl * 54 + ti_s[tix * 6 + i]) * 100 + 64 + rc * 4);
                a.x += p.x; a.y += p.y; a.z += p.z; a.w += p.w;
            }
            float4 tpv = *(const float4*)(tpb + bl * 128 + 96 + rc * 4);
            float m0 = mishf(tpv.x + a.x * (1.f / 6.f));
            float m1 = mishf(tpv.y + a.y * (1.f / 6.f));
            float m2 = mishf(tpv.z + a.z * (1.f / 6.f));
            float m3 = mishf(tpv.w + a.w * (1.f / 6.f));
            #pragma unroll
            for (int o = 0; o < 5; o++) {
                float4 rv = *(const float4*)(rob2_s + o * 32 + rc * 4);
                float part = m0 * rv.x + m1 * rv.y + m2 * rv.z + m3 * rv.w;
                part += __shfl_xor_sync(0xffffffffu, part, 1);
                part += __shfl_xor_sync(0xffffffffu, part, 2);
                part += __shfl_xor_sync(0xffffffffu, part, 4);
                if (rc == 0 && valid)
                    out[((size_t)(pair * 2 + bl)) * 397 + 185 + tile * 5 + o] = part + b2_s[3 + o];
            }
        }
        // (no end barrier: next iteration's top barrier protects P_s/tproj/AH)
    }
}

// ------------------------------ K3: BN + mish + gfc2, 8-row batched ------------------------------
__global__ __launch_bounds__(128) void k3(const float* __restrict__ gfc2_w,
                                          const float* __restrict__ gfc2_b,
                                          float* __restrict__ out, int B) {
    __shared__ __align__(16) float m8[80 * 8];
    __shared__ __align__(16) float Wg[80 * 122];
    __shared__ float bs[122];
    __shared__ float sc[80], sh[80];
    int tid = threadIdx.x;
    for (int i = tid; i < 80 * 122; i += 128) {
        int k = i / 122, t = i % 122;
        int r = (t < 5) ? t : (275 + t);
        Wg[i] = gfc2_w[r * 80 + k];
    }
    if (tid < 122) { int r = (tid < 5) ? tid : (275 + tid); bs[tid] = gfc2_b[r]; }
    if (tid < 80) { sc[tid] = d_bnscale[tid]; sh[tid] = d_bnshift[tid]; }
    __syncthreads();
    int nq = (B + 7) >> 3;
    for (int qb = blockIdx.x; qb < nq; qb += gridDim.x) {
        if (tid < 80) {
            #pragma unroll
            for (int rb = 0; rb < 8; rb++) {
                int b = qb * 8 + rb;
                float v = (b < B) ? d_h[(size_t)b * 80 + tid] : 0.f;
                m8[tid * 8 + rb] = mishf(v * sc[tid] + sh[tid]);
            }
        }
        __syncthreads();
        if (tid < 122) {
            float a[8];
            #pragma unroll
            for (int rb = 0; rb < 8; rb++) a[rb] = bs[tid];
            for (int k = 0; k < 80; k++) {
                float4 mA = *(const float4*)(m8 + k * 8);
                float4 mB = *(const float4*)(m8 + k * 8 + 4);
                float w = Wg[k * 122 + tid];
                a[0] += mA.x * w; a[1] += mA.y * w; a[2] += mA.z * w; a[3] += mA.w * w;
                a[4] += mB.x * w; a[5] += mB.y * w; a[6] += mB.z * w; a[7] += mB.w * w;
            }
            int col = (tid < 5) ? tid : (275 + tid);
            #pragma unroll
            for (int rb = 0; rb < 8; rb++) {
                int b = qb * 8 + rb;
                if (b < B) out[(size_t)b * 397 + col] = a[rb];
            }
        }
        __syncthreads();
    }
}

// ------------------------------ launch ------------------------------
extern "C" void kernel_launch(void* const* d_in, const int* in_sizes, int n_in,
                              void* d_out, int out_size) {
    const float* trunk      = (const float*)d_in[0];
    const float* node_emb   = (const float*)d_in[1];
    const int*   road_pairs = (const int*)d_in[2];
    const int*   tile_nodes = (const int*)d_in[3];
    const float* ln_t_w = (const float*)d_in[4];
    const float* ln_t_b = (const float*)d_in[5];
    const float* ln_n_w = (const float*)d_in[6];
    const float* ln_n_b = (const float*)d_in[7];
    const float* gfc1_w = (const float*)d_in[8];
    const float* gfc1_b = (const float*)d_in[9];
    const float* bn_w   = (const float*)d_in[10];
    const float* bn_b   = (const float*)d_in[11];
    const float* gfc2_w = (const float*)d_in[12];
    const float* gfc2_b = (const float*)d_in[13];
    const float* sett1_w = (const float*)d_in[14];
    const float* sett1_b = (const float*)d_in[15];
    const float* sett2_w = (const float*)d_in[16];
    const float* sett2_b = (const float*)d_in[17];
    const float* city1_w = (const float*)d_in[18];
    const float* city1_b = (const float*)d_in[19];
    const float* city2_w = (const float*)d_in[20];
    const float* city2_b = (const float*)d_in[21];
    const float* road1_w = (const float*)d_in[22];
    const float* road1_b = (const float*)d_in[23];
    const float* road2_w = (const float*)d_in[24];
    const float* road2_b = (const float*)d_in[25];
    const float* rob1_w = (const float*)d_in[26];
    const float* rob1_b = (const float*)d_in[27];
    const float* rob2_w = (const float*)d_in[28];
    const float* rob2_b = (const float*)d_in[29];

    int B = in_sizes[0] / 80;
    if (B > BMAX) B = BMAX;
    float* out = (float*)d_out;
    int nblk1 = (B + 127) / 128;

    cudaFuncSetAttribute(k1, cudaFuncAttributeMaxDynamicSharedMemorySize, K1_SMEM);
    cudaFuncSetAttribute(k2, cudaFuncAttributeMaxDynamicSharedMemorySize, SM_TOTAL);

    k_prep<<<(208 * 80 + 255) / 256, 256>>>(sett1_w, city1_w, road1_w, rob1_w, gfc1_w,
                                            sett1_b, city1_b, road1_b, rob1_b, gfc1_b,
                                            ln_n_w, ln_n_b);
    k1<<<nblk1, 512, K1_SMEM>>>(trunk, ln_t_w, ln_t_b, B);
    k_bn<<<1, 80>>>(bn_w, bn_b, B, nblk1);
    k2<<<K2_GRID, 256, SM_TOTAL>>>(node_emb, road_pairs, tile_nodes,
                                   sett2_w, sett2_b, city2_w, city2_b,
                                   road2_w, road2_b, rob2_w, rob2_b, out, B);
    k3<<<K3_GRID, 128>>>(gfc2_w, gfc2_b, out, B);
}